// round 1
// baseline (speedup 1.0000x reference)
#include <cuda_runtime.h>
#include <math.h>

// ---------------- problem constants ----------------
#define Bq 4
#define Sq 512
#define Hq 1024
#define Iq 4096
#define Eq 8
#define Vq 32000
#define Lq 2
#define NHq 8
#define DHq 128
#define Tq (Bq*Sq)          // 2048 tokens

typedef long long ll;

// ---------------- device scratch (static, no allocs) ----------------
__device__ float g_x[Tq*Hq];            // residual stream
__device__ float g_n[Tq*Hq];            // layernorm output
__device__ float g_qkv[Tq*3*Hq];        // fused qkv
__device__ float g_scores[Bq*NHq*Sq*Sq];// attention scores
__device__ float g_attno[Tq*Hq];        // attention output (pre out-proj)
__device__ float g_h[2*Tq*Iq];          // MoE hidden (compacted rows)
__device__ float g_moe[2*Tq*Hq];        // per-slot MoE outputs
__device__ int   g_sel[Tq*2];
__device__ int   g_cnt[Eq];
__device__ int   g_off[Eq];
__device__ int   g_cur[Eq];
__device__ int   g_tokmap[2*Tq];
__device__ int   g_outmap[2*Tq];
__device__ float g_aux[1];

// ---------------- generic tiled SGEMM ----------------
// C[M,N] = alpha * A[M,K] x op(B) + epilogue
// TB=true : B is [N,K] row-major (NT)   TB=false: B is [K,N] row-major (NN)
// MOE: 0 = dense (batched via z with zdiv decomposition)
//      1 = fc1: gather A rows via g_tokmap, C rows compacted (rowbase+m)
//      2 = fc2: A rows compacted, scatter C rows via g_outmap
// Assumes: N multiple of 128, K multiple of 8, lda/ldb multiples of 4.
enum { EPI_NONE=0, EPI_BIAS=1, EPI_BIAS_RES=2, EPI_BIAS_GELU=3 };

template<bool TB, int EPI, int MOE>
__global__ __launch_bounds__(256)
void gemm_k(int M, int N, int Kd,
            const float* __restrict__ A, int lda,
            const float* __restrict__ Bw, int ldb,
            float* __restrict__ C, int ldc,
            float alpha,
            const float* __restrict__ bias, ll sBiasZ,
            const float* __restrict__ res,
            int zdiv,
            ll sA1, ll sA2, ll sB1, ll sB2, ll sC1, ll sC2)
{
    int z = blockIdx.z;
    int Me = M;
    ll aoff = 0, boff = 0, coff = 0;
    int rowbase = 0;
    if (MOE) {
        Me      = g_cnt[z];
        rowbase = g_off[z];
        boff    = (ll)z * sB1;
        bias   += (ll)z * sBiasZ;
    } else {
        int zb = z / zdiv, zh = z % zdiv;
        aoff = zb*sA1 + zh*sA2;
        boff = zb*sB1 + zh*sB2;
        coff = zb*sC1 + zh*sC2;
    }
    int m0 = blockIdx.y * 128;
    if (m0 >= Me) return;
    int n0 = blockIdx.x * 128;

    __shared__ float As[8][128];
    __shared__ float Bs[8][128];
    float acc[8][8];
    #pragma unroll
    for (int i = 0; i < 8; i++)
        #pragma unroll
        for (int j = 0; j < 8; j++) acc[i][j] = 0.f;

    int tid = threadIdx.x;
    int lr  = tid >> 1;          // 0..127
    int lk  = (tid & 1) * 4;     // 0 or 4

    int grow = m0 + lr;
    bool a_ok = grow < Me;
    const float* Arow = A;
    if (a_ok) {
        int ar;
        if      (MOE == 1) ar = g_tokmap[rowbase + grow];
        else if (MOE == 2) ar = rowbase + grow;
        else               ar = grow;
        Arow = A + aoff + (ll)ar * lda;
    }
    const float* Brow;
    int bk = 0, bn = 0;
    if (TB) {
        Brow = Bw + boff + (ll)(n0 + lr) * ldb;
    } else {
        bk = tid >> 5; bn = (tid & 31) * 4;
        Brow = Bw + boff + (ll)bk * ldb + n0 + bn;
    }
    int tx = tid & 15, ty = tid >> 4;

    for (int kk = 0; kk < Kd; kk += 8) {
        float4 av = make_float4(0.f,0.f,0.f,0.f);
        if (a_ok) av = *(const float4*)(Arow + kk + lk);
        As[lk+0][lr] = av.x; As[lk+1][lr] = av.y;
        As[lk+2][lr] = av.z; As[lk+3][lr] = av.w;
        if (TB) {
            float4 bv = *(const float4*)(Brow + kk + lk);
            Bs[lk+0][lr] = bv.x; Bs[lk+1][lr] = bv.y;
            Bs[lk+2][lr] = bv.z; Bs[lk+3][lr] = bv.w;
        } else {
            float4 bv = *(const float4*)(Brow + (ll)kk * ldb);
            *(float4*)&Bs[bk][bn] = bv;
        }
        __syncthreads();
        #pragma unroll
        for (int k = 0; k < 8; k++) {
            float4 a0 = *(const float4*)&As[k][ty*8];
            float4 a1 = *(const float4*)&As[k][ty*8+4];
            float4 b0 = *(const float4*)&Bs[k][tx*8];
            float4 b1 = *(const float4*)&Bs[k][tx*8+4];
            float a[8] = {a0.x,a0.y,a0.z,a0.w,a1.x,a1.y,a1.z,a1.w};
            float b[8] = {b0.x,b0.y,b0.z,b0.w,b1.x,b1.y,b1.z,b1.w};
            #pragma unroll
            for (int i = 0; i < 8; i++)
                #pragma unroll
                for (int j = 0; j < 8; j++)
                    acc[i][j] += a[i]*b[j];
        }
        __syncthreads();
    }

    #pragma unroll
    for (int i = 0; i < 8; i++) {
        int r = m0 + ty*8 + i;
        if (r >= Me) continue;
        int cr;
        if      (MOE == 2) cr = g_outmap[rowbase + r];
        else if (MOE == 1) cr = rowbase + r;
        else               cr = r;
        float* Crow = C + coff + (ll)cr*ldc + n0 + tx*8;
        const float* Rrow = (EPI == EPI_BIAS_RES) ? (res + (ll)r*ldc + n0 + tx*8) : nullptr;
        #pragma unroll
        for (int j = 0; j < 8; j++) {
            float v = acc[i][j] * alpha;
            if (EPI >= EPI_BIAS)      v += bias[n0 + tx*8 + j];
            if (EPI == EPI_BIAS_RES)  v += Rrow[j];
            if (EPI == EPI_BIAS_GELU) v = 0.5f*v*(1.f + erff(v*0.70710678118654752f));
            Crow[j] = v;
        }
    }
}

// ---------------- small kernels ----------------
__global__ void embed_k(const int* __restrict__ ids, const float* __restrict__ emb) {
    int idx = blockIdx.x*256 + threadIdx.x;          // T*H threads
    int t = idx / Hq, h = idx - t*Hq;
    g_x[idx] = emb[(ll)ids[t]*Hq + h];
}

__global__ void ln_k(const float* __restrict__ x, const float* __restrict__ g,
                     const float* __restrict__ b, float* __restrict__ o) {
    int t = blockIdx.x;
    const float* xr = x + (ll)t*Hq;
    int tid = threadIdx.x;
    float v[4]; float s = 0.f;
    #pragma unroll
    for (int i = 0; i < 4; i++) { v[i] = xr[tid + 256*i]; s += v[i]; }
    __shared__ float red[256];
    red[tid] = s; __syncthreads();
    for (int o2 = 128; o2; o2 >>= 1) { if (tid < o2) red[tid] += red[tid+o2]; __syncthreads(); }
    float mu = red[0] * (1.f/Hq);
    __syncthreads();
    s = 0.f;
    #pragma unroll
    for (int i = 0; i < 4; i++) { float d = v[i]-mu; s += d*d; }
    red[tid] = s; __syncthreads();
    for (int o2 = 128; o2; o2 >>= 1) { if (tid < o2) red[tid] += red[tid+o2]; __syncthreads(); }
    float inv = rsqrtf(red[0]*(1.f/Hq) + 1e-5f);
    float* orow = o + (ll)t*Hq;
    #pragma unroll
    for (int i = 0; i < 4; i++) { int h = tid + 256*i; orow[h] = (v[i]-mu)*inv*g[h] + b[h]; }
}

__global__ void softmax_k(float* __restrict__ sc) {
    ll row = blockIdx.x;
    float* r = sc + row*Sq;
    int tid = threadIdx.x;
    float a = r[tid], b = r[tid+256];
    __shared__ float red[256];
    red[tid] = fmaxf(a,b); __syncthreads();
    for (int o = 128; o; o >>= 1) { if (tid < o) red[tid] = fmaxf(red[tid], red[tid+o]); __syncthreads(); }
    float m = red[0]; __syncthreads();
    a = expf(a-m); b = expf(b-m);
    red[tid] = a+b; __syncthreads();
    for (int o = 128; o; o >>= 1) { if (tid < o) red[tid] += red[tid+o]; __syncthreads(); }
    float inv = 1.f/red[0];
    r[tid] = a*inv; r[tid+256] = b*inv;
}

__global__ void zero_cnt_k() { if (threadIdx.x < Eq) g_cnt[threadIdx.x] = 0; }
__global__ void zero_aux_k() { g_aux[0] = 0.f; }

__global__ void router_k(const float* __restrict__ n2, const float* __restrict__ rw,
                         const float* __restrict__ rb) {
    int t = blockIdx.x;
    int w = threadIdx.x >> 5, lane = threadIdx.x & 31;   // 8 warps = 8 experts
    const float* xr = n2 + (ll)t*Hq;
    const float* wr = rw + (ll)w*Hq;
    float s = 0.f;
    for (int h = lane; h < Hq; h += 32) s += xr[h]*wr[h];
    #pragma unroll
    for (int o = 16; o; o >>= 1) s += __shfl_xor_sync(0xffffffffu, s, o);
    __shared__ float lg[Eq];
    if (lane == 0) lg[w] = s + rb[w];
    __syncthreads();
    if (threadIdx.x == 0) {
        int b0 = 0; float v0 = lg[0];
        for (int e = 1; e < Eq; e++) if (lg[e] > v0) { v0 = lg[e]; b0 = e; }
        int b1 = -1; float v1 = -3.4e38f;
        for (int e = 0; e < Eq; e++) { if (e == b0) continue; if (lg[e] > v1) { v1 = lg[e]; b1 = e; } }
        g_sel[2*t]   = b0;
        g_sel[2*t+1] = b1;
        atomicAdd(&g_cnt[b0], 1);
        atomicAdd(&g_cnt[b1], 1);
    }
}

__global__ void offsets_k() {
    int s = 0;
    for (int e = 0; e < Eq; e++) { g_off[e] = s; g_cur[e] = s; s += g_cnt[e]; }
}

__global__ void build_k() {
    int t = blockIdx.x*256 + threadIdx.x;
    if (t >= Tq) return;
    #pragma unroll
    for (int slot = 0; slot < 2; slot++) {
        int e = g_sel[2*t + slot];
        int p = atomicAdd(&g_cur[e], 1);
        g_tokmap[p] = t;
        g_outmap[p] = slot*Tq + t;
    }
}

__global__ void aux_k() {
    float s = 0.f;
    const float target = (float)Tq / (float)Eq;
    for (int e = 0; e < Eq; e++) { float d = (float)g_cnt[e] - target; s += d*d; }
    g_aux[0] += 0.01f * s / (float)Eq;
}

__global__ void combine_k() {
    int idx = blockIdx.x*256 + threadIdx.x;          // T*H threads
    g_x[idx] += g_moe[idx] + g_moe[(ll)Tq*Hq + idx];
}

__global__ void tail_k(float* __restrict__ out, ll out_size) {
    ll base = (ll)Tq * Vq;
    for (ll i = base + threadIdx.x; i < out_size; i += 256)
        out[i] = g_aux[0];
}

// ---------------- launch ----------------
extern "C" void kernel_launch(void* const* d_in, const int* in_sizes, int n_in,
                              void* d_out, int out_size) {
    const int*   ids  = (const int*)  d_in[0];
    const float* emb  = (const float*)d_in[1];
    const float* ln1g = (const float*)d_in[2];
    const float* ln1b = (const float*)d_in[3];
    const float* aiw  = (const float*)d_in[4];
    const float* aib  = (const float*)d_in[5];
    const float* aow  = (const float*)d_in[6];
    const float* aob  = (const float*)d_in[7];
    const float* ln2g = (const float*)d_in[8];
    const float* ln2b = (const float*)d_in[9];
    const float* rw   = (const float*)d_in[10];
    const float* rb   = (const float*)d_in[11];
    const float* f1w  = (const float*)d_in[12];
    const float* f1b  = (const float*)d_in[13];
    const float* f2w  = (const float*)d_in[14];
    const float* f2b  = (const float*)d_in[15];
    const float* lmw  = (const float*)d_in[16];
    const float* lmb  = (const float*)d_in[17];
    float* out = (float*)d_out;

    float *px, *pn, *pqkv, *psc, *pao, *ph, *pmoe;
    cudaGetSymbolAddress((void**)&px,   g_x);
    cudaGetSymbolAddress((void**)&pn,   g_n);
    cudaGetSymbolAddress((void**)&pqkv, g_qkv);
    cudaGetSymbolAddress((void**)&psc,  g_scores);
    cudaGetSymbolAddress((void**)&pao,  g_attno);
    cudaGetSymbolAddress((void**)&ph,   g_h);
    cudaGetSymbolAddress((void**)&pmoe, g_moe);

    zero_aux_k<<<1,1>>>();
    embed_k<<<(Tq*Hq)/256, 256>>>(ids, emb);

    for (int l = 0; l < Lq; l++) {
        // --- attention ---
        ln_k<<<Tq,256>>>(px, ln1g + (ll)l*Hq, ln1b + (ll)l*Hq, pn);

        // qkv = n1 @ W_in^T + b  : [T, 3H]
        gemm_k<true, EPI_BIAS, 0><<<dim3(3*Hq/128, Tq/128, 1), 256>>>(
            Tq, 3*Hq, Hq, pn, Hq, aiw + (ll)l*3*Hq*Hq, Hq, pqkv, 3*Hq,
            1.f, aib + (ll)l*3*Hq, 0, nullptr, 1, 0,0,0,0,0,0);

        // scores = q @ k^T / sqrt(DH)  batched over B*NH
        gemm_k<true, EPI_NONE, 0><<<dim3(Sq/128, Sq/128, Bq*NHq), 256>>>(
            Sq, Sq, DHq, pqkv, 3*Hq, pqkv + Hq, 3*Hq, psc, Sq,
            1.f/11.313708498984761f, nullptr, 0, nullptr,
            NHq, (ll)Sq*3*Hq, DHq, (ll)Sq*3*Hq, DHq, (ll)NHq*Sq*Sq, (ll)Sq*Sq);

        softmax_k<<<Bq*NHq*Sq, 256>>>(psc);

        // o = attn @ v  (NN)
        gemm_k<false, EPI_NONE, 0><<<dim3(DHq/128, Sq/128, Bq*NHq), 256>>>(
            Sq, DHq, Sq, psc, Sq, pqkv + 2*Hq, 3*Hq, pao, Hq,
            1.f, nullptr, 0, nullptr,
            NHq, (ll)NHq*Sq*Sq, (ll)Sq*Sq, (ll)Sq*3*Hq, DHq, (ll)Sq*Hq, DHq);

        // x = x + o @ W_out^T + b
        gemm_k<true, EPI_BIAS_RES, 0><<<dim3(Hq/128, Tq/128, 1), 256>>>(
            Tq, Hq, Hq, pao, Hq, aow + (ll)l*Hq*Hq, Hq, px, Hq,
            1.f, aob + (ll)l*Hq, 0, px, 1, 0,0,0,0,0,0);

        // --- MoE ---
        ln_k<<<Tq,256>>>(px, ln2g + (ll)l*Hq, ln2b + (ll)l*Hq, pn);

        zero_cnt_k<<<1,32>>>();
        router_k<<<Tq,256>>>(pn, rw + (ll)l*Eq*Hq, rb + (ll)l*Eq);
        offsets_k<<<1,1>>>();
        build_k<<<Tq/256,256>>>();
        aux_k<<<1,1>>>();

        // fc1: gather tokens per expert, h = gelu(x @ W1^T + b1)
        gemm_k<true, EPI_BIAS_GELU, 1><<<dim3(Iq/128, Tq/128, Eq), 256>>>(
            Tq, Iq, Hq, pn, Hq, f1w + (ll)l*Eq*Iq*Hq, Hq, ph, Iq,
            1.f, f1b + (ll)l*Eq*Iq, Iq, nullptr,
            1, 0,0, (ll)Iq*Hq, 0, 0,0);

        // fc2: scatter to per-slot buffers, out = h @ W2^T + b2
        gemm_k<true, EPI_BIAS, 2><<<dim3(Hq/128, Tq/128, Eq), 256>>>(
            Tq, Hq, Iq, ph, Iq, f2w + (ll)l*Eq*Hq*Iq, Iq, pmoe, Hq,
            1.f, f2b + (ll)l*Eq*Hq, Hq, nullptr,
            1, 0,0, (ll)Hq*Iq, 0, 0,0);

        combine_k<<<(Tq*Hq)/256, 256>>>();
    }

    // lm head: logits = x @ lm_w^T + b  -> directly into d_out
    gemm_k<true, EPI_BIAS, 0><<<dim3(Vq/128, Tq/128, 1), 256>>>(
        Tq, Vq, Hq, px, Hq, lmw, Hq, out, Vq,
        1.f, lmb, 0, nullptr, 1, 0,0,0,0,0,0);

    tail_k<<<1,256>>>(out, (ll)out_size);
}

// round 3
// speedup vs baseline: 1.6555x; 1.6555x over previous
#include <cuda_runtime.h>
#include <cuda_bf16.h>
#include <math.h>
#include <stdint.h>

// ---------------- problem constants ----------------
#define Bq 4
#define Sq 512
#define Hq 1024
#define Iq 4096
#define Eq 8
#define Vq 32000
#define Lq 2
#define NHq 8
#define DHq 128
#define Tq (Bq*Sq)          // 2048 tokens

typedef long long ll;

__device__ __forceinline__ uint32_t smem_u32(const void* p) {
    uint32_t a;
    asm("{ .reg .u64 t; cvta.to.shared.u64 t, %1; cvt.u32.u64 %0, t; }" : "=r"(a) : "l"(p));
    return a;
}

// ---------------- device scratch (static, no allocs) ----------------
__device__ float g_x[Tq*Hq];
__device__ float g_n[Tq*Hq];
__device__ float g_qkv[Tq*3*Hq];
__device__ float g_scores[Bq*NHq*Sq*Sq];
__device__ float g_attno[Tq*Hq];
__device__ float g_moe[2*Tq*Hq];
__device__ int   g_sel[Tq*2];
__device__ int   g_cnt[Eq];
__device__ int   g_off[Eq];
__device__ int   g_cur[Eq];
__device__ int   g_tokmap[2*Tq];
__device__ int   g_outmap[2*Tq];
__device__ float g_aux[1];
// split-bf16 buffers (K expanded 3x)
__device__ __nv_bfloat16 g_win3 [Lq*3*Hq*3*Hq];
__device__ __nv_bfloat16 g_wout3[Lq*Hq*3*Hq];
__device__ __nv_bfloat16 g_wfc13[(size_t)Lq*Eq*Iq*3*Hq];
__device__ __nv_bfloat16 g_wfc23[(size_t)Lq*Eq*Hq*3*Iq];
__device__ __nv_bfloat16 g_wlm3 [(size_t)Vq*3*Hq];
__device__ __nv_bfloat16 g_n3   [Tq*3*Hq];
__device__ __nv_bfloat16 g_pao3 [Tq*3*Hq];
__device__ __nv_bfloat16 g_x3   [Tq*3*Hq];
__device__ __nv_bfloat16 g_h3   [(size_t)2*Tq*3*Iq];

// ---------------- split conversion kernels ----------------
// A-layout: [hi | lo | hi]   B-layout: [hi | hi | lo]
template<bool ISA>
__global__ void cvt_k(const float* __restrict__ src, __nv_bfloat16* __restrict__ dst,
                      int K, ll total) {
    ll idx = (ll)blockIdx.x * 256 + threadIdx.x;
    if (idx >= total) return;
    ll r = idx / K; int k = (int)(idx - r * K);
    float x = src[idx];
    __nv_bfloat16 hi = __float2bfloat16(x);
    __nv_bfloat16 lo = __float2bfloat16(x - __bfloat162float(hi));
    __nv_bfloat16* d = dst + r * (ll)(3 * K);
    if (ISA) { d[k] = hi; d[K + k] = lo; d[2*K + k] = hi; }
    else     { d[k] = hi; d[K + k] = hi; d[2*K + k] = lo; }
}

// ---------------- HMMA bf16 GEMM: C[M,N] = A'[M,3K] x B'[N,3K]^T ----------------
// CTA tile 128x128, BK=32, 3-stage cp.async pipeline, 8 warps (2x4), warp 64x32.
// EPI: 1=bias(f32 out), 2=bias+res(f32), 3=bias+gelu -> split-bf16 A-layout out.
// MOE: 0 dense, 1 gather-A/compact-C, 2 compact-A/scatter-C.
#define STAGE_B 20480u          // (128*40 + 128*40) * 2 bytes
#define DSMB (3*20480)

__device__ __forceinline__ void ldmx4(uint32_t* r, uint32_t addr) {
    asm volatile("ldmatrix.sync.aligned.m8n8.x4.shared.b16 {%0,%1,%2,%3}, [%4];"
        : "=r"(r[0]), "=r"(r[1]), "=r"(r[2]), "=r"(r[3]) : "r"(addr));
}
__device__ __forceinline__ void mma16816(float* c, const uint32_t* a, uint32_t b0, uint32_t b1) {
    asm volatile("mma.sync.aligned.m16n8k16.row.col.f32.bf16.bf16.f32 "
        "{%0,%1,%2,%3}, {%4,%5,%6,%7}, {%8,%9}, {%0,%1,%2,%3};"
        : "+f"(c[0]), "+f"(c[1]), "+f"(c[2]), "+f"(c[3])
        : "r"(a[0]), "r"(a[1]), "r"(a[2]), "r"(a[3]), "r"(b0), "r"(b1));
}

template<int EPI, int MOE>
__global__ __launch_bounds__(256, 1)
void bgemm(int M, int N, int K3,
           const __nv_bfloat16* __restrict__ A,
           const __nv_bfloat16* __restrict__ Bw,
           void* __restrict__ Cv, int ldc,
           const float* __restrict__ bias,
           const float* __restrict__ res,
           ll sBz, ll sBiasZ)
{
    int Me = M, rowbase = 0;
    if (MOE) {
        int z = blockIdx.z;
        Me = g_cnt[z]; rowbase = g_off[z];
        Bw += (ll)z * sBz; bias += (ll)z * sBiasZ;
    }
    int m0 = blockIdx.x * 128;
    if (m0 >= Me) return;
    int n0 = blockIdx.y * 128;

    __shared__ int s_row[128];
    __shared__ int s_cout[128];
    extern __shared__ __align__(16) char dsm[];
    uint32_t dbase = smem_u32(dsm);

    int tid = threadIdx.x, lane = tid & 31, wid = tid >> 5;
    int wm = wid >> 2, wn = wid & 3;   // 2 x 4 warp grid

    if (tid < 128) {
        int grow = m0 + tid;
        int rid = -1, cid = -1;
        if (grow < Me) {
            if      (MOE == 1) { rid = g_tokmap[rowbase + grow]; cid = rowbase + grow; }
            else if (MOE == 2) { rid = rowbase + grow;           cid = g_outmap[rowbase + grow]; }
            else               { rid = grow;                     cid = grow; }
        }
        s_row[tid] = rid; s_cout[tid] = cid;
    }
    __syncthreads();

    // per-thread load chunks: c = tid + i*256 ; row = c>>2 ; col16 = c&3
    int rowA0 = tid >> 2,            colA0 = tid & 3;
    int rowA1 = (tid + 256) >> 2,    colA1 = tid & 3;

    float acc[4][4][4];
    #pragma unroll
    for (int a = 0; a < 4; a++)
        #pragma unroll
        for (int b = 0; b < 4; b++)
            #pragma unroll
            for (int c = 0; c < 4; c++) acc[a][b][c] = 0.f;

    int S = K3 / 32;

    auto load_stage = [&](int s) {
        int c0 = s * 32;
        uint32_t base = dbase + (uint32_t)(s % 3) * STAGE_B;
        #pragma unroll
        for (int i = 0; i < 2; i++) {
            int row = i ? rowA1 : rowA0;
            int col16 = i ? colA1 : colA0;
            // A (gathered, zero-filled when row invalid)
            int r = s_row[row];
            const void* srcA = (r >= 0) ? (const void*)(A + (ll)r * K3 + c0 + col16 * 8)
                                        : (const void*)A;
            uint32_t dstA = base + (uint32_t)(row * 80 + col16 * 16);
            uint32_t szA = (r >= 0) ? 16u : 0u;
            asm volatile("cp.async.cg.shared.global [%0], [%1], 16, %2;"
                :: "r"(dstA), "l"(srcA), "r"(szA));
            // B (always valid)
            const void* srcB = (const void*)(Bw + (ll)(n0 + row) * K3 + c0 + col16 * 8);
            uint32_t dstB = base + 10240u + (uint32_t)(row * 80 + col16 * 16);
            asm volatile("cp.async.cg.shared.global [%0], [%1], 16;"
                :: "r"(dstB), "l"(srcB));
        }
        asm volatile("cp.async.commit_group;" ::: "memory");
    };

    load_stage(0);
    load_stage(1);

    for (int s = 0; s < S; s++) {
        if (s + 1 < S) { asm volatile("cp.async.wait_group 1;" ::: "memory"); }
        else           { asm volatile("cp.async.wait_group 0;" ::: "memory"); }
        __syncthreads();
        if (s + 2 < S) load_stage(s + 2);

        uint32_t base = dbase + (uint32_t)(s % 3) * STAGE_B;
        uint32_t Ab = base, Bb = base + 10240u;

        #pragma unroll
        for (int kk = 0; kk < 2; kk++) {
            uint32_t a[4][4], b[2][4];
            #pragma unroll
            for (int mf = 0; mf < 4; mf++) {
                uint32_t ad = Ab + (uint32_t)(((wm*64 + mf*16 + (lane & 15)) * 40
                                              + kk*16 + (lane >> 4) * 8) * 2);
                ldmx4(a[mf], ad);
            }
            #pragma unroll
            for (int bt = 0; bt < 2; bt++) {
                int g = lane >> 3;
                uint32_t bd = Bb + (uint32_t)(((wn*32 + bt*16 + (g >> 1)*8 + (lane & 7)) * 40
                                              + kk*16 + (g & 1) * 8) * 2);
                ldmx4(b[bt], bd);
            }
            #pragma unroll
            for (int mf = 0; mf < 4; mf++)
                #pragma unroll
                for (int nf = 0; nf < 4; nf++)
                    mma16816(acc[mf][nf], a[mf], b[nf >> 1][(nf & 1)*2], b[nf >> 1][(nf & 1)*2 + 1]);
        }
        // next iteration's top sync protects buffer reuse
    }

    // ---------------- epilogue (register-direct) ----------------
    #pragma unroll
    for (int mf = 0; mf < 4; mf++) {
        int rbase = wm*64 + mf*16 + (lane >> 2);
        #pragma unroll
        for (int half = 0; half < 2; half++) {
            int rloc = rbase + half * 8;
            int cr = s_cout[rloc];
            if (cr < 0) continue;
            #pragma unroll
            for (int nf = 0; nf < 4; nf++) {
                int col = n0 + wn*32 + nf*8 + (lane & 3)*2;
                float v0 = acc[mf][nf][half*2 + 0];
                float v1 = acc[mf][nf][half*2 + 1];
                float2 bv = *(const float2*)&bias[col];
                v0 += bv.x; v1 += bv.y;
                if (EPI == 2) {
                    float2 rv = *(const float2*)(res + (ll)cr*ldc + col);
                    v0 += rv.x; v1 += rv.y;
                }
                if (EPI == 3) {
                    v0 = 0.5f*v0*(1.f + erff(v0*0.70710678118654752f));
                    v1 = 0.5f*v1*(1.f + erff(v1*0.70710678118654752f));
                    __nv_bfloat16 h0 = __float2bfloat16(v0);
                    __nv_bfloat16 l0 = __float2bfloat16(v0 - __bfloat162float(h0));
                    __nv_bfloat16 h1 = __float2bfloat16(v1);
                    __nv_bfloat16 l1 = __float2bfloat16(v1 - __bfloat162float(h1));
                    __nv_bfloat16* D = (__nv_bfloat16*)Cv + (ll)cr * (3 * N);
                    *(__nv_bfloat162*)&D[col]         = __nv_bfloat162(h0, h1);
                    *(__nv_bfloat162*)&D[N + col]     = __nv_bfloat162(l0, l1);
                    *(__nv_bfloat162*)&D[2*N + col]   = __nv_bfloat162(h0, h1);
                } else {
                    *(float2*)((float*)Cv + (ll)cr*ldc + col) = make_float2(v0, v1);
                }
            }
        }
    }
}

// ---------------- fp32 tiled SGEMM (attention scores / AV only) ----------------
template<bool TB>
__global__ __launch_bounds__(256)
void gemm_k(int M, int N, int Kd,
            const float* __restrict__ A, int lda,
            const float* __restrict__ Bw, int ldb,
            float* __restrict__ C, int ldc,
            float alpha, int zdiv,
            ll sA1, ll sA2, ll sB1, ll sB2, ll sC1, ll sC2)
{
    int z = blockIdx.z;
    int zb = z / zdiv, zh = z % zdiv;
    ll aoff = zb*sA1 + zh*sA2;
    ll boff = zb*sB1 + zh*sB2;
    ll coff = zb*sC1 + zh*sC2;
    int m0 = blockIdx.y * 128;
    int n0 = blockIdx.x * 128;

    __shared__ float As[8][128];
    __shared__ float Bs[8][128];
    float acc[8][8];
    #pragma unroll
    for (int i = 0; i < 8; i++)
        #pragma unroll
        for (int j = 0; j < 8; j++) acc[i][j] = 0.f;

    int tid = threadIdx.x;
    int lr  = tid >> 1;
    int lk  = (tid & 1) * 4;
    const float* Arow = A + aoff + (ll)(m0 + lr) * lda;
    const float* Brow;
    int bk = 0, bn = 0;
    if (TB) {
        Brow = Bw + boff + (ll)(n0 + lr) * ldb;
    } else {
        bk = tid >> 5; bn = (tid & 31) * 4;
        Brow = Bw + boff + (ll)bk * ldb + n0 + bn;
    }
    int tx = tid & 15, ty = tid >> 4;

    for (int kk = 0; kk < Kd; kk += 8) {
        float4 av = *(const float4*)(Arow + kk + lk);
        As[lk+0][lr] = av.x; As[lk+1][lr] = av.y;
        As[lk+2][lr] = av.z; As[lk+3][lr] = av.w;
        if (TB) {
            float4 bv = *(const float4*)(Brow + kk + lk);
            Bs[lk+0][lr] = bv.x; Bs[lk+1][lr] = bv.y;
            Bs[lk+2][lr] = bv.z; Bs[lk+3][lr] = bv.w;
        } else {
            float4 bv = *(const float4*)(Brow + (ll)kk * ldb);
            *(float4*)&Bs[bk][bn] = bv;
        }
        __syncthreads();
        #pragma unroll
        for (int k = 0; k < 8; k++) {
            float4 a0 = *(const float4*)&As[k][ty*8];
            float4 a1 = *(const float4*)&As[k][ty*8+4];
            float4 b0 = *(const float4*)&Bs[k][tx*8];
            float4 b1 = *(const float4*)&Bs[k][tx*8+4];
            float a[8] = {a0.x,a0.y,a0.z,a0.w,a1.x,a1.y,a1.z,a1.w};
            float b[8] = {b0.x,b0.y,b0.z,b0.w,b1.x,b1.y,b1.z,b1.w};
            #pragma unroll
            for (int i = 0; i < 8; i++)
                #pragma unroll
                for (int j = 0; j < 8; j++)
                    acc[i][j] += a[i]*b[j];
        }
        __syncthreads();
    }
    #pragma unroll
    for (int i = 0; i < 8; i++) {
        float* Crow = C + coff + (ll)(m0 + ty*8 + i)*ldc + n0 + tx*8;
        #pragma unroll
        for (int j = 0; j < 8; j++) Crow[j] = acc[i][j] * alpha;
    }
}

// ---------------- small kernels ----------------
__global__ void embed_k(const int* __restrict__ ids, const float* __restrict__ emb) {
    int idx = blockIdx.x*256 + threadIdx.x;
    int t = idx / Hq, h = idx - t*Hq;
    g_x[idx] = emb[(ll)ids[t]*Hq + h];
}

__global__ void ln_k(const float* __restrict__ x, const float* __restrict__ g,
                     const float* __restrict__ b, float* __restrict__ o,
                     __nv_bfloat16* __restrict__ o3) {
    int t = blockIdx.x;
    const float* xr = x + (ll)t*Hq;
    int tid = threadIdx.x;
    float v[4]; float s = 0.f;
    #pragma unroll
    for (int i = 0; i < 4; i++) { v[i] = xr[tid + 256*i]; s += v[i]; }
    __shared__ float red[256];
    red[tid] = s; __syncthreads();
    for (int o2 = 128; o2; o2 >>= 1) { if (tid < o2) red[tid] += red[tid+o2]; __syncthreads(); }
    float mu = red[0] * (1.f/Hq);
    __syncthreads();
    s = 0.f;
    #pragma unroll
    for (int i = 0; i < 4; i++) { float d = v[i]-mu; s += d*d; }
    red[tid] = s; __syncthreads();
    for (int o2 = 128; o2; o2 >>= 1) { if (tid < o2) red[tid] += red[tid+o2]; __syncthreads(); }
    float inv = rsqrtf(red[0]*(1.f/Hq) + 1e-5f);
    float* orow = o + (ll)t*Hq;
    __nv_bfloat16* o3r = o3 + (ll)t*3*Hq;
    #pragma unroll
    for (int i = 0; i < 4; i++) {
        int h = tid + 256*i;
        float y = (v[i]-mu)*inv*g[h] + b[h];
        orow[h] = y;
        __nv_bfloat16 hi = __float2bfloat16(y);
        __nv_bfloat16 lo = __float2bfloat16(y - __bfloat162float(hi));
        o3r[h] = hi; o3r[Hq + h] = lo; o3r[2*Hq + h] = hi;
    }
}

__global__ void softmax_k(float* __restrict__ sc) {
    ll row = blockIdx.x;
    float* r = sc + row*Sq;
    int tid = threadIdx.x;
    float a = r[tid], b = r[tid+256];
    __shared__ float red[256];
    red[tid] = fmaxf(a,b); __syncthreads();
    for (int o = 128; o; o >>= 1) { if (tid < o) red[tid] = fmaxf(red[tid], red[tid+o]); __syncthreads(); }
    float m = red[0]; __syncthreads();
    a = expf(a-m); b = expf(b-m);
    red[tid] = a+b; __syncthreads();
    for (int o = 128; o; o >>= 1) { if (tid < o) red[tid] += red[tid+o]; __syncthreads(); }
    float inv = 1.f/red[0];
    r[tid] = a*inv; r[tid+256] = b*inv;
}

__global__ void zero_cnt_k() { if (threadIdx.x < Eq) g_cnt[threadIdx.x] = 0; }
__global__ void zero_aux_k() { g_aux[0] = 0.f; }

__global__ void router_k(const float* __restrict__ n2, const float* __restrict__ rw,
                         const float* __restrict__ rb) {
    int t = blockIdx.x;
    int w = threadIdx.x >> 5, lane = threadIdx.x & 31;
    const float* xr = n2 + (ll)t*Hq;
    const float* wr = rw + (ll)w*Hq;
    float s = 0.f;
    for (int h = lane; h < Hq; h += 32) s += xr[h]*wr[h];
    #pragma unroll
    for (int o = 16; o; o >>= 1) s += __shfl_xor_sync(0xffffffffu, s, o);
    __shared__ float lg[Eq];
    if (lane == 0) lg[w] = s + rb[w];
    __syncthreads();
    if (threadIdx.x == 0) {
        int b0 = 0; float v0 = lg[0];
        for (int e = 1; e < Eq; e++) if (lg[e] > v0) { v0 = lg[e]; b0 = e; }
        int b1 = -1; float v1 = -3.4e38f;
        for (int e = 0; e < Eq; e++) { if (e == b0) continue; if (lg[e] > v1) { v1 = lg[e]; b1 = e; } }
        g_sel[2*t]   = b0;
        g_sel[2*t+1] = b1;
        atomicAdd(&g_cnt[b0], 1);
        atomicAdd(&g_cnt[b1], 1);
    }
}

__global__ void offsets_k() {
    int s = 0;
    for (int e = 0; e < Eq; e++) { g_off[e] = s; g_cur[e] = s; s += g_cnt[e]; }
}

__global__ void build_k() {
    int t = blockIdx.x*256 + threadIdx.x;
    if (t >= Tq) return;
    #pragma unroll
    for (int slot = 0; slot < 2; slot++) {
        int e = g_sel[2*t + slot];
        int p = atomicAdd(&g_cur[e], 1);
        g_tokmap[p] = t;
        g_outmap[p] = slot*Tq + t;
    }
}

__global__ void aux_k() {
    float s = 0.f;
    const float target = (float)Tq / (float)Eq;
    for (int e = 0; e < Eq; e++) { float d = (float)g_cnt[e] - target; s += d*d; }
    g_aux[0] += 0.01f * s / (float)Eq;
}

__global__ void combine_k() {
    int idx = blockIdx.x*256 + threadIdx.x;
    g_x[idx] += g_moe[idx] + g_moe[(ll)Tq*Hq + idx];
}

__global__ void tail_k(float* __restrict__ out, ll out_size) {
    ll base = (ll)Tq * Vq;
    for (ll i = base + threadIdx.x; i < out_size; i += 256)
        out[i] = g_aux[0];
}

// ---------------- launch ----------------
static inline int cvblocks(ll total) { return (int)((total + 255) / 256); }

extern "C" void kernel_launch(void* const* d_in, const int* in_sizes, int n_in,
                              void* d_out, int out_size) {
    const int*   ids  = (const int*)  d_in[0];
    const float* emb  = (const float*)d_in[1];
    const float* ln1g = (const float*)d_in[2];
    const float* ln1b = (const float*)d_in[3];
    const float* aiw  = (const float*)d_in[4];
    const float* aib  = (const float*)d_in[5];
    const float* aow  = (const float*)d_in[6];
    const float* aob  = (const float*)d_in[7];
    const float* ln2g = (const float*)d_in[8];
    const float* ln2b = (const float*)d_in[9];
    const float* rw   = (const float*)d_in[10];
    const float* rb   = (const float*)d_in[11];
    const float* f1w  = (const float*)d_in[12];
    const float* f1b  = (const float*)d_in[13];
    const float* f2w  = (const float*)d_in[14];
    const float* f2b  = (const float*)d_in[15];
    const float* lmw  = (const float*)d_in[16];
    const float* lmb  = (const float*)d_in[17];
    float* out = (float*)d_out;

    cudaFuncSetAttribute(bgemm<1,0>, cudaFuncAttributeMaxDynamicSharedMemorySize, DSMB);
    cudaFuncSetAttribute(bgemm<2,0>, cudaFuncAttributeMaxDynamicSharedMemorySize, DSMB);
    cudaFuncSetAttribute(bgemm<3,1>, cudaFuncAttributeMaxDynamicSharedMemorySize, DSMB);
    cudaFuncSetAttribute(bgemm<1,2>, cudaFuncAttributeMaxDynamicSharedMemorySize, DSMB);

    float *px, *pn, *pqkv, *psc, *pao, *pmoe;
    cudaGetSymbolAddress((void**)&px,   g_x);
    cudaGetSymbolAddress((void**)&pn,   g_n);
    cudaGetSymbolAddress((void**)&pqkv, g_qkv);
    cudaGetSymbolAddress((void**)&psc,  g_scores);
    cudaGetSymbolAddress((void**)&pao,  g_attno);
    cudaGetSymbolAddress((void**)&pmoe, g_moe);
    __nv_bfloat16 *pwin3, *pwout3, *pwfc13, *pwfc23, *pwlm3, *pn3, *pao3, *px3, *ph3;
    cudaGetSymbolAddress((void**)&pwin3,  g_win3);
    cudaGetSymbolAddress((void**)&pwout3, g_wout3);
    cudaGetSymbolAddress((void**)&pwfc13, g_wfc13);
    cudaGetSymbolAddress((void**)&pwfc23, g_wfc23);
    cudaGetSymbolAddress((void**)&pwlm3,  g_wlm3);
    cudaGetSymbolAddress((void**)&pn3,    g_n3);
    cudaGetSymbolAddress((void**)&pao3,   g_pao3);
    cudaGetSymbolAddress((void**)&px3,    g_x3);
    cudaGetSymbolAddress((void**)&ph3,    g_h3);

    // ---- weight conversions (fp32 -> split-bf16, B-layout) ----
    cvt_k<false><<<cvblocks((ll)Lq*3*Hq*Hq), 256>>>(aiw, pwin3,  Hq, (ll)Lq*3*Hq*Hq);
    cvt_k<false><<<cvblocks((ll)Lq*Hq*Hq),   256>>>(aow, pwout3, Hq, (ll)Lq*Hq*Hq);
    cvt_k<false><<<cvblocks((ll)Lq*Eq*Iq*Hq),256>>>(f1w, pwfc13, Hq, (ll)Lq*Eq*Iq*Hq);
    cvt_k<false><<<cvblocks((ll)Lq*Eq*Hq*Iq),256>>>(f2w, pwfc23, Iq, (ll)Lq*Eq*Hq*Iq);
    cvt_k<false><<<cvblocks((ll)Vq*Hq),      256>>>(lmw, pwlm3,  Hq, (ll)Vq*Hq);

    zero_aux_k<<<1,1>>>();
    embed_k<<<(Tq*Hq)/256, 256>>>(ids, emb);

    for (int l = 0; l < Lq; l++) {
        // --- attention ---
        ln_k<<<Tq,256>>>(px, ln1g + (ll)l*Hq, ln1b + (ll)l*Hq, pn, pn3);

        // qkv = n1 @ W_in^T + b  (HMMA)
        bgemm<1,0><<<dim3(Tq/128, 3*Hq/128, 1), 256, DSMB>>>(
            Tq, 3*Hq, 3*Hq, pn3, pwin3 + (ll)l*3*Hq*3*Hq, pqkv, 3*Hq,
            aib + (ll)l*3*Hq, nullptr, 0, 0);

        // scores = q @ k^T / sqrt(DH)  (fp32, batched over B*NH)
        gemm_k<true><<<dim3(Sq/128, Sq/128, Bq*NHq), 256>>>(
            Sq, Sq, DHq, pqkv, 3*Hq, pqkv + Hq, 3*Hq, psc, Sq,
            1.f/11.313708498984761f, NHq,
            (ll)Sq*3*Hq, DHq, (ll)Sq*3*Hq, DHq, (ll)NHq*Sq*Sq, (ll)Sq*Sq);

        softmax_k<<<Bq*NHq*Sq, 256>>>(psc);

        // o = attn @ v  (fp32, NN)
        gemm_k<false><<<dim3(DHq/128, Sq/128, Bq*NHq), 256>>>(
            Sq, DHq, Sq, psc, Sq, pqkv + 2*Hq, 3*Hq, pao, Hq,
            1.f, NHq,
            (ll)NHq*Sq*Sq, (ll)Sq*Sq, (ll)Sq*3*Hq, DHq, (ll)Sq*Hq, DHq);

        // convert attn output to split
        cvt_k<true><<<cvblocks((ll)Tq*Hq), 256>>>(pao, pao3, Hq, (ll)Tq*Hq);

        // x = x + o @ W_out^T + b
        bgemm<2,0><<<dim3(Tq/128, Hq/128, 1), 256, DSMB>>>(
            Tq, Hq, 3*Hq, pao3, pwout3 + (ll)l*Hq*3*Hq, px, Hq,
            aob + (ll)l*Hq, px, 0, 0);

        // --- MoE ---
        ln_k<<<Tq,256>>>(px, ln2g + (ll)l*Hq, ln2b + (ll)l*Hq, pn, pn3);

        zero_cnt_k<<<1,32>>>();
        router_k<<<Tq,256>>>(pn, rw + (ll)l*Eq*Hq, rb + (ll)l*Eq);
        offsets_k<<<1,1>>>();
        build_k<<<Tq/256,256>>>();
        aux_k<<<1,1>>>();

        // fc1: gather, gelu, write split-bf16 hidden
        bgemm<3,1><<<dim3(Tq/128, Iq/128, Eq), 256, DSMB>>>(
            Tq, Iq, 3*Hq, pn3, pwfc13 + (ll)l*Eq*Iq*3*Hq, ph3, 0,
            f1b + (ll)l*Eq*Iq, nullptr, (ll)Iq*3*Hq, (ll)Iq);

        // fc2: scatter to per-slot fp32 buffers
        bgemm<1,2><<<dim3(Tq/128, Hq/128, Eq), 256, DSMB>>>(
            Tq, Hq, 3*Iq, ph3, pwfc23 + (ll)l*Eq*Hq*3*Iq, pmoe, Hq,
            f2b + (ll)l*Eq*Hq, nullptr, (ll)Hq*3*Iq, (ll)Hq);

        combine_k<<<(Tq*Hq)/256, 256>>>();
    }

    // lm head
    cvt_k<true><<<cvblocks((ll)Tq*Hq), 256>>>(px, px3, Hq, (ll)Tq*Hq);
    bgemm<1,0><<<dim3(Tq/128, Vq/128, 1), 256, DSMB>>>(
        Tq, Vq, 3*Hq, px3, pwlm3, out, Vq,
        lmb, nullptr, 0, 0);

    tail_k<<<1,256>>>(out, (ll)out_size);
}

// round 4
// speedup vs baseline: 2.3202x; 1.4015x over previous
#include <cuda_runtime.h>
#include <cuda_fp16.h>
#include <math.h>
#include <stdint.h>

// ---------------- problem constants ----------------
#define Bq 4
#define Sq 512
#define Hq 1024
#define Iq 4096
#define Eq 8
#define Vq 32000
#define Lq 2
#define NHq 8
#define DHq 128
#define Tq (Bq*Sq)          // 2048 tokens

typedef long long ll;

__device__ __forceinline__ uint32_t smem_u32(const void* p) {
    uint32_t a;
    asm("{ .reg .u64 t; cvta.to.shared.u64 t, %1; cvt.u32.u64 %0, t; }" : "=r"(a) : "l"(p));
    return a;
}

// ---------------- device scratch (static, no allocs) ----------------
__device__ float g_x[Tq*Hq];
__device__ float g_n[Tq*Hq];
__device__ float g_qkv[Tq*3*Hq];
__device__ float g_scores[Bq*NHq*Sq*Sq];
__device__ float g_attno[Tq*Hq];
__device__ float g_moe[2*Tq*Hq];
__device__ int   g_sel[Tq*2];
__device__ int   g_cnt[Eq];
__device__ int   g_off[Eq];
__device__ int   g_cur[Eq];
__device__ int   g_tokmap[2*Tq];
__device__ int   g_outmap[2*Tq];
__device__ float g_aux[1];
// fp16 hi/lo planes
__device__ __half g_winH[Lq*3*Hq*Hq],  g_winL[Lq*3*Hq*Hq];
__device__ __half g_woutH[Lq*Hq*Hq],   g_woutL[Lq*Hq*Hq];
__device__ __half g_f1H[(size_t)Lq*Eq*Iq*Hq], g_f1L[(size_t)Lq*Eq*Iq*Hq];
__device__ __half g_f2H[(size_t)Lq*Eq*Hq*Iq], g_f2L[(size_t)Lq*Eq*Hq*Iq];
__device__ __half g_lmH[(size_t)Vq*Hq], g_lmL[(size_t)Vq*Hq];
__device__ __half g_nH[Tq*Hq],  g_nL[Tq*Hq];
__device__ __half g_aoH[Tq*Hq], g_aoL[Tq*Hq];
__device__ __half g_xH[Tq*Hq],  g_xL[Tq*Hq];
__device__ __half g_hH[(size_t)2*Tq*Iq], g_hL[(size_t)2*Tq*Iq];

// ---------------- split conversion: fp32 -> (hi, lo) fp16 planes ----------------
__global__ void cvt2_k(const float* __restrict__ src, __half* __restrict__ hi,
                       __half* __restrict__ lo, ll total) {
    ll i = ((ll)blockIdx.x * 256 + threadIdx.x) * 8;
    if (i >= total) return;
    float4 a = *(const float4*)(src + i);
    float4 b = *(const float4*)(src + i + 4);
    float v[8] = {a.x, a.y, a.z, a.w, b.x, b.y, b.z, b.w};
    __align__(16) __half h[8];
    __align__(16) __half l[8];
    #pragma unroll
    for (int j = 0; j < 8; j++) {
        h[j] = __float2half(v[j]);
        l[j] = __float2half(v[j] - __half2float(h[j]));
    }
    *(uint4*)(hi + i) = *(const uint4*)h;
    *(uint4*)(lo + i) = *(const uint4*)l;
}

// ---------------- HMMA fp16 split GEMM ----------------
// C[M,N] = (Ah+Al)[M,K] x (Bh+Bl)[N,K]^T  via 3 terms: Ah*Bh + Al*Bh + Ah*Bl
// CTA tile 128x128, BK=32 (original K), 4-stage cp.async pipeline, 8 warps (2x4).
// EPI: 1=bias(f32 out), 2=bias+res(f32), 3=bias+gelu -> fp16 hi/lo planes.
// MOE: 0 dense, 1 gather-A/compact-C, 2 compact-A/scatter-C.
#define STAGE_B 40960u     // 4 tiles x 128 x 40 halves x 2B
#define DSMB (4*40960)

__device__ __forceinline__ void ldmx4(uint32_t* r, uint32_t addr) {
    asm volatile("ldmatrix.sync.aligned.m8n8.x4.shared.b16 {%0,%1,%2,%3}, [%4];"
        : "=r"(r[0]), "=r"(r[1]), "=r"(r[2]), "=r"(r[3]) : "r"(addr));
}
__device__ __forceinline__ void mma16816(float* c, const uint32_t* a, uint32_t b0, uint32_t b1) {
    asm volatile("mma.sync.aligned.m16n8k16.row.col.f32.f16.f16.f32 "
        "{%0,%1,%2,%3}, {%4,%5,%6,%7}, {%8,%9}, {%0,%1,%2,%3};"
        : "+f"(c[0]), "+f"(c[1]), "+f"(c[2]), "+f"(c[3])
        : "r"(a[0]), "r"(a[1]), "r"(a[2]), "r"(a[3]), "r"(b0), "r"(b1));
}
__device__ __forceinline__ void cpasync16(uint32_t dst, const void* src) {
    asm volatile("cp.async.cg.shared.global [%0], [%1], 16;" :: "r"(dst), "l"(src));
}
__device__ __forceinline__ void cpasync16z(uint32_t dst, const void* src, uint32_t sz) {
    asm volatile("cp.async.cg.shared.global [%0], [%1], 16, %2;" :: "r"(dst), "l"(src), "r"(sz));
}

template<int EPI, int MOE>
__global__ __launch_bounds__(256, 1)
void bgemm(int M, int N, int K,
           const __half* __restrict__ Ah, const __half* __restrict__ Al,
           const __half* __restrict__ Bh, const __half* __restrict__ Bl,
           void* __restrict__ Cv, int ldc,
           const float* __restrict__ bias,
           const float* __restrict__ res,
           __half* __restrict__ Clo,
           ll sBz, ll sBiasZ)
{
    int Me = M, rowbase = 0;
    if (MOE) {
        int z = blockIdx.z;
        Me = g_cnt[z]; rowbase = g_off[z];
        Bh += (ll)z * sBz; Bl += (ll)z * sBz;
        bias += (ll)z * sBiasZ;
    }
    int m0 = blockIdx.x * 128;
    if (m0 >= Me) return;
    int n0 = blockIdx.y * 128;

    __shared__ int s_row[128];
    __shared__ int s_cout[128];
    extern __shared__ __align__(16) char dsm[];
    uint32_t dbase = smem_u32(dsm);

    int tid = threadIdx.x, lane = tid & 31, wid = tid >> 5;
    int wm = wid >> 2, wn = wid & 3;   // 2 x 4 warp grid

    if (tid < 128) {
        int grow = m0 + tid;
        int rid = -1, cid = -1;
        if (grow < Me) {
            if      (MOE == 1) { rid = g_tokmap[rowbase + grow]; cid = rowbase + grow; }
            else if (MOE == 2) { rid = rowbase + grow;           cid = g_outmap[rowbase + grow]; }
            else               { rid = grow;                     cid = grow; }
        }
        s_row[tid] = rid; s_cout[tid] = cid;
    }
    __syncthreads();

    float acc[4][4][4];
    #pragma unroll
    for (int a = 0; a < 4; a++)
        #pragma unroll
        for (int b = 0; b < 4; b++)
            #pragma unroll
            for (int c = 0; c < 4; c++) acc[a][b][c] = 0.f;

    int S = K / 32;

    auto load_stage = [&](int s) {
        int c0 = s * 32;
        uint32_t base = dbase + (uint32_t)(s & 3) * STAGE_B;
        #pragma unroll
        for (int i = 0; i < 2; i++) {
            int idx = tid + i * 256;
            int row = idx >> 2, c = idx & 3;
            uint32_t off = (uint32_t)(row * 80 + c * 16);
            // A hi/lo (gathered, zero-filled when row invalid)
            int r = s_row[row];
            ll aoff = (r >= 0) ? ((ll)r * K + c0 + c * 8) : 0;
            uint32_t sz = (r >= 0) ? 16u : 0u;
            cpasync16z(base + off,          Ah + aoff, sz);
            cpasync16z(base + 10240u + off, Al + aoff, sz);
            // B hi/lo
            ll boff = (ll)(n0 + row) * K + c0 + c * 8;
            cpasync16(base + 20480u + off, Bh + boff);
            cpasync16(base + 30720u + off, Bl + boff);
        }
        asm volatile("cp.async.commit_group;" ::: "memory");
    };

    load_stage(0);
    load_stage(1);
    load_stage(2);

    for (int s = 0; s < S; s++) {
        if      (s + 2 < S) asm volatile("cp.async.wait_group 2;" ::: "memory");
        else if (s + 1 < S) asm volatile("cp.async.wait_group 1;" ::: "memory");
        else                asm volatile("cp.async.wait_group 0;" ::: "memory");
        __syncthreads();
        if (s + 3 < S) load_stage(s + 3);

        uint32_t base = dbase + (uint32_t)(s & 3) * STAGE_B;
        uint32_t Ahb = base, Alb = base + 10240u, Bhb = base + 20480u, Blb = base + 30720u;

        #pragma unroll
        for (int kk = 0; kk < 2; kk++) {
            uint32_t ah[4][4], al[4][4], bh[2][4], bl[2][4];
            #pragma unroll
            for (int mf = 0; mf < 4; mf++) {
                uint32_t roff = (uint32_t)(((wm*64 + mf*16 + (lane & 15)) * 40
                                            + kk*16 + (lane >> 4) * 8) * 2);
                ldmx4(ah[mf], Ahb + roff);
                ldmx4(al[mf], Alb + roff);
            }
            #pragma unroll
            for (int bt = 0; bt < 2; bt++) {
                int g = lane >> 3;
                uint32_t roff = (uint32_t)(((wn*32 + bt*16 + (g >> 1)*8 + (lane & 7)) * 40
                                            + kk*16 + (g & 1) * 8) * 2);
                ldmx4(bh[bt], Bhb + roff);
                ldmx4(bl[bt], Blb + roff);
            }
            #pragma unroll
            for (int mf = 0; mf < 4; mf++)
                #pragma unroll
                for (int nf = 0; nf < 4; nf++) {
                    uint32_t b0 = bh[nf >> 1][(nf & 1)*2], b1 = bh[nf >> 1][(nf & 1)*2 + 1];
                    mma16816(acc[mf][nf], ah[mf], b0, b1);
                    mma16816(acc[mf][nf], al[mf], b0, b1);
                    mma16816(acc[mf][nf], ah[mf],
                              bl[nf >> 1][(nf & 1)*2], bl[nf >> 1][(nf & 1)*2 + 1]);
                }
        }
    }

    // ---------------- epilogue (register-direct) ----------------
    #pragma unroll
    for (int mf = 0; mf < 4; mf++) {
        int rbase = wm*64 + mf*16 + (lane >> 2);
        #pragma unroll
        for (int half = 0; half < 2; half++) {
            int rloc = rbase + half * 8;
            int cr = s_cout[rloc];
            if (cr < 0) continue;
            #pragma unroll
            for (int nf = 0; nf < 4; nf++) {
                int col = n0 + wn*32 + nf*8 + (lane & 3)*2;
                float v0 = acc[mf][nf][half*2 + 0];
                float v1 = acc[mf][nf][half*2 + 1];
                float2 bv = *(const float2*)&bias[col];
                v0 += bv.x; v1 += bv.y;
                if (EPI == 2) {
                    float2 rv = *(const float2*)(res + (ll)cr*ldc + col);
                    v0 += rv.x; v1 += rv.y;
                }
                if (EPI == 3) {
                    v0 = 0.5f*v0*(1.f + erff(v0*0.70710678118654752f));
                    v1 = 0.5f*v1*(1.f + erff(v1*0.70710678118654752f));
                    __half h0 = __float2half(v0);
                    __half l0 = __float2half(v0 - __half2float(h0));
                    __half h1 = __float2half(v1);
                    __half l1 = __float2half(v1 - __half2float(h1));
                    __half* DH = (__half*)Cv + (ll)cr * N + col;
                    __half* DL = Clo + (ll)cr * N + col;
                    *(__half2*)DH = __halves2half2(h0, h1);
                    *(__half2*)DL = __halves2half2(l0, l1);
                } else {
                    *(float2*)((float*)Cv + (ll)cr*ldc + col) = make_float2(v0, v1);
                }
            }
        }
    }
}

// ---------------- fp32 tiled SGEMM (attention scores / AV only) ----------------
template<bool TB>
__global__ __launch_bounds__(256)
void gemm_k(int M, int N, int Kd,
            const float* __restrict__ A, int lda,
            const float* __restrict__ Bw, int ldb,
            float* __restrict__ C, int ldc,
            float alpha, int zdiv,
            ll sA1, ll sA2, ll sB1, ll sB2, ll sC1, ll sC2)
{
    int z = blockIdx.z;
    int zb = z / zdiv, zh = z % zdiv;
    ll aoff = zb*sA1 + zh*sA2;
    ll boff = zb*sB1 + zh*sB2;
    ll coff = zb*sC1 + zh*sC2;
    int m0 = blockIdx.y * 128;
    int n0 = blockIdx.x * 128;

    __shared__ float As[8][128];
    __shared__ float Bs[8][128];
    float acc[8][8];
    #pragma unroll
    for (int i = 0; i < 8; i++)
        #pragma unroll
        for (int j = 0; j < 8; j++) acc[i][j] = 0.f;

    int tid = threadIdx.x;
    int lr  = tid >> 1;
    int lk  = (tid & 1) * 4;
    const float* Arow = A + aoff + (ll)(m0 + lr) * lda;
    const float* Brow;
    int bk = 0, bn = 0;
    if (TB) {
        Brow = Bw + boff + (ll)(n0 + lr) * ldb;
    } else {
        bk = tid >> 5; bn = (tid & 31) * 4;
        Brow = Bw + boff + (ll)bk * ldb + n0 + bn;
    }
    int tx = tid & 15, ty = tid >> 4;

    for (int kk = 0; kk < Kd; kk += 8) {
        float4 av = *(const float4*)(Arow + kk + lk);
        As[lk+0][lr] = av.x; As[lk+1][lr] = av.y;
        As[lk+2][lr] = av.z; As[lk+3][lr] = av.w;
        if (TB) {
            float4 bv = *(const float4*)(Brow + kk + lk);
            Bs[lk+0][lr] = bv.x; Bs[lk+1][lr] = bv.y;
            Bs[lk+2][lr] = bv.z; Bs[lk+3][lr] = bv.w;
        } else {
            float4 bv = *(const float4*)(Brow + (ll)kk * ldb);
            *(float4*)&Bs[bk][bn] = bv;
        }
        __syncthreads();
        #pragma unroll
        for (int k = 0; k < 8; k++) {
            float4 a0 = *(const float4*)&As[k][ty*8];
            float4 a1 = *(const float4*)&As[k][ty*8+4];
            float4 b0 = *(const float4*)&Bs[k][tx*8];
            float4 b1 = *(const float4*)&Bs[k][tx*8+4];
            float a[8] = {a0.x,a0.y,a0.z,a0.w,a1.x,a1.y,a1.z,a1.w};
            float b[8] = {b0.x,b0.y,b0.z,b0.w,b1.x,b1.y,b1.z,b1.w};
            #pragma unroll
            for (int i = 0; i < 8; i++)
                #pragma unroll
                for (int j = 0; j < 8; j++)
                    acc[i][j] += a[i]*b[j];
        }
        __syncthreads();
    }
    #pragma unroll
    for (int i = 0; i < 8; i++) {
        float* Crow = C + coff + (ll)(m0 + ty*8 + i)*ldc + n0 + tx*8;
        #pragma unroll
        for (int j = 0; j < 8; j++) Crow[j] = acc[i][j] * alpha;
    }
}

// ---------------- small kernels ----------------
__global__ void embed_k(const int* __restrict__ ids, const float* __restrict__ emb) {
    int idx = blockIdx.x*256 + threadIdx.x;
    int t = idx / Hq, h = idx - t*Hq;
    g_x[idx] = emb[(ll)ids[t]*Hq + h];
}

__global__ void ln_k(const float* __restrict__ x, const float* __restrict__ g,
                     const float* __restrict__ b, float* __restrict__ o,
                     __half* __restrict__ oH, __half* __restrict__ oL) {
    int t = blockIdx.x;
    const float* xr = x + (ll)t*Hq;
    int tid = threadIdx.x;
    float v[4]; float s = 0.f;
    #pragma unroll
    for (int i = 0; i < 4; i++) { v[i] = xr[tid + 256*i]; s += v[i]; }
    __shared__ float red[256];
    red[tid] = s; __syncthreads();
    for (int o2 = 128; o2; o2 >>= 1) { if (tid < o2) red[tid] += red[tid+o2]; __syncthreads(); }
    float mu = red[0] * (1.f/Hq);
    __syncthreads();
    s = 0.f;
    #pragma unroll
    for (int i = 0; i < 4; i++) { float d = v[i]-mu; s += d*d; }
    red[tid] = s; __syncthreads();
    for (int o2 = 128; o2; o2 >>= 1) { if (tid < o2) red[tid] += red[tid+o2]; __syncthreads(); }
    float inv = rsqrtf(red[0]*(1.f/Hq) + 1e-5f);
    float* orow = o + (ll)t*Hq;
    __half* hr = oH + (ll)t*Hq;
    __half* lr = oL + (ll)t*Hq;
    #pragma unroll
    for (int i = 0; i < 4; i++) {
        int h = tid + 256*i;
        float y = (v[i]-mu)*inv*g[h] + b[h];
        orow[h] = y;
        __half hi = __float2half(y);
        hr[h] = hi;
        lr[h] = __float2half(y - __half2float(hi));
    }
}

__global__ void softmax_k(float* __restrict__ sc) {
    ll row = blockIdx.x;
    float* r = sc + row*Sq;
    int tid = threadIdx.x;
    float a = r[tid], b = r[tid+256];
    __shared__ float red[256];
    red[tid] = fmaxf(a,b); __syncthreads();
    for (int o = 128; o; o >>= 1) { if (tid < o) red[tid] = fmaxf(red[tid], red[tid+o]); __syncthreads(); }
    float m = red[0]; __syncthreads();
    a = expf(a-m); b = expf(b-m);
    red[tid] = a+b; __syncthreads();
    for (int o = 128; o; o >>= 1) { if (tid < o) red[tid] += red[tid+o]; __syncthreads(); }
    float inv = 1.f/red[0];
    r[tid] = a*inv; r[tid+256] = b*inv;
}

__global__ void zero_cnt_k() { if (threadIdx.x < Eq) g_cnt[threadIdx.x] = 0; }
__global__ void zero_aux_k() { g_aux[0] = 0.f; }

__global__ void router_k(const float* __restrict__ n2, const float* __restrict__ rw,
                         const float* __restrict__ rb) {
    int t = blockIdx.x;
    int w = threadIdx.x >> 5, lane = threadIdx.x & 31;
    const float* xr = n2 + (ll)t*Hq;
    const float* wr = rw + (ll)w*Hq;
    float s = 0.f;
    for (int h = lane; h < Hq; h += 32) s += xr[h]*wr[h];
    #pragma unroll
    for (int o = 16; o; o >>= 1) s += __shfl_xor_sync(0xffffffffu, s, o);
    __shared__ float lg[Eq];
    if (lane == 0) lg[w] = s + rb[w];
    __syncthreads();
    if (threadIdx.x == 0) {
        int b0 = 0; float v0 = lg[0];
        for (int e = 1; e < Eq; e++) if (lg[e] > v0) { v0 = lg[e]; b0 = e; }
        int b1 = -1; float v1 = -3.4e38f;
        for (int e = 0; e < Eq; e++) { if (e == b0) continue; if (lg[e] > v1) { v1 = lg[e]; b1 = e; } }
        g_sel[2*t]   = b0;
        g_sel[2*t+1] = b1;
        atomicAdd(&g_cnt[b0], 1);
        atomicAdd(&g_cnt[b1], 1);
    }
}

__global__ void offsets_k() {
    int s = 0;
    for (int e = 0; e < Eq; e++) { g_off[e] = s; g_cur[e] = s; s += g_cnt[e]; }
}

__global__ void build_k() {
    int t = blockIdx.x*256 + threadIdx.x;
    if (t >= Tq) return;
    #pragma unroll
    for (int slot = 0; slot < 2; slot++) {
        int e = g_sel[2*t + slot];
        int p = atomicAdd(&g_cur[e], 1);
        g_tokmap[p] = t;
        g_outmap[p] = slot*Tq + t;
    }
}

__global__ void aux_k() {
    float s = 0.f;
    const float target = (float)Tq / (float)Eq;
    for (int e = 0; e < Eq; e++) { float d = (float)g_cnt[e] - target; s += d*d; }
    g_aux[0] += 0.01f * s / (float)Eq;
}

__global__ void combine_k() {
    int idx = blockIdx.x*256 + threadIdx.x;
    g_x[idx] += g_moe[idx] + g_moe[(ll)Tq*Hq + idx];
}

__global__ void tail_k(float* __restrict__ out, ll out_size) {
    ll base = (ll)Tq * Vq;
    for (ll i = base + threadIdx.x; i < out_size; i += 256)
        out[i] = g_aux[0];
}

// ---------------- launch ----------------
static inline int cv8blocks(ll total) { return (int)((total/8 + 255) / 256); }

extern "C" void kernel_launch(void* const* d_in, const int* in_sizes, int n_in,
                              void* d_out, int out_size) {
    const int*   ids  = (const int*)  d_in[0];
    const float* emb  = (const float*)d_in[1];
    const float* ln1g = (const float*)d_in[2];
    const float* ln1b = (const float*)d_in[3];
    const float* aiw  = (const float*)d_in[4];
    const float* aib  = (const float*)d_in[5];
    const float* aow  = (const float*)d_in[6];
    const float* aob  = (const float*)d_in[7];
    const float* ln2g = (const float*)d_in[8];
    const float* ln2b = (const float*)d_in[9];
    const float* rw   = (const float*)d_in[10];
    const float* rb   = (const float*)d_in[11];
    const float* f1w  = (const float*)d_in[12];
    const float* f1b  = (const float*)d_in[13];
    const float* f2w  = (const float*)d_in[14];
    const float* f2b  = (const float*)d_in[15];
    const float* lmw  = (const float*)d_in[16];
    const float* lmb  = (const float*)d_in[17];
    float* out = (float*)d_out;

    cudaFuncSetAttribute(bgemm<1,0>, cudaFuncAttributeMaxDynamicSharedMemorySize, DSMB);
    cudaFuncSetAttribute(bgemm<2,0>, cudaFuncAttributeMaxDynamicSharedMemorySize, DSMB);
    cudaFuncSetAttribute(bgemm<3,1>, cudaFuncAttributeMaxDynamicSharedMemorySize, DSMB);
    cudaFuncSetAttribute(bgemm<1,2>, cudaFuncAttributeMaxDynamicSharedMemorySize, DSMB);

    float *px, *pn, *pqkv, *psc, *pao, *pmoe;
    cudaGetSymbolAddress((void**)&px,   g_x);
    cudaGetSymbolAddress((void**)&pn,   g_n);
    cudaGetSymbolAddress((void**)&pqkv, g_qkv);
    cudaGetSymbolAddress((void**)&psc,  g_scores);
    cudaGetSymbolAddress((void**)&pao,  g_attno);
    cudaGetSymbolAddress((void**)&pmoe, g_moe);
    __half *winH,*winL,*woutH,*woutL,*f1H,*f1L,*f2H,*f2L,*lmH,*lmL;
    __half *nH,*nL,*aoH,*aoL,*xH,*xL,*hH,*hL;
    cudaGetSymbolAddress((void**)&winH,  g_winH);  cudaGetSymbolAddress((void**)&winL,  g_winL);
    cudaGetSymbolAddress((void**)&woutH, g_woutH); cudaGetSymbolAddress((void**)&woutL, g_woutL);
    cudaGetSymbolAddress((void**)&f1H,   g_f1H);   cudaGetSymbolAddress((void**)&f1L,   g_f1L);
    cudaGetSymbolAddress((void**)&f2H,   g_f2H);   cudaGetSymbolAddress((void**)&f2L,   g_f2L);
    cudaGetSymbolAddress((void**)&lmH,   g_lmH);   cudaGetSymbolAddress((void**)&lmL,   g_lmL);
    cudaGetSymbolAddress((void**)&nH,    g_nH);    cudaGetSymbolAddress((void**)&nL,    g_nL);
    cudaGetSymbolAddress((void**)&aoH,   g_aoH);   cudaGetSymbolAddress((void**)&aoL,   g_aoL);
    cudaGetSymbolAddress((void**)&xH,    g_xH);    cudaGetSymbolAddress((void**)&xL,    g_xL);
    cudaGetSymbolAddress((void**)&hH,    g_hH);    cudaGetSymbolAddress((void**)&hL,    g_hL);

    // ---- weight conversions (fp32 -> fp16 hi/lo planes) ----
    cvt2_k<<<cv8blocks((ll)Lq*3*Hq*Hq),  256>>>(aiw, winH,  winL,  (ll)Lq*3*Hq*Hq);
    cvt2_k<<<cv8blocks((ll)Lq*Hq*Hq),    256>>>(aow, woutH, woutL, (ll)Lq*Hq*Hq);
    cvt2_k<<<cv8blocks((ll)Lq*Eq*Iq*Hq), 256>>>(f1w, f1H,   f1L,   (ll)Lq*Eq*Iq*Hq);
    cvt2_k<<<cv8blocks((ll)Lq*Eq*Hq*Iq), 256>>>(f2w, f2H,   f2L,   (ll)Lq*Eq*Hq*Iq);
    cvt2_k<<<cv8blocks((ll)Vq*Hq),       256>>>(lmw, lmH,   lmL,   (ll)Vq*Hq);

    zero_aux_k<<<1,1>>>();
    embed_k<<<(Tq*Hq)/256, 256>>>(ids, emb);

    for (int l = 0; l < Lq; l++) {
        // --- attention ---
        ln_k<<<Tq,256>>>(px, ln1g + (ll)l*Hq, ln1b + (ll)l*Hq, pn, nH, nL);

        // qkv = n1 @ W_in^T + b
        bgemm<1,0><<<dim3(Tq/128, 3*Hq/128, 1), 256, DSMB>>>(
            Tq, 3*Hq, Hq, nH, nL,
            winH + (ll)l*3*Hq*Hq, winL + (ll)l*3*Hq*Hq,
            pqkv, 3*Hq, aib + (ll)l*3*Hq, nullptr, nullptr, 0, 0);

        // scores = q @ k^T / sqrt(DH)  (fp32, batched over B*NH)
        gemm_k<true><<<dim3(Sq/128, Sq/128, Bq*NHq), 256>>>(
            Sq, Sq, DHq, pqkv, 3*Hq, pqkv + Hq, 3*Hq, psc, Sq,
            1.f/11.313708498984761f, NHq,
            (ll)Sq*3*Hq, DHq, (ll)Sq*3*Hq, DHq, (ll)NHq*Sq*Sq, (ll)Sq*Sq);

        softmax_k<<<Bq*NHq*Sq, 256>>>(psc);

        // o = attn @ v  (fp32, NN)
        gemm_k<false><<<dim3(DHq/128, Sq/128, Bq*NHq), 256>>>(
            Sq, DHq, Sq, psc, Sq, pqkv + 2*Hq, 3*Hq, pao, Hq,
            1.f, NHq,
            (ll)NHq*Sq*Sq, (ll)Sq*Sq, (ll)Sq*3*Hq, DHq, (ll)Sq*Hq, DHq);

        // convert attn output to hi/lo planes
        cvt2_k<<<cv8blocks((ll)Tq*Hq), 256>>>(pao, aoH, aoL, (ll)Tq*Hq);

        // x = x + o @ W_out^T + b
        bgemm<2,0><<<dim3(Tq/128, Hq/128, 1), 256, DSMB>>>(
            Tq, Hq, Hq, aoH, aoL,
            woutH + (ll)l*Hq*Hq, woutL + (ll)l*Hq*Hq,
            px, Hq, aob + (ll)l*Hq, px, nullptr, 0, 0);

        // --- MoE ---
        ln_k<<<Tq,256>>>(px, ln2g + (ll)l*Hq, ln2b + (ll)l*Hq, pn, nH, nL);

        zero_cnt_k<<<1,32>>>();
        router_k<<<Tq,256>>>(pn, rw + (ll)l*Eq*Hq, rb + (ll)l*Eq);
        offsets_k<<<1,1>>>();
        build_k<<<Tq/256,256>>>();
        aux_k<<<1,1>>>();

        // fc1: gather, gelu, write hi/lo hidden planes
        bgemm<3,1><<<dim3(Tq/128, Iq/128, Eq), 256, DSMB>>>(
            Tq, Iq, Hq, nH, nL,
            f1H + (ll)l*Eq*Iq*Hq, f1L + (ll)l*Eq*Iq*Hq,
            hH, Iq, f1b + (ll)l*Eq*Iq, nullptr, hL,
            (ll)Iq*Hq, (ll)Iq);

        // fc2: scatter to per-slot fp32 buffers
        bgemm<1,2><<<dim3(Tq/128, Hq/128, Eq), 256, DSMB>>>(
            Tq, Hq, Iq, hH, hL,
            f2H + (ll)l*Eq*Hq*Iq, f2L + (ll)l*Eq*Hq*Iq,
            pmoe, Hq, f2b + (ll)l*Eq*Hq, nullptr, nullptr,
            (ll)Hq*Iq, (ll)Hq);

        combine_k<<<(Tq*Hq)/256, 256>>>();
    }

    // lm head
    cvt2_k<<<cv8blocks((ll)Tq*Hq), 256>>>(px, xH, xL, (ll)Tq*Hq);
    bgemm<1,0><<<dim3(Tq/128, Vq/128, 1), 256, DSMB>>>(
        Tq, Vq, Hq, xH, xL, lmH, lmL, out, Vq,
        lmb, nullptr, nullptr, 0, 0);

    tail_k<<<1,256>>>(out, (ll)out_size);
}

// round 5
// speedup vs baseline: 2.5200x; 1.0861x over previous
#include <cuda_runtime.h>
#include <cuda_fp16.h>
#include <math.h>
#include <stdint.h>

// ---------------- problem constants ----------------
#define Bq 4
#define Sq 512
#define Hq 1024
#define Iq 4096
#define Eq 8
#define Vq 32000
#define Lq 2
#define NHq 8
#define DHq 128
#define Tq (Bq*Sq)          // 2048 tokens

typedef long long ll;

__device__ __forceinline__ uint32_t smem_u32(const void* p) {
    uint32_t a;
    asm("{ .reg .u64 t; cvta.to.shared.u64 t, %1; cvt.u32.u64 %0, t; }" : "=r"(a) : "l"(p));
    return a;
}

// ---------------- device scratch (static, no allocs) ----------------
__device__ float g_x[Tq*Hq];
__device__ float g_n[Tq*Hq];
__device__ float g_scores[Bq*NHq*Sq*Sq];
__device__ float g_moe[2*Tq*Hq];
__device__ int   g_sel[Tq*2];
__device__ int   g_cnt[Eq];
__device__ int   g_off[Eq];
__device__ int   g_cur[Eq];
__device__ int   g_tokmap[2*Tq];
__device__ int   g_outmap[2*Tq];
__device__ float g_aux[1];
__device__ float g_zb[DHq];      // zero bias
// fp16 hi/lo planes
__device__ __half g_winH[Lq*3*Hq*Hq],  g_winL[Lq*3*Hq*Hq];
__device__ __half g_woutH[Lq*Hq*Hq],   g_woutL[Lq*Hq*Hq];
__device__ __half g_f1H[(size_t)Lq*Eq*Iq*Hq], g_f1L[(size_t)Lq*Eq*Iq*Hq];
__device__ __half g_f2H[(size_t)Lq*Eq*Hq*Iq], g_f2L[(size_t)Lq*Eq*Hq*Iq];
__device__ __half g_lmH[(size_t)Vq*Hq], g_lmL[(size_t)Vq*Hq];
__device__ __half g_nH[Tq*Hq],  g_nL[Tq*Hq];
__device__ __half g_qkvH[Tq*3*Hq], g_qkvL[Tq*3*Hq];
__device__ __half g_vTH[Tq*Hq], g_vTL[Tq*Hq];
__device__ __half g_pH[(size_t)Bq*NHq*Sq*Sq], g_pL[(size_t)Bq*NHq*Sq*Sq];
__device__ __half g_aoH[Tq*Hq], g_aoL[Tq*Hq];
__device__ __half g_xH[Tq*Hq],  g_xL[Tq*Hq];
__device__ __half g_hH[(size_t)2*Tq*Iq], g_hL[(size_t)2*Tq*Iq];

// ---------------- split conversion: fp32 -> (hi, lo) fp16 planes ----------------
__global__ void cvt2_k(const float* __restrict__ src, __half* __restrict__ hi,
                       __half* __restrict__ lo, ll total) {
    ll i = ((ll)blockIdx.x * 256 + threadIdx.x) * 8;
    if (i >= total) return;
    float4 a = *(const float4*)(src + i);
    float4 b = *(const float4*)(src + i + 4);
    float v[8] = {a.x, a.y, a.z, a.w, b.x, b.y, b.z, b.w};
    __align__(16) __half h[8];
    __align__(16) __half l[8];
    #pragma unroll
    for (int j = 0; j < 8; j++) {
        h[j] = __float2half(v[j]);
        l[j] = __float2half(v[j] - __half2float(h[j]));
    }
    *(uint4*)(hi + i) = *(const uint4*)h;
    *(uint4*)(lo + i) = *(const uint4*)l;
}

// ---------------- HMMA fp16 split GEMM ----------------
// C[M,N] = (Ah+Al)[M,K] x (Bh+Bl)[N,K]^T  via 3 terms: Ah*Bh + Al*Bh + Ah*Bl
// CTA tile 128x128, BK=32, 4-stage cp.async pipeline, 8 warps (2x4).
// EPI: 0=alpha (f32 out), 1=bias(f32), 2=bias+res(f32), 3=bias+gelu->planes,
//      4=bias->planes.
// MOE: 0 dense/batched, 1 gather-A/compact-C, 2 compact-A/scatter-C.
#define STAGE_B 40960u     // 4 tiles x 128 x 40 halves x 2B
#define DSMB (4*40960)

__device__ __forceinline__ void ldmx4(uint32_t* r, uint32_t addr) {
    asm volatile("ldmatrix.sync.aligned.m8n8.x4.shared.b16 {%0,%1,%2,%3}, [%4];"
        : "=r"(r[0]), "=r"(r[1]), "=r"(r[2]), "=r"(r[3]) : "r"(addr));
}
__device__ __forceinline__ void mma16816(float* c, const uint32_t* a, uint32_t b0, uint32_t b1) {
    asm volatile("mma.sync.aligned.m16n8k16.row.col.f32.f16.f16.f32 "
        "{%0,%1,%2,%3}, {%4,%5,%6,%7}, {%8,%9}, {%0,%1,%2,%3};"
        : "+f"(c[0]), "+f"(c[1]), "+f"(c[2]), "+f"(c[3])
        : "r"(a[0]), "r"(a[1]), "r"(a[2]), "r"(a[3]), "r"(b0), "r"(b1));
}
__device__ __forceinline__ void cpasync16(uint32_t dst, const void* src) {
    asm volatile("cp.async.cg.shared.global [%0], [%1], 16;" :: "r"(dst), "l"(src));
}
__device__ __forceinline__ void cpasync16z(uint32_t dst, const void* src, uint32_t sz) {
    asm volatile("cp.async.cg.shared.global [%0], [%1], 16, %2;" :: "r"(dst), "l"(src), "r"(sz));
}

template<int EPI, int MOE>
__global__ __launch_bounds__(256, 1)
void bgemm(int M, int N, int K,
           const __half* __restrict__ Ah, const __half* __restrict__ Al, int lda,
           const __half* __restrict__ Bh, const __half* __restrict__ Bl, int ldb,
           void* __restrict__ Cv, __half* __restrict__ Clo, int ldc,
           const float* __restrict__ bias,
           const float* __restrict__ res,
           float alpha, int zdiv,
           ll sA1, ll sA2, ll sB1, ll sB2, ll sC1, ll sC2,
           ll sBz, ll sBiasZ)
{
    int Me = M, rowbase = 0;
    ll coff = 0;
    if (MOE) {
        int z = blockIdx.z;
        Me = g_cnt[z]; rowbase = g_off[z];
        Bh += (ll)z * sBz; Bl += (ll)z * sBz;
        bias += (ll)z * sBiasZ;
    } else {
        int z = blockIdx.z;
        int zb = z / zdiv, zh = z - zb * zdiv;
        Ah += zb*sA1 + zh*sA2; Al += zb*sA1 + zh*sA2;
        Bh += zb*sB1 + zh*sB2; Bl += zb*sB1 + zh*sB2;
        coff = zb*sC1 + zh*sC2;
    }
    int m0 = blockIdx.x * 128;
    if (m0 >= Me) return;
    int n0 = blockIdx.y * 128;

    __shared__ int s_row[128];
    __shared__ int s_cout[128];
    extern __shared__ __align__(16) char dsm[];
    uint32_t dbase = smem_u32(dsm);

    int tid = threadIdx.x, lane = tid & 31, wid = tid >> 5;
    int wm = wid >> 2, wn = wid & 3;   // 2 x 4 warp grid

    if (tid < 128) {
        int grow = m0 + tid;
        int rid = -1, cid = -1;
        if (grow < Me) {
            if      (MOE == 1) { rid = g_tokmap[rowbase + grow]; cid = rowbase + grow; }
            else if (MOE == 2) { rid = rowbase + grow;           cid = g_outmap[rowbase + grow]; }
            else               { rid = grow;                     cid = grow; }
        }
        s_row[tid] = rid; s_cout[tid] = cid;
    }
    __syncthreads();

    float acc[4][4][4];
    #pragma unroll
    for (int a = 0; a < 4; a++)
        #pragma unroll
        for (int b = 0; b < 4; b++)
            #pragma unroll
            for (int c = 0; c < 4; c++) acc[a][b][c] = 0.f;

    int S = K / 32;

    auto load_stage = [&](int s) {
        int c0 = s * 32;
        uint32_t base = dbase + (uint32_t)(s & 3) * STAGE_B;
        #pragma unroll
        for (int i = 0; i < 2; i++) {
            int idx = tid + i * 256;
            int row = idx >> 2, c = idx & 3;
            uint32_t off = (uint32_t)(row * 80 + c * 16);
            // A hi/lo (gathered, zero-filled when row invalid)
            int r = s_row[row];
            ll aoff = (r >= 0) ? ((ll)r * lda + c0 + c * 8) : 0;
            uint32_t sz = (r >= 0) ? 16u : 0u;
            cpasync16z(base + off,          Ah + aoff, sz);
            cpasync16z(base + 10240u + off, Al + aoff, sz);
            // B hi/lo
            ll boff = (ll)(n0 + row) * ldb + c0 + c * 8;
            cpasync16(base + 20480u + off, Bh + boff);
            cpasync16(base + 30720u + off, Bl + boff);
        }
        asm volatile("cp.async.commit_group;" ::: "memory");
    };

    load_stage(0);
    load_stage(1);
    load_stage(2);

    for (int s = 0; s < S; s++) {
        if      (s + 2 < S) asm volatile("cp.async.wait_group 2;" ::: "memory");
        else if (s + 1 < S) asm volatile("cp.async.wait_group 1;" ::: "memory");
        else                asm volatile("cp.async.wait_group 0;" ::: "memory");
        __syncthreads();
        if (s + 3 < S) load_stage(s + 3);

        uint32_t base = dbase + (uint32_t)(s & 3) * STAGE_B;
        uint32_t Ahb = base, Alb = base + 10240u, Bhb = base + 20480u, Blb = base + 30720u;

        #pragma unroll
        for (int kk = 0; kk < 2; kk++) {
            uint32_t ah[4][4], al[4][4], bh[2][4], bl[2][4];
            #pragma unroll
            for (int mf = 0; mf < 4; mf++) {
                uint32_t roff = (uint32_t)(((wm*64 + mf*16 + (lane & 15)) * 40
                                            + kk*16 + (lane >> 4) * 8) * 2);
                ldmx4(ah[mf], Ahb + roff);
                ldmx4(al[mf], Alb + roff);
            }
            #pragma unroll
            for (int bt = 0; bt < 2; bt++) {
                int g = lane >> 3;
                uint32_t roff = (uint32_t)(((wn*32 + bt*16 + (g >> 1)*8 + (lane & 7)) * 40
                                            + kk*16 + (g & 1) * 8) * 2);
                ldmx4(bh[bt], Bhb + roff);
                ldmx4(bl[bt], Blb + roff);
            }
            #pragma unroll
            for (int mf = 0; mf < 4; mf++)
                #pragma unroll
                for (int nf = 0; nf < 4; nf++) {
                    uint32_t b0 = bh[nf >> 1][(nf & 1)*2], b1 = bh[nf >> 1][(nf & 1)*2 + 1];
                    mma16816(acc[mf][nf], ah[mf], b0, b1);
                    mma16816(acc[mf][nf], al[mf], b0, b1);
                    mma16816(acc[mf][nf], ah[mf],
                              bl[nf >> 1][(nf & 1)*2], bl[nf >> 1][(nf & 1)*2 + 1]);
                }
        }
    }

    // ---------------- epilogue (register-direct) ----------------
    #pragma unroll
    for (int mf = 0; mf < 4; mf++) {
        int rbase = wm*64 + mf*16 + (lane >> 2);
        #pragma unroll
        for (int half = 0; half < 2; half++) {
            int rloc = rbase + half * 8;
            int cr = s_cout[rloc];
            if (cr < 0) continue;
            #pragma unroll
            for (int nf = 0; nf < 4; nf++) {
                int col = n0 + wn*32 + nf*8 + (lane & 3)*2;
                float v0 = acc[mf][nf][half*2 + 0] * alpha;
                float v1 = acc[mf][nf][half*2 + 1] * alpha;
                if (EPI >= 1) {
                    float2 bv = *(const float2*)&bias[col];
                    v0 += bv.x; v1 += bv.y;
                }
                if (EPI == 2) {
                    float2 rv = *(const float2*)(res + (ll)cr*ldc + col);
                    v0 += rv.x; v1 += rv.y;
                }
                if (EPI == 3 || EPI == 4) {
                    if (EPI == 3) {
                        v0 = 0.5f*v0*(1.f + erff(v0*0.70710678118654752f));
                        v1 = 0.5f*v1*(1.f + erff(v1*0.70710678118654752f));
                    }
                    __half h0 = __float2half(v0);
                    __half l0 = __float2half(v0 - __half2float(h0));
                    __half h1 = __float2half(v1);
                    __half l1 = __float2half(v1 - __half2float(h1));
                    __half* DH = (__half*)Cv + coff + (ll)cr * ldc + col;
                    __half* DL = Clo + coff + (ll)cr * ldc + col;
                    *(__half2*)DH = __halves2half2(h0, h1);
                    *(__half2*)DL = __halves2half2(l0, l1);
                } else {
                    *(float2*)((float*)Cv + coff + (ll)cr*ldc + col) = make_float2(v0, v1);
                }
            }
        }
    }
}

// ---------------- V transpose: qkv planes -> per-(b,h) V^T planes ----------------
__global__ void vtrans_k(const __half* __restrict__ qH, const __half* __restrict__ qL,
                         __half* __restrict__ vTH, __half* __restrict__ vTL) {
    int z = blockIdx.z; int b = z >> 3; int h = z & 7;
    int d0 = blockIdx.y * 32;
    int s0 = blockIdx.x * 32;
    __shared__ __half tH[32][33], tL[32][33];
    int tx = threadIdx.x, ty = threadIdx.y;   // 32 x 8
    #pragma unroll
    for (int i = 0; i < 4; i++) {
        int sl = ty*4 + i;
        ll src = (ll)(b*Sq + s0 + sl)*(3*Hq) + 2*Hq + h*DHq + d0 + tx;
        tH[sl][tx] = qH[src];
        tL[sl][tx] = qL[src];
    }
    __syncthreads();
    #pragma unroll
    for (int i = 0; i < 4; i++) {
        int dl = ty*4 + i;
        ll dst = ((ll)z*DHq + d0 + dl)*Sq + s0 + tx;
        vTH[dst] = tH[tx][dl];
        vTL[dst] = tL[tx][dl];
    }
}

// ---------------- small kernels ----------------
__global__ void embed_k(const int* __restrict__ ids, const float* __restrict__ emb) {
    int idx = blockIdx.x*256 + threadIdx.x;
    int t = idx / Hq, h = idx - t*Hq;
    g_x[idx] = emb[(ll)ids[t]*Hq + h];
}

__global__ void ln_k(const float* __restrict__ x, const float* __restrict__ g,
                     const float* __restrict__ b, float* __restrict__ o,
                     __half* __restrict__ oH, __half* __restrict__ oL) {
    int t = blockIdx.x;
    const float* xr = x + (ll)t*Hq;
    int tid = threadIdx.x;
    float v[4]; float s = 0.f;
    #pragma unroll
    for (int i = 0; i < 4; i++) { v[i] = xr[tid + 256*i]; s += v[i]; }
    __shared__ float red[256];
    red[tid] = s; __syncthreads();
    for (int o2 = 128; o2; o2 >>= 1) { if (tid < o2) red[tid] += red[tid+o2]; __syncthreads(); }
    float mu = red[0] * (1.f/Hq);
    __syncthreads();
    s = 0.f;
    #pragma unroll
    for (int i = 0; i < 4; i++) { float d = v[i]-mu; s += d*d; }
    red[tid] = s; __syncthreads();
    for (int o2 = 128; o2; o2 >>= 1) { if (tid < o2) red[tid] += red[tid+o2]; __syncthreads(); }
    float inv = rsqrtf(red[0]*(1.f/Hq) + 1e-5f);
    float* orow = o + (ll)t*Hq;
    __half* hr = oH + (ll)t*Hq;
    __half* lr = oL + (ll)t*Hq;
    #pragma unroll
    for (int i = 0; i < 4; i++) {
        int h = tid + 256*i;
        float y = (v[i]-mu)*inv*g[h] + b[h];
        orow[h] = y;
        __half hi = __float2half(y);
        hr[h] = hi;
        lr[h] = __float2half(y - __half2float(hi));
    }
}

__global__ void softmax_k(const float* __restrict__ sc,
                          __half* __restrict__ pH, __half* __restrict__ pL) {
    ll row = blockIdx.x;
    const float* r = sc + row*Sq;
    int tid = threadIdx.x;
    float a = r[tid], b = r[tid+256];
    __shared__ float red[256];
    red[tid] = fmaxf(a,b); __syncthreads();
    for (int o = 128; o; o >>= 1) { if (tid < o) red[tid] = fmaxf(red[tid], red[tid+o]); __syncthreads(); }
    float m = red[0]; __syncthreads();
    a = expf(a-m); b = expf(b-m);
    red[tid] = a+b; __syncthreads();
    for (int o = 128; o; o >>= 1) { if (tid < o) red[tid] += red[tid+o]; __syncthreads(); }
    float inv = 1.f/red[0];
    a *= inv; b *= inv;
    __half ha = __float2half(a), hb = __float2half(b);
    pH[row*Sq + tid]       = ha;
    pL[row*Sq + tid]       = __float2half(a - __half2float(ha));
    pH[row*Sq + tid + 256] = hb;
    pL[row*Sq + tid + 256] = __float2half(b - __half2float(hb));
}

__global__ void zero_cnt_k() { if (threadIdx.x < Eq) g_cnt[threadIdx.x] = 0; }
__global__ void zero_aux_k() {
    if (threadIdx.x == 0) g_aux[0] = 0.f;
    if (threadIdx.x < DHq) g_zb[threadIdx.x] = 0.f;
}

__global__ void router_k(const float* __restrict__ n2, const float* __restrict__ rw,
                         const float* __restrict__ rb) {
    int t = blockIdx.x;
    int w = threadIdx.x >> 5, lane = threadIdx.x & 31;
    const float* xr = n2 + (ll)t*Hq;
    const float* wr = rw + (ll)w*Hq;
    float s = 0.f;
    for (int h = lane; h < Hq; h += 32) s += xr[h]*wr[h];
    #pragma unroll
    for (int o = 16; o; o >>= 1) s += __shfl_xor_sync(0xffffffffu, s, o);
    __shared__ float lg[Eq];
    if (lane == 0) lg[w] = s + rb[w];
    __syncthreads();
    if (threadIdx.x == 0) {
        int b0 = 0; float v0 = lg[0];
        for (int e = 1; e < Eq; e++) if (lg[e] > v0) { v0 = lg[e]; b0 = e; }
        int b1 = -1; float v1 = -3.4e38f;
        for (int e = 0; e < Eq; e++) { if (e == b0) continue; if (lg[e] > v1) { v1 = lg[e]; b1 = e; } }
        g_sel[2*t]   = b0;
        g_sel[2*t+1] = b1;
        atomicAdd(&g_cnt[b0], 1);
        atomicAdd(&g_cnt[b1], 1);
    }
}

__global__ void offsets_k() {
    int s = 0;
    for (int e = 0; e < Eq; e++) { g_off[e] = s; g_cur[e] = s; s += g_cnt[e]; }
}

__global__ void build_k() {
    int t = blockIdx.x*256 + threadIdx.x;
    if (t >= Tq) return;
    #pragma unroll
    for (int slot = 0; slot < 2; slot++) {
        int e = g_sel[2*t + slot];
        int p = atomicAdd(&g_cur[e], 1);
        g_tokmap[p] = t;
        g_outmap[p] = slot*Tq + t;
    }
}

__global__ void aux_k() {
    float s = 0.f;
    const float target = (float)Tq / (float)Eq;
    for (int e = 0; e < Eq; e++) { float d = (float)g_cnt[e] - target; s += d*d; }
    g_aux[0] += 0.01f * s / (float)Eq;
}

__global__ void combine_k() {
    int idx = blockIdx.x*256 + threadIdx.x;
    g_x[idx] += g_moe[idx] + g_moe[(ll)Tq*Hq + idx];
}

__global__ void tail_k(float* __restrict__ out, ll out_size) {
    ll base = (ll)Tq * Vq;
    for (ll i = base + threadIdx.x; i < out_size; i += 256)
        out[i] = g_aux[0];
}

// ---------------- launch ----------------
static inline int cv8blocks(ll total) { return (int)((total/8 + 255) / 256); }

extern "C" void kernel_launch(void* const* d_in, const int* in_sizes, int n_in,
                              void* d_out, int out_size) {
    const int*   ids  = (const int*)  d_in[0];
    const float* emb  = (const float*)d_in[1];
    const float* ln1g = (const float*)d_in[2];
    const float* ln1b = (const float*)d_in[3];
    const float* aiw  = (const float*)d_in[4];
    const float* aib  = (const float*)d_in[5];
    const float* aow  = (const float*)d_in[6];
    const float* aob  = (const float*)d_in[7];
    const float* ln2g = (const float*)d_in[8];
    const float* ln2b = (const float*)d_in[9];
    const float* rw   = (const float*)d_in[10];
    const float* rb   = (const float*)d_in[11];
    const float* f1w  = (const float*)d_in[12];
    const float* f1b  = (const float*)d_in[13];
    const float* f2w  = (const float*)d_in[14];
    const float* f2b  = (const float*)d_in[15];
    const float* lmw  = (const float*)d_in[16];
    const float* lmb  = (const float*)d_in[17];
    float* out = (float*)d_out;

    cudaFuncSetAttribute(bgemm<0,0>, cudaFuncAttributeMaxDynamicSharedMemorySize, DSMB);
    cudaFuncSetAttribute(bgemm<1,0>, cudaFuncAttributeMaxDynamicSharedMemorySize, DSMB);
    cudaFuncSetAttribute(bgemm<2,0>, cudaFuncAttributeMaxDynamicSharedMemorySize, DSMB);
    cudaFuncSetAttribute(bgemm<4,0>, cudaFuncAttributeMaxDynamicSharedMemorySize, DSMB);
    cudaFuncSetAttribute(bgemm<3,1>, cudaFuncAttributeMaxDynamicSharedMemorySize, DSMB);
    cudaFuncSetAttribute(bgemm<1,2>, cudaFuncAttributeMaxDynamicSharedMemorySize, DSMB);

    float *px, *pn, *psc, *pmoe;
    cudaGetSymbolAddress((void**)&px,   g_x);
    cudaGetSymbolAddress((void**)&pn,   g_n);
    cudaGetSymbolAddress((void**)&psc,  g_scores);
    cudaGetSymbolAddress((void**)&pmoe, g_moe);
    float* pzb; cudaGetSymbolAddress((void**)&pzb, g_zb);
    __half *winH,*winL,*woutH,*woutL,*f1H,*f1L,*f2H,*f2L,*lmH,*lmL;
    __half *nH,*nL,*qkvH,*qkvL,*vTH,*vTL,*pH,*pL,*aoH,*aoL,*xH,*xL,*hH,*hL;
    cudaGetSymbolAddress((void**)&winH,  g_winH);  cudaGetSymbolAddress((void**)&winL,  g_winL);
    cudaGetSymbolAddress((void**)&woutH, g_woutH); cudaGetSymbolAddress((void**)&woutL, g_woutL);
    cudaGetSymbolAddress((void**)&f1H,   g_f1H);   cudaGetSymbolAddress((void**)&f1L,   g_f1L);
    cudaGetSymbolAddress((void**)&f2H,   g_f2H);   cudaGetSymbolAddress((void**)&f2L,   g_f2L);
    cudaGetSymbolAddress((void**)&lmH,   g_lmH);   cudaGetSymbolAddress((void**)&lmL,   g_lmL);
    cudaGetSymbolAddress((void**)&nH,    g_nH);    cudaGetSymbolAddress((void**)&nL,    g_nL);
    cudaGetSymbolAddress((void**)&qkvH,  g_qkvH);  cudaGetSymbolAddress((void**)&qkvL,  g_qkvL);
    cudaGetSymbolAddress((void**)&vTH,   g_vTH);   cudaGetSymbolAddress((void**)&vTL,   g_vTL);
    cudaGetSymbolAddress((void**)&pH,    g_pH);    cudaGetSymbolAddress((void**)&pL,    g_pL);
    cudaGetSymbolAddress((void**)&aoH,   g_aoH);   cudaGetSymbolAddress((void**)&aoL,   g_aoL);
    cudaGetSymbolAddress((void**)&xH,    g_xH);    cudaGetSymbolAddress((void**)&xL,    g_xL);
    cudaGetSymbolAddress((void**)&hH,    g_hH);    cudaGetSymbolAddress((void**)&hL,    g_hL);

    // ---- weight conversions (fp32 -> fp16 hi/lo planes) ----
    cvt2_k<<<cv8blocks((ll)Lq*3*Hq*Hq),  256>>>(aiw, winH,  winL,  (ll)Lq*3*Hq*Hq);
    cvt2_k<<<cv8blocks((ll)Lq*Hq*Hq),    256>>>(aow, woutH, woutL, (ll)Lq*Hq*Hq);
    cvt2_k<<<cv8blocks((ll)Lq*Eq*Iq*Hq), 256>>>(f1w, f1H,   f1L,   (ll)Lq*Eq*Iq*Hq);
    cvt2_k<<<cv8blocks((ll)Lq*Eq*Hq*Iq), 256>>>(f2w, f2H,   f2L,   (ll)Lq*Eq*Hq*Iq);
    cvt2_k<<<cv8blocks((ll)Vq*Hq),       256>>>(lmw, lmH,   lmL,   (ll)Vq*Hq);

    zero_aux_k<<<1,256>>>();
    embed_k<<<(Tq*Hq)/256, 256>>>(ids, emb);

    for (int l = 0; l < Lq; l++) {
        // --- attention ---
        ln_k<<<Tq,256>>>(px, ln1g + (ll)l*Hq, ln1b + (ll)l*Hq, pn, nH, nL);

        // qkv = n1 @ W_in^T + b  -> hi/lo planes
        bgemm<4,0><<<dim3(Tq/128, 3*Hq/128, 1), 256, DSMB>>>(
            Tq, 3*Hq, Hq, nH, nL, Hq,
            winH + (ll)l*3*Hq*Hq, winL + (ll)l*3*Hq*Hq, Hq,
            qkvH, qkvL, 3*Hq, aib + (ll)l*3*Hq, nullptr,
            1.f, 1, 0,0,0,0,0,0, 0,0);

        // V^T planes per (b,h)
        vtrans_k<<<dim3(Sq/32, DHq/32, Bq*NHq), dim3(32,8)>>>(qkvH, qkvL, vTH, vTL);

        // scores = q @ k^T / sqrt(DH)  (HMMA, batched over B*NH)
        bgemm<0,0><<<dim3(Sq/128, Sq/128, Bq*NHq), 256, DSMB>>>(
            Sq, Sq, DHq, qkvH, qkvL, 3*Hq,
            qkvH + Hq, qkvL + Hq, 3*Hq,
            psc, nullptr, Sq, nullptr, nullptr,
            1.f/11.313708498984761f, NHq,
            (ll)Sq*3*Hq, DHq, (ll)Sq*3*Hq, DHq, (ll)NHq*Sq*Sq, (ll)Sq*Sq,
            0, 0);

        softmax_k<<<Bq*NHq*Sq, 256>>>(psc, pH, pL);

        // o = attn @ v  (HMMA, batched) -> ao hi/lo planes
        bgemm<4,0><<<dim3(Sq/128, DHq/128, Bq*NHq), 256, DSMB>>>(
            Sq, DHq, Sq, pH, pL, Sq,
            vTH, vTL, Sq,
            aoH, aoL, Hq, pzb, nullptr,
            1.f, NHq,
            (ll)NHq*Sq*Sq, (ll)Sq*Sq, (ll)NHq*DHq*Sq, (ll)DHq*Sq,
            (ll)Sq*Hq, DHq,
            0, 0);

        // x = x + o @ W_out^T + b
        bgemm<2,0><<<dim3(Tq/128, Hq/128, 1), 256, DSMB>>>(
            Tq, Hq, Hq, aoH, aoL, Hq,
            woutH + (ll)l*Hq*Hq, woutL + (ll)l*Hq*Hq, Hq,
            px, nullptr, Hq, aob + (ll)l*Hq, px,
            1.f, 1, 0,0,0,0,0,0, 0,0);

        // --- MoE ---
        ln_k<<<Tq,256>>>(px, ln2g + (ll)l*Hq, ln2b + (ll)l*Hq, pn, nH, nL);

        zero_cnt_k<<<1,32>>>();
        router_k<<<Tq,256>>>(pn, rw + (ll)l*Eq*Hq, rb + (ll)l*Eq);
        offsets_k<<<1,1>>>();
        build_k<<<Tq/256,256>>>();
        aux_k<<<1,1>>>();

        // fc1: gather, gelu, write hi/lo hidden planes
        bgemm<3,1><<<dim3(Tq/128, Iq/128, Eq), 256, DSMB>>>(
            Tq, Iq, Hq, nH, nL, Hq,
            f1H + (ll)l*Eq*Iq*Hq, f1L + (ll)l*Eq*Iq*Hq, Hq,
            hH, hL, Iq, f1b + (ll)l*Eq*Iq, nullptr,
            1.f, 1, 0,0,0,0,0,0, (ll)Iq*Hq, (ll)Iq);

        // fc2: scatter to per-slot fp32 buffers
        bgemm<1,2><<<dim3(Tq/128, Hq/128, Eq), 256, DSMB>>>(
            Tq, Hq, Iq, hH, hL, Iq,
            f2H + (ll)l*Eq*Hq*Iq, f2L + (ll)l*Eq*Hq*Iq, Iq,
            pmoe, nullptr, Hq, f2b + (ll)l*Eq*Hq, nullptr,
            1.f, 1, 0,0,0,0,0,0, (ll)Hq*Iq, (ll)Hq);

        combine_k<<<(Tq*Hq)/256, 256>>>();
    }

    // lm head
    cvt2_k<<<cv8blocks((ll)Tq*Hq), 256>>>(px, xH, xL, (ll)Tq*Hq);
    bgemm<1,0><<<dim3(Tq/128, Vq/128, 1), 256, DSMB>>>(
        Tq, Vq, Hq, xH, xL, Hq, lmH, lmL, Hq, out, nullptr, Vq,
        lmb, nullptr, 1.f, 1, 0,0,0,0,0,0, 0, 0);

    tail_k<<<1,256>>>(out, (ll)out_size);
}

// round 6
// speedup vs baseline: 2.6627x; 1.0566x over previous
#include <cuda_runtime.h>
#include <cuda_fp16.h>
#include <math.h>
#include <stdint.h>

// ---------------- problem constants ----------------
#define Bq 4
#define Sq 512
#define Hq 1024
#define Iq 4096
#define Eq 8
#define Vq 32000
#define Lq 2
#define NHq 8
#define DHq 128
#define Tq (Bq*Sq)          // 2048 tokens

typedef long long ll;

__device__ __forceinline__ uint32_t smem_u32(const void* p) {
    uint32_t a;
    asm("{ .reg .u64 t; cvta.to.shared.u64 t, %1; cvt.u32.u64 %0, t; }" : "=r"(a) : "l"(p));
    return a;
}

// ---------------- device scratch (static, no allocs) ----------------
__device__ float g_x[Tq*Hq];
__device__ float g_n[Tq*Hq];
__device__ float g_scores[Bq*NHq*Sq*Sq];
__device__ float g_moe[2*Tq*Hq];
__device__ int   g_sel[Tq*2];
__device__ int   g_cnt[Eq];
__device__ int   g_off[Eq];
__device__ int   g_cur[Eq];
__device__ int   g_tokmap[2*Tq];
__device__ int   g_outmap[2*Tq];
__device__ float g_aux[1];
__device__ float g_zb[DHq];      // zero bias
// fp16 hi/lo planes
__device__ __half g_winH[Lq*3*Hq*Hq],  g_winL[Lq*3*Hq*Hq];
__device__ __half g_woutH[Lq*Hq*Hq],   g_woutL[Lq*Hq*Hq];
__device__ __half g_f1H[(size_t)Lq*Eq*Iq*Hq], g_f1L[(size_t)Lq*Eq*Iq*Hq];
__device__ __half g_f2H[(size_t)Lq*Eq*Hq*Iq], g_f2L[(size_t)Lq*Eq*Hq*Iq];
__device__ __half g_lmH[(size_t)Vq*Hq], g_lmL[(size_t)Vq*Hq];
__device__ __half g_nH[Tq*Hq],  g_nL[Tq*Hq];
__device__ __half g_qkvH[Tq*3*Hq], g_qkvL[Tq*3*Hq];
__device__ __half g_vTH[Tq*Hq], g_vTL[Tq*Hq];
__device__ __half g_pH[(size_t)Bq*NHq*Sq*Sq], g_pL[(size_t)Bq*NHq*Sq*Sq];
__device__ __half g_aoH[Tq*Hq], g_aoL[Tq*Hq];
__device__ __half g_xH[Tq*Hq],  g_xL[Tq*Hq];
__device__ __half g_hH[(size_t)2*Tq*Iq], g_hL[(size_t)2*Tq*Iq];

// ---------------- split conversion: fp32 -> (hi, lo) fp16 planes ----------------
__global__ void cvt2_k(const float* __restrict__ src, __half* __restrict__ hi,
                       __half* __restrict__ lo, ll total) {
    ll i = ((ll)blockIdx.x * 256 + threadIdx.x) * 8;
    if (i >= total) return;
    float4 a = *(const float4*)(src + i);
    float4 b = *(const float4*)(src + i + 4);
    float v[8] = {a.x, a.y, a.z, a.w, b.x, b.y, b.z, b.w};
    __align__(16) __half h[8];
    __align__(16) __half l[8];
    #pragma unroll
    for (int j = 0; j < 8; j++) {
        h[j] = __float2half(v[j]);
        l[j] = __float2half(v[j] - __half2float(h[j]));
    }
    *(uint4*)(hi + i) = *(const uint4*)h;
    *(uint4*)(lo + i) = *(const uint4*)l;
}

// ---------------- HMMA fp16 split GEMM ----------------
// C[M,N] = (Ah+Al)[M,K] x (Bh+Bl)[N,K]^T  via 3 terms: Ah*Bh + Al*Bh + Ah*Bl
// CTA tile 128xTN (TN=128 or 256), BK=32, cp.async pipeline, 8 warps (2x4),
// warp tile 64x(TN/4).
// EPI: 0=alpha (f32 out), 1=bias(f32), 2=bias+res(f32), 3=bias+gelu->planes,
//      4=bias->planes.
// MOE: 0 dense/batched, 1 gather-A/compact-C, 2 compact-A/scatter-C.
#define DSMB128 (4*40960)       // 4 stages x (20480 + 128*160)
#define DSMB256 (3*61440)       // 3 stages x (20480 + 256*160)

__device__ __forceinline__ void ldmx4(uint32_t* r, uint32_t addr) {
    asm volatile("ldmatrix.sync.aligned.m8n8.x4.shared.b16 {%0,%1,%2,%3}, [%4];"
        : "=r"(r[0]), "=r"(r[1]), "=r"(r[2]), "=r"(r[3]) : "r"(addr));
}
__device__ __forceinline__ void mma16816(float* c, const uint32_t* a, uint32_t b0, uint32_t b1) {
    asm volatile("mma.sync.aligned.m16n8k16.row.col.f32.f16.f16.f32 "
        "{%0,%1,%2,%3}, {%4,%5,%6,%7}, {%8,%9}, {%0,%1,%2,%3};"
        : "+f"(c[0]), "+f"(c[1]), "+f"(c[2]), "+f"(c[3])
        : "r"(a[0]), "r"(a[1]), "r"(a[2]), "r"(a[3]), "r"(b0), "r"(b1));
}
__device__ __forceinline__ void cpasync16(uint32_t dst, const void* src) {
    asm volatile("cp.async.cg.shared.global [%0], [%1], 16;" :: "r"(dst), "l"(src));
}
__device__ __forceinline__ void cpasync16z(uint32_t dst, const void* src, uint32_t sz) {
    asm volatile("cp.async.cg.shared.global [%0], [%1], 16, %2;" :: "r"(dst), "l"(src), "r"(sz));
}

template<int EPI, int MOE, int TN>
__global__ __launch_bounds__(256, 1)
void bgemm(int M, int N, int K,
           const __half* __restrict__ Ah, const __half* __restrict__ Al, int lda,
           const __half* __restrict__ Bh, const __half* __restrict__ Bl, int ldb,
           void* __restrict__ Cv, __half* __restrict__ Clo, int ldc,
           const float* __restrict__ bias,
           const float* __restrict__ res,
           float alpha, int zdiv,
           ll sA1, ll sA2, ll sB1, ll sB2, ll sC1, ll sC2,
           ll sBz, ll sBiasZ)
{
    constexpr int WN     = TN / 4;       // warp n extent: 32 or 64
    constexpr int NF     = WN / 8;       // n8 frags per warp: 4 or 8
    constexpr int NB16   = WN / 16;      // B ldmx4 per plane per k16: 2 or 4
    constexpr int STAGES = (TN == 256) ? 3 : 4;
    constexpr uint32_t STB = 20480u + (uint32_t)TN * 160u;  // stage bytes
    constexpr uint32_t BHOFF = 20480u;
    constexpr uint32_t BLOFF = 20480u + (uint32_t)TN * 80u;

    int Me = M, rowbase = 0;
    ll coff = 0;
    if (MOE) {
        int z = blockIdx.z;
        Me = g_cnt[z]; rowbase = g_off[z];
        Bh += (ll)z * sBz; Bl += (ll)z * sBz;
        bias += (ll)z * sBiasZ;
    } else {
        int z = blockIdx.z;
        int zb = z / zdiv, zh = z - zb * zdiv;
        Ah += zb*sA1 + zh*sA2; Al += zb*sA1 + zh*sA2;
        Bh += zb*sB1 + zh*sB2; Bl += zb*sB1 + zh*sB2;
        coff = zb*sC1 + zh*sC2;
    }
    int m0 = blockIdx.x * 128;
    if (m0 >= Me) return;
    int n0 = blockIdx.y * TN;

    __shared__ int s_row[128];
    __shared__ int s_cout[128];
    extern __shared__ __align__(16) char dsm[];
    uint32_t dbase = smem_u32(dsm);

    int tid = threadIdx.x, lane = tid & 31, wid = tid >> 5;
    int wm = wid >> 2, wn = wid & 3;   // 2 x 4 warp grid

    if (tid < 128) {
        int grow = m0 + tid;
        int rid = -1, cid = -1;
        if (grow < Me) {
            if      (MOE == 1) { rid = g_tokmap[rowbase + grow]; cid = rowbase + grow; }
            else if (MOE == 2) { rid = rowbase + grow;           cid = g_outmap[rowbase + grow]; }
            else               { rid = grow;                     cid = grow; }
        }
        s_row[tid] = rid; s_cout[tid] = cid;
    }
    __syncthreads();

    float acc[4][NF][4];
    #pragma unroll
    for (int a = 0; a < 4; a++)
        #pragma unroll
        for (int b = 0; b < NF; b++)
            #pragma unroll
            for (int c = 0; c < 4; c++) acc[a][b][c] = 0.f;

    int S = K / 32;

    auto load_stage = [&](int s) {
        int c0 = s * 32;
        uint32_t base = dbase + (uint32_t)(s % STAGES) * STB;
        constexpr int CH_A = 512;        // 16B chunks per A plane
        constexpr int CH_B = TN * 4;     // per B plane
        constexpr int ITER = (2*CH_A + 2*CH_B) / 256;
        #pragma unroll
        for (int j = 0; j < ITER; j++) {
            int idx = tid + j * 256;
            if (idx < CH_A) {
                int row = idx >> 2, c = idx & 3;
                int r = s_row[row];
                ll aoff = (r >= 0) ? ((ll)r * lda + c0 + c * 8) : 0;
                cpasync16z(base + (uint32_t)(row*80 + c*16), Ah + aoff, (r>=0)?16u:0u);
            } else if (idx < 2*CH_A) {
                int k2 = idx - CH_A;
                int row = k2 >> 2, c = k2 & 3;
                int r = s_row[row];
                ll aoff = (r >= 0) ? ((ll)r * lda + c0 + c * 8) : 0;
                cpasync16z(base + 10240u + (uint32_t)(row*80 + c*16), Al + aoff, (r>=0)?16u:0u);
            } else if (idx < 2*CH_A + CH_B) {
                int k2 = idx - 2*CH_A;
                int row = k2 >> 2, c = k2 & 3;
                cpasync16(base + BHOFF + (uint32_t)(row*80 + c*16),
                          Bh + (ll)(n0 + row) * ldb + c0 + c * 8);
            } else {
                int k2 = idx - 2*CH_A - CH_B;
                int row = k2 >> 2, c = k2 & 3;
                cpasync16(base + BLOFF + (uint32_t)(row*80 + c*16),
                          Bl + (ll)(n0 + row) * ldb + c0 + c * 8);
            }
        }
        asm volatile("cp.async.commit_group;" ::: "memory");
    };

    #pragma unroll
    for (int i = 0; i < STAGES - 1; i++) load_stage(i);

    for (int s = 0; s < S; s++) {
        if (S - s - 1 >= STAGES - 2) {
            asm volatile("cp.async.wait_group %0;" :: "n"(STAGES - 2) : "memory");
        } else {
            asm volatile("cp.async.wait_group 0;" ::: "memory");
        }
        __syncthreads();
        if (s + STAGES - 1 < S) load_stage(s + STAGES - 1);

        uint32_t base = dbase + (uint32_t)(s % STAGES) * STB;
        uint32_t Ahb = base, Alb = base + 10240u, Bhb = base + BHOFF, Blb = base + BLOFF;

        #pragma unroll
        for (int kk = 0; kk < 2; kk++) {
            uint32_t ah[4][4], al[4][4];
            #pragma unroll
            for (int mf = 0; mf < 4; mf++) {
                uint32_t roff = (uint32_t)(((wm*64 + mf*16 + (lane & 15)) * 40
                                            + kk*16 + (lane >> 4) * 8) * 2);
                ldmx4(ah[mf], Ahb + roff);
                ldmx4(al[mf], Alb + roff);
            }
            int g = lane >> 3;
            #pragma unroll
            for (int bt = 0; bt < NB16; bt++) {
                uint32_t bhf[4], blf[4];
                uint32_t roff = (uint32_t)(((wn*WN + bt*16 + (g >> 1)*8 + (lane & 7)) * 40
                                            + kk*16 + (g & 1) * 8) * 2);
                ldmx4(bhf, Bhb + roff);
                ldmx4(blf, Blb + roff);
                #pragma unroll
                for (int sub = 0; sub < 2; sub++) {
                    int nf = bt*2 + sub;
                    #pragma unroll
                    for (int mf = 0; mf < 4; mf++) {
                        mma16816(acc[mf][nf], ah[mf], bhf[sub*2], bhf[sub*2+1]);
                        mma16816(acc[mf][nf], al[mf], bhf[sub*2], bhf[sub*2+1]);
                        mma16816(acc[mf][nf], ah[mf], blf[sub*2], blf[sub*2+1]);
                    }
                }
            }
        }
    }

    // ---------------- epilogue (register-direct) ----------------
    #pragma unroll
    for (int mf = 0; mf < 4; mf++) {
        int rbase = wm*64 + mf*16 + (lane >> 2);
        #pragma unroll
        for (int half = 0; half < 2; half++) {
            int rloc = rbase + half * 8;
            int cr = s_cout[rloc];
            if (cr < 0) continue;
            #pragma unroll
            for (int nf = 0; nf < NF; nf++) {
                int col = n0 + wn*WN + nf*8 + (lane & 3)*2;
                float v0 = acc[mf][nf][half*2 + 0] * alpha;
                float v1 = acc[mf][nf][half*2 + 1] * alpha;
                if (EPI >= 1) {
                    float2 bv = *(const float2*)&bias[col];
                    v0 += bv.x; v1 += bv.y;
                }
                if (EPI == 2) {
                    float2 rv = *(const float2*)(res + (ll)cr*ldc + col);
                    v0 += rv.x; v1 += rv.y;
                }
                if (EPI == 3 || EPI == 4) {
                    if (EPI == 3) {
                        v0 = 0.5f*v0*(1.f + erff(v0*0.70710678118654752f));
                        v1 = 0.5f*v1*(1.f + erff(v1*0.70710678118654752f));
                    }
                    __half h0 = __float2half(v0);
                    __half l0 = __float2half(v0 - __half2float(h0));
                    __half h1 = __float2half(v1);
                    __half l1 = __float2half(v1 - __half2float(h1));
                    __half* DH = (__half*)Cv + coff + (ll)cr * ldc + col;
                    __half* DL = Clo + coff + (ll)cr * ldc + col;
                    *(__half2*)DH = __halves2half2(h0, h1);
                    *(__half2*)DL = __halves2half2(l0, l1);
                } else {
                    *(float2*)((float*)Cv + coff + (ll)cr*ldc + col) = make_float2(v0, v1);
                }
            }
        }
    }
}

// ---------------- V transpose: qkv planes -> per-(b,h) V^T planes ----------------
__global__ void vtrans_k(const __half* __restrict__ qH, const __half* __restrict__ qL,
                         __half* __restrict__ vTH, __half* __restrict__ vTL) {
    int z = blockIdx.z; int b = z >> 3; int h = z & 7;
    int d0 = blockIdx.y * 32;
    int s0 = blockIdx.x * 32;
    __shared__ __half tH[32][33], tL[32][33];
    int tx = threadIdx.x, ty = threadIdx.y;   // 32 x 8
    #pragma unroll
    for (int i = 0; i < 4; i++) {
        int sl = ty*4 + i;
        ll src = (ll)(b*Sq + s0 + sl)*(3*Hq) + 2*Hq + h*DHq + d0 + tx;
        tH[sl][tx] = qH[src];
        tL[sl][tx] = qL[src];
    }
    __syncthreads();
    #pragma unroll
    for (int i = 0; i < 4; i++) {
        int dl = ty*4 + i;
        ll dst = ((ll)z*DHq + d0 + dl)*Sq + s0 + tx;
        vTH[dst] = tH[tx][dl];
        vTL[dst] = tL[tx][dl];
    }
}

// ---------------- small kernels ----------------
__global__ void embed_k(const int* __restrict__ ids, const float* __restrict__ emb) {
    int idx = blockIdx.x*256 + threadIdx.x;
    int t = idx / Hq, h = idx - t*Hq;
    g_x[idx] = emb[(ll)ids[t]*Hq + h];
}

__global__ void ln_k(const float* __restrict__ x, const float* __restrict__ g,
                     const float* __restrict__ b, float* __restrict__ o,
                     __half* __restrict__ oH, __half* __restrict__ oL) {
    int t = blockIdx.x;
    const float* xr = x + (ll)t*Hq;
    int tid = threadIdx.x;
    float v[4]; float s = 0.f;
    #pragma unroll
    for (int i = 0; i < 4; i++) { v[i] = xr[tid + 256*i]; s += v[i]; }
    __shared__ float red[256];
    red[tid] = s; __syncthreads();
    for (int o2 = 128; o2; o2 >>= 1) { if (tid < o2) red[tid] += red[tid+o2]; __syncthreads(); }
    float mu = red[0] * (1.f/Hq);
    __syncthreads();
    s = 0.f;
    #pragma unroll
    for (int i = 0; i < 4; i++) { float d = v[i]-mu; s += d*d; }
    red[tid] = s; __syncthreads();
    for (int o2 = 128; o2; o2 >>= 1) { if (tid < o2) red[tid] += red[tid+o2]; __syncthreads(); }
    float inv = rsqrtf(red[0]*(1.f/Hq) + 1e-5f);
    float* orow = o + (ll)t*Hq;
    __half* hr = oH + (ll)t*Hq;
    __half* lr = oL + (ll)t*Hq;
    #pragma unroll
    for (int i = 0; i < 4; i++) {
        int h = tid + 256*i;
        float y = (v[i]-mu)*inv*g[h] + b[h];
        orow[h] = y;
        __half hi = __float2half(y);
        hr[h] = hi;
        lr[h] = __float2half(y - __half2float(hi));
    }
}

__global__ void softmax_k(const float* __restrict__ sc,
                          __half* __restrict__ pH, __half* __restrict__ pL) {
    ll row = blockIdx.x;
    const float* r = sc + row*Sq;
    int tid = threadIdx.x;
    float a = r[tid], b = r[tid+256];
    __shared__ float red[256];
    red[tid] = fmaxf(a,b); __syncthreads();
    for (int o = 128; o; o >>= 1) { if (tid < o) red[tid] = fmaxf(red[tid], red[tid+o]); __syncthreads(); }
    float m = red[0]; __syncthreads();
    a = expf(a-m); b = expf(b-m);
    red[tid] = a+b; __syncthreads();
    for (int o = 128; o; o >>= 1) { if (tid < o) red[tid] += red[tid+o]; __syncthreads(); }
    float inv = 1.f/red[0];
    a *= inv; b *= inv;
    __half ha = __float2half(a), hb = __float2half(b);
    pH[row*Sq + tid]       = ha;
    pL[row*Sq + tid]       = __float2half(a - __half2float(ha));
    pH[row*Sq + tid + 256] = hb;
    pL[row*Sq + tid + 256] = __float2half(b - __half2float(hb));
}

__global__ void zero_cnt_k() { if (threadIdx.x < Eq) g_cnt[threadIdx.x] = 0; }
__global__ void zero_aux_k() {
    if (threadIdx.x == 0) g_aux[0] = 0.f;
    if (threadIdx.x < DHq) g_zb[threadIdx.x] = 0.f;
}

__global__ void router_k(const float* __restrict__ n2, const float* __restrict__ rw,
                         const float* __restrict__ rb) {
    int t = blockIdx.x;
    int w = threadIdx.x >> 5, lane = threadIdx.x & 31;
    const float* xr = n2 + (ll)t*Hq;
    const float* wr = rw + (ll)w*Hq;
    float s = 0.f;
    for (int h = lane; h < Hq; h += 32) s += xr[h]*wr[h];
    #pragma unroll
    for (int o = 16; o; o >>= 1) s += __shfl_xor_sync(0xffffffffu, s, o);
    __shared__ float lg[Eq];
    if (lane == 0) lg[w] = s + rb[w];
    __syncthreads();
    if (threadIdx.x == 0) {
        int b0 = 0; float v0 = lg[0];
        for (int e = 1; e < Eq; e++) if (lg[e] > v0) { v0 = lg[e]; b0 = e; }
        int b1 = -1; float v1 = -3.4e38f;
        for (int e = 0; e < Eq; e++) { if (e == b0) continue; if (lg[e] > v1) { v1 = lg[e]; b1 = e; } }
        g_sel[2*t]   = b0;
        g_sel[2*t+1] = b1;
        atomicAdd(&g_cnt[b0], 1);
        atomicAdd(&g_cnt[b1], 1);
    }
}

__global__ void offsets_k() {
    int s = 0;
    for (int e = 0; e < Eq; e++) { g_off[e] = s; g_cur[e] = s; s += g_cnt[e]; }
}

__global__ void build_k() {
    int t = blockIdx.x*256 + threadIdx.x;
    if (t >= Tq) return;
    #pragma unroll
    for (int slot = 0; slot < 2; slot++) {
        int e = g_sel[2*t + slot];
        int p = atomicAdd(&g_cur[e], 1);
        g_tokmap[p] = t;
        g_outmap[p] = slot*Tq + t;
    }
}

__global__ void aux_k() {
    float s = 0.f;
    const float target = (float)Tq / (float)Eq;
    for (int e = 0; e < Eq; e++) { float d = (float)g_cnt[e] - target; s += d*d; }
    g_aux[0] += 0.01f * s / (float)Eq;
}

__global__ void combine_k() {
    int idx = blockIdx.x*256 + threadIdx.x;
    g_x[idx] += g_moe[idx] + g_moe[(ll)Tq*Hq + idx];
}

__global__ void tail_k(float* __restrict__ out, ll out_size) {
    ll base = (ll)Tq * Vq;
    for (ll i = base + threadIdx.x; i < out_size; i += 256)
        out[i] = g_aux[0];
}

// ---------------- launch ----------------
static inline int cv8blocks(ll total) { return (int)((total/8 + 255) / 256); }

extern "C" void kernel_launch(void* const* d_in, const int* in_sizes, int n_in,
                              void* d_out, int out_size) {
    const int*   ids  = (const int*)  d_in[0];
    const float* emb  = (const float*)d_in[1];
    const float* ln1g = (const float*)d_in[2];
    const float* ln1b = (const float*)d_in[3];
    const float* aiw  = (const float*)d_in[4];
    const float* aib  = (const float*)d_in[5];
    const float* aow  = (const float*)d_in[6];
    const float* aob  = (const float*)d_in[7];
    const float* ln2g = (const float*)d_in[8];
    const float* ln2b = (const float*)d_in[9];
    const float* rw   = (const float*)d_in[10];
    const float* rb   = (const float*)d_in[11];
    const float* f1w  = (const float*)d_in[12];
    const float* f1b  = (const float*)d_in[13];
    const float* f2w  = (const float*)d_in[14];
    const float* f2b  = (const float*)d_in[15];
    const float* lmw  = (const float*)d_in[16];
    const float* lmb  = (const float*)d_in[17];
    float* out = (float*)d_out;

    cudaFuncSetAttribute(bgemm<4,0,256>, cudaFuncAttributeMaxDynamicSharedMemorySize, DSMB256);
    cudaFuncSetAttribute(bgemm<0,0,256>, cudaFuncAttributeMaxDynamicSharedMemorySize, DSMB256);
    cudaFuncSetAttribute(bgemm<1,0,256>, cudaFuncAttributeMaxDynamicSharedMemorySize, DSMB256);
    cudaFuncSetAttribute(bgemm<3,1,256>, cudaFuncAttributeMaxDynamicSharedMemorySize, DSMB256);
    cudaFuncSetAttribute(bgemm<1,2,256>, cudaFuncAttributeMaxDynamicSharedMemorySize, DSMB256);
    cudaFuncSetAttribute(bgemm<4,0,128>, cudaFuncAttributeMaxDynamicSharedMemorySize, DSMB128);
    cudaFuncSetAttribute(bgemm<2,0,128>, cudaFuncAttributeMaxDynamicSharedMemorySize, DSMB128);

    float *px, *pn, *psc, *pmoe;
    cudaGetSymbolAddress((void**)&px,   g_x);
    cudaGetSymbolAddress((void**)&pn,   g_n);
    cudaGetSymbolAddress((void**)&psc,  g_scores);
    cudaGetSymbolAddress((void**)&pmoe, g_moe);
    float* pzb; cudaGetSymbolAddress((void**)&pzb, g_zb);
    __half *winH,*winL,*woutH,*woutL,*f1H,*f1L,*f2H,*f2L,*lmH,*lmL;
    __half *nH,*nL,*qkvH,*qkvL,*vTH,*vTL,*pH,*pL,*aoH,*aoL,*xH,*xL,*hH,*hL;
    cudaGetSymbolAddress((void**)&winH,  g_winH);  cudaGetSymbolAddress((void**)&winL,  g_winL);
    cudaGetSymbolAddress((void**)&woutH, g_woutH); cudaGetSymbolAddress((void**)&woutL, g_woutL);
    cudaGetSymbolAddress((void**)&f1H,   g_f1H);   cudaGetSymbolAddress((void**)&f1L,   g_f1L);
    cudaGetSymbolAddress((void**)&f2H,   g_f2H);   cudaGetSymbolAddress((void**)&f2L,   g_f2L);
    cudaGetSymbolAddress((void**)&lmH,   g_lmH);   cudaGetSymbolAddress((void**)&lmL,   g_lmL);
    cudaGetSymbolAddress((void**)&nH,    g_nH);    cudaGetSymbolAddress((void**)&nL,    g_nL);
    cudaGetSymbolAddress((void**)&qkvH,  g_qkvH);  cudaGetSymbolAddress((void**)&qkvL,  g_qkvL);
    cudaGetSymbolAddress((void**)&vTH,   g_vTH);   cudaGetSymbolAddress((void**)&vTL,   g_vTL);
    cudaGetSymbolAddress((void**)&pH,    g_pH);    cudaGetSymbolAddress((void**)&pL,    g_pL);
    cudaGetSymbolAddress((void**)&aoH,   g_aoH);   cudaGetSymbolAddress((void**)&aoL,   g_aoL);
    cudaGetSymbolAddress((void**)&xH,    g_xH);    cudaGetSymbolAddress((void**)&xL,    g_xL);
    cudaGetSymbolAddress((void**)&hH,    g_hH);    cudaGetSymbolAddress((void**)&hL,    g_hL);

    // ---- weight conversions (fp32 -> fp16 hi/lo planes) ----
    cvt2_k<<<cv8blocks((ll)Lq*3*Hq*Hq),  256>>>(aiw, winH,  winL,  (ll)Lq*3*Hq*Hq);
    cvt2_k<<<cv8blocks((ll)Lq*Hq*Hq),    256>>>(aow, woutH, woutL, (ll)Lq*Hq*Hq);
    cvt2_k<<<cv8blocks((ll)Lq*Eq*Iq*Hq), 256>>>(f1w, f1H,   f1L,   (ll)Lq*Eq*Iq*Hq);
    cvt2_k<<<cv8blocks((ll)Lq*Eq*Hq*Iq), 256>>>(f2w, f2H,   f2L,   (ll)Lq*Eq*Hq*Iq);
    cvt2_k<<<cv8blocks((ll)Vq*Hq),       256>>>(lmw, lmH,   lmL,   (ll)Vq*Hq);

    zero_aux_k<<<1,256>>>();
    embed_k<<<(Tq*Hq)/256, 256>>>(ids, emb);

    for (int l = 0; l < Lq; l++) {
        // --- attention ---
        ln_k<<<Tq,256>>>(px, ln1g + (ll)l*Hq, ln1b + (ll)l*Hq, pn, nH, nL);

        // qkv = n1 @ W_in^T + b  -> hi/lo planes
        bgemm<4,0,256><<<dim3(Tq/128, 3*Hq/256, 1), 256, DSMB256>>>(
            Tq, 3*Hq, Hq, nH, nL, Hq,
            winH + (ll)l*3*Hq*Hq, winL + (ll)l*3*Hq*Hq, Hq,
            qkvH, qkvL, 3*Hq, aib + (ll)l*3*Hq, nullptr,
            1.f, 1, 0,0,0,0,0,0, 0,0);

        // V^T planes per (b,h)
        vtrans_k<<<dim3(Sq/32, DHq/32, Bq*NHq), dim3(32,8)>>>(qkvH, qkvL, vTH, vTL);

        // scores = q @ k^T / sqrt(DH)  (HMMA, batched over B*NH)
        bgemm<0,0,256><<<dim3(Sq/128, Sq/256, Bq*NHq), 256, DSMB256>>>(
            Sq, Sq, DHq, qkvH, qkvL, 3*Hq,
            qkvH + Hq, qkvL + Hq, 3*Hq,
            psc, nullptr, Sq, nullptr, nullptr,
            1.f/11.313708498984761f, NHq,
            (ll)Sq*3*Hq, DHq, (ll)Sq*3*Hq, DHq, (ll)NHq*Sq*Sq, (ll)Sq*Sq,
            0, 0);

        softmax_k<<<Bq*NHq*Sq, 256>>>(psc, pH, pL);

        // o = attn @ v  (HMMA, batched, N=128) -> ao hi/lo planes
        bgemm<4,0,128><<<dim3(Sq/128, DHq/128, Bq*NHq), 256, DSMB128>>>(
            Sq, DHq, Sq, pH, pL, Sq,
            vTH, vTL, Sq,
            aoH, aoL, Hq, pzb, nullptr,
            1.f, NHq,
            (ll)NHq*Sq*Sq, (ll)Sq*Sq, (ll)NHq*DHq*Sq, (ll)DHq*Sq,
            (ll)Sq*Hq, DHq,
            0, 0);

        // x = x + o @ W_out^T + b  (N=1024, keep 128-wide tiles for occupancy)
        bgemm<2,0,128><<<dim3(Tq/128, Hq/128, 1), 256, DSMB128>>>(
            Tq, Hq, Hq, aoH, aoL, Hq,
            woutH + (ll)l*Hq*Hq, woutL + (ll)l*Hq*Hq, Hq,
            px, nullptr, Hq, aob + (ll)l*Hq, px,
            1.f, 1, 0,0,0,0,0,0, 0,0);

        // --- MoE ---
        ln_k<<<Tq,256>>>(px, ln2g + (ll)l*Hq, ln2b + (ll)l*Hq, pn, nH, nL);

        zero_cnt_k<<<1,32>>>();
        router_k<<<Tq,256>>>(pn, rw + (ll)l*Eq*Hq, rb + (ll)l*Eq);
        offsets_k<<<1,1>>>();
        build_k<<<Tq/256,256>>>();
        aux_k<<<1,1>>>();

        // fc1: gather, gelu, write hi/lo hidden planes
        bgemm<3,1,256><<<dim3(Tq/128, Iq/256, Eq), 256, DSMB256>>>(
            Tq, Iq, Hq, nH, nL, Hq,
            f1H + (ll)l*Eq*Iq*Hq, f1L + (ll)l*Eq*Iq*Hq, Hq,
            hH, hL, Iq, f1b + (ll)l*Eq*Iq, nullptr,
            1.f, 1, 0,0,0,0,0,0, (ll)Iq*Hq, (ll)Iq);

        // fc2: scatter to per-slot fp32 buffers
        bgemm<1,2,256><<<dim3(Tq/128, Hq/256, Eq), 256, DSMB256>>>(
            Tq, Hq, Iq, hH, hL, Iq,
            f2H + (ll)l*Eq*Hq*Iq, f2L + (ll)l*Eq*Hq*Iq, Iq,
            pmoe, nullptr, Hq, f2b + (ll)l*Eq*Hq, nullptr,
            1.f, 1, 0,0,0,0,0,0, (ll)Hq*Iq, (ll)Hq);

        combine_k<<<(Tq*Hq)/256, 256>>>();
    }

    // lm head
    cvt2_k<<<cv8blocks((ll)Tq*Hq), 256>>>(px, xH, xL, (ll)Tq*Hq);
    bgemm<1,0,256><<<dim3(Tq/128, Vq/256, 1), 256, DSMB256>>>(
        Tq, Vq, Hq, xH, xL, Hq, lmH, lmL, Hq, out, nullptr, Vq,
        lmb, nullptr, 1.f, 1, 0,0,0,0,0,0, 0, 0);

    tail_k<<<1,256>>>(out, (ll)out_size);
}

// round 7
// speedup vs baseline: 3.4581x; 1.2987x over previous
#include <cuda_runtime.h>
#include <cuda_fp16.h>
#include <math.h>
#include <stdint.h>

// ---------------- problem constants ----------------
#define Bq 4
#define Sq 512
#define Hq 1024
#define Iq 4096
#define Eq 8
#define Vq 32000
#define Lq 2
#define NHq 8
#define DHq 128
#define Tq (Bq*Sq)          // 2048 tokens

typedef long long ll;

__device__ __forceinline__ uint32_t smem_u32(const void* p) {
    uint32_t a;
    asm("{ .reg .u64 t; cvta.to.shared.u64 t, %1; cvt.u32.u64 %0, t; }" : "=r"(a) : "l"(p));
    return a;
}

// ---------------- device scratch (static, no allocs) ----------------
__device__ float g_x[Tq*Hq];
__device__ float g_n[Tq*Hq];
__device__ float g_scores[Bq*NHq*Sq*Sq];
__device__ float g_moe[2*Tq*Hq];
__device__ int   g_sel[Tq*2];
__device__ int   g_cnt[Eq];
__device__ int   g_off[Eq];
__device__ int   g_cur[Eq];
__device__ int   g_tokmap[2*Tq];
__device__ int   g_outmap[2*Tq];
__device__ float g_aux[1];
__device__ float g_zb[DHq];      // zero bias
// fp16 planes (hi/lo for activations + attn weights; hi-only for fc/lm weights)
__device__ __half g_winH[Lq*3*Hq*Hq],  g_winL[Lq*3*Hq*Hq];
__device__ __half g_woutH[Lq*Hq*Hq],   g_woutL[Lq*Hq*Hq];
__device__ __half g_f1H[(size_t)Lq*Eq*Iq*Hq];
__device__ __half g_f2H[(size_t)Lq*Eq*Hq*Iq];
__device__ __half g_lmH[(size_t)Vq*Hq];
__device__ __half g_nH[Tq*Hq],  g_nL[Tq*Hq];
__device__ __half g_qkvH[Tq*3*Hq], g_qkvL[Tq*3*Hq];
__device__ __half g_vTH[Tq*Hq], g_vTL[Tq*Hq];
__device__ __half g_pH[(size_t)Bq*NHq*Sq*Sq], g_pL[(size_t)Bq*NHq*Sq*Sq];
__device__ __half g_aoH[Tq*Hq], g_aoL[Tq*Hq];
__device__ __half g_xH[Tq*Hq],  g_xL[Tq*Hq];
__device__ __half g_hH[(size_t)2*Tq*Iq], g_hL[(size_t)2*Tq*Iq];

// ---------------- split conversions ----------------
__global__ void cvt2_k(const float* __restrict__ src, __half* __restrict__ hi,
                       __half* __restrict__ lo, ll total) {
    ll i = ((ll)blockIdx.x * 256 + threadIdx.x) * 8;
    if (i >= total) return;
    float4 a = *(const float4*)(src + i);
    float4 b = *(const float4*)(src + i + 4);
    float v[8] = {a.x, a.y, a.z, a.w, b.x, b.y, b.z, b.w};
    __align__(16) __half h[8];
    __align__(16) __half l[8];
    #pragma unroll
    for (int j = 0; j < 8; j++) {
        h[j] = __float2half(v[j]);
        l[j] = __float2half(v[j] - __half2float(h[j]));
    }
    *(uint4*)(hi + i) = *(const uint4*)h;
    *(uint4*)(lo + i) = *(const uint4*)l;
}
__global__ void cvt1_k(const float* __restrict__ src, __half* __restrict__ hi, ll total) {
    ll i = ((ll)blockIdx.x * 256 + threadIdx.x) * 8;
    if (i >= total) return;
    float4 a = *(const float4*)(src + i);
    float4 b = *(const float4*)(src + i + 4);
    float v[8] = {a.x, a.y, a.z, a.w, b.x, b.y, b.z, b.w};
    __align__(16) __half h[8];
    #pragma unroll
    for (int j = 0; j < 8; j++) h[j] = __float2half(v[j]);
    *(uint4*)(hi + i) = *(const uint4*)h;
}

// ---------------- HMMA fp16 split GEMM ----------------
// TERMS=3: C = Ah*Bh + Al*Bh + Ah*Bl (full split)
// TERMS=2: C = (Ah+Al)*Bh            (weight-lo dropped; Bl unused)
// CTA tile 128xTN, BK=32, cp.async pipeline, 8 warps (2x4), warp 64x(TN/4).
// EPI: 0=alpha(f32), 1=bias(f32), 2=bias+res(f32), 3=bias+gelu->planes, 4=bias->planes.
// MOE: 0 dense/batched, 1 gather-A/compact-C, 2 compact-A/scatter-C.
#define DS_TN256_T3 184320   // 3 stages x 61440
#define DS_TN128_T3 163840   // 4 stages x 40960
#define DS_TN256_T2 163840   // 4 stages x 40960

__device__ __forceinline__ void ldmx4(uint32_t* r, uint32_t addr) {
    asm volatile("ldmatrix.sync.aligned.m8n8.x4.shared.b16 {%0,%1,%2,%3}, [%4];"
        : "=r"(r[0]), "=r"(r[1]), "=r"(r[2]), "=r"(r[3]) : "r"(addr));
}
__device__ __forceinline__ void mma16816(float* c, const uint32_t* a, uint32_t b0, uint32_t b1) {
    asm volatile("mma.sync.aligned.m16n8k16.row.col.f32.f16.f16.f32 "
        "{%0,%1,%2,%3}, {%4,%5,%6,%7}, {%8,%9}, {%0,%1,%2,%3};"
        : "+f"(c[0]), "+f"(c[1]), "+f"(c[2]), "+f"(c[3])
        : "r"(a[0]), "r"(a[1]), "r"(a[2]), "r"(a[3]), "r"(b0), "r"(b1));
}
__device__ __forceinline__ void cpasync16(uint32_t dst, const void* src) {
    asm volatile("cp.async.cg.shared.global [%0], [%1], 16;" :: "r"(dst), "l"(src));
}
__device__ __forceinline__ void cpasync16z(uint32_t dst, const void* src, uint32_t sz) {
    asm volatile("cp.async.cg.shared.global [%0], [%1], 16, %2;" :: "r"(dst), "l"(src), "r"(sz));
}

template<int EPI, int MOE, int TN, int TERMS>
__global__ __launch_bounds__(256, 1)
void bgemm(int M, int N, int K,
           const __half* __restrict__ Ah, const __half* __restrict__ Al, int lda,
           const __half* __restrict__ Bh, const __half* __restrict__ Bl, int ldb,
           void* __restrict__ Cv, __half* __restrict__ Clo, int ldc,
           const float* __restrict__ bias,
           const float* __restrict__ res,
           float alpha, int zdiv,
           ll sA1, ll sA2, ll sB1, ll sB2, ll sC1, ll sC2,
           ll sBz, ll sBiasZ)
{
    constexpr int WN     = TN / 4;
    constexpr int NF     = WN / 8;
    constexpr int NB16   = WN / 16;
    constexpr int STAGES = (TERMS == 3 && TN == 256) ? 3 : 4;
    constexpr uint32_t STB = 20480u + (uint32_t)TN * 80u * (TERMS - 1);
    constexpr uint32_t BHOFF = 20480u;
    constexpr uint32_t BLOFF = 20480u + (uint32_t)TN * 80u;

    int Me = M, rowbase = 0;
    ll coff = 0;
    if (MOE) {
        int z = blockIdx.z;
        Me = g_cnt[z]; rowbase = g_off[z];
        Bh += (ll)z * sBz; if (TERMS == 3) Bl += (ll)z * sBz;
        bias += (ll)z * sBiasZ;
    } else {
        int z = blockIdx.z;
        int zb = z / zdiv, zh = z - zb * zdiv;
        Ah += zb*sA1 + zh*sA2; Al += zb*sA1 + zh*sA2;
        Bh += zb*sB1 + zh*sB2; if (TERMS == 3) Bl += zb*sB1 + zh*sB2;
        coff = zb*sC1 + zh*sC2;
    }
    int m0 = blockIdx.x * 128;
    if (m0 >= Me) return;
    int n0 = blockIdx.y * TN;

    __shared__ int s_row[128];
    __shared__ int s_cout[128];
    extern __shared__ __align__(16) char dsm[];
    uint32_t dbase = smem_u32(dsm);

    int tid = threadIdx.x, lane = tid & 31, wid = tid >> 5;
    int wm = wid >> 2, wn = wid & 3;

    if (tid < 128) {
        int grow = m0 + tid;
        int rid = -1, cid = -1;
        if (grow < Me) {
            if      (MOE == 1) { rid = g_tokmap[rowbase + grow]; cid = rowbase + grow; }
            else if (MOE == 2) { rid = rowbase + grow;           cid = g_outmap[rowbase + grow]; }
            else               { rid = grow;                     cid = grow; }
        }
        s_row[tid] = rid; s_cout[tid] = cid;
    }
    __syncthreads();

    float acc[4][NF][4];
    #pragma unroll
    for (int a = 0; a < 4; a++)
        #pragma unroll
        for (int b = 0; b < NF; b++)
            #pragma unroll
            for (int c = 0; c < 4; c++) acc[a][b][c] = 0.f;

    int S = K / 32;

    auto load_stage = [&](int s) {
        int c0 = s * 32;
        uint32_t base = dbase + (uint32_t)(s % STAGES) * STB;
        constexpr int CH_A = 512;
        constexpr int CH_B = TN * 4;
        constexpr int ITER = (2*CH_A + (TERMS-1)*CH_B) / 256;
        #pragma unroll
        for (int j = 0; j < ITER; j++) {
            int idx = tid + j * 256;
            if (idx < CH_A) {
                int row = idx >> 2, c = idx & 3;
                int r = s_row[row];
                ll aoff = (r >= 0) ? ((ll)r * lda + c0 + c * 8) : 0;
                cpasync16z(base + (uint32_t)(row*80 + c*16), Ah + aoff, (r>=0)?16u:0u);
            } else if (idx < 2*CH_A) {
                int k2 = idx - CH_A;
                int row = k2 >> 2, c = k2 & 3;
                int r = s_row[row];
                ll aoff = (r >= 0) ? ((ll)r * lda + c0 + c * 8) : 0;
                cpasync16z(base + 10240u + (uint32_t)(row*80 + c*16), Al + aoff, (r>=0)?16u:0u);
            } else if (idx < 2*CH_A + CH_B) {
                int k2 = idx - 2*CH_A;
                int row = k2 >> 2, c = k2 & 3;
                cpasync16(base + BHOFF + (uint32_t)(row*80 + c*16),
                          Bh + (ll)(n0 + row) * ldb + c0 + c * 8);
            } else if (TERMS == 3) {
                int k2 = idx - 2*CH_A - CH_B;
                int row = k2 >> 2, c = k2 & 3;
                cpasync16(base + BLOFF + (uint32_t)(row*80 + c*16),
                          Bl + (ll)(n0 + row) * ldb + c0 + c * 8);
            }
        }
        asm volatile("cp.async.commit_group;" ::: "memory");
    };

    #pragma unroll
    for (int i = 0; i < STAGES - 1; i++) load_stage(i);

    for (int s = 0; s < S; s++) {
        if (S - s - 1 >= STAGES - 2) {
            asm volatile("cp.async.wait_group %0;" :: "n"(STAGES - 2) : "memory");
        } else {
            asm volatile("cp.async.wait_group 0;" ::: "memory");
        }
        __syncthreads();
        if (s + STAGES - 1 < S) load_stage(s + STAGES - 1);

        uint32_t base = dbase + (uint32_t)(s % STAGES) * STB;
        uint32_t Ahb = base, Alb = base + 10240u, Bhb = base + BHOFF, Blb = base + BLOFF;

        #pragma unroll
        for (int kk = 0; kk < 2; kk++) {
            uint32_t ah[4][4], al[4][4];
            #pragma unroll
            for (int mf = 0; mf < 4; mf++) {
                uint32_t roff = (uint32_t)(((wm*64 + mf*16 + (lane & 15)) * 40
                                            + kk*16 + (lane >> 4) * 8) * 2);
                ldmx4(ah[mf], Ahb + roff);
                ldmx4(al[mf], Alb + roff);
            }
            int g = lane >> 3;
            #pragma unroll
            for (int bt = 0; bt < NB16; bt++) {
                uint32_t bhf[4], blf[4];
                uint32_t roff = (uint32_t)(((wn*WN + bt*16 + (g >> 1)*8 + (lane & 7)) * 40
                                            + kk*16 + (g & 1) * 8) * 2);
                ldmx4(bhf, Bhb + roff);
                if (TERMS == 3) ldmx4(blf, Blb + roff);
                #pragma unroll
                for (int sub = 0; sub < 2; sub++) {
                    int nf = bt*2 + sub;
                    #pragma unroll
                    for (int mf = 0; mf < 4; mf++) {
                        mma16816(acc[mf][nf], ah[mf], bhf[sub*2], bhf[sub*2+1]);
                        mma16816(acc[mf][nf], al[mf], bhf[sub*2], bhf[sub*2+1]);
                        if (TERMS == 3)
                            mma16816(acc[mf][nf], ah[mf], blf[sub*2], blf[sub*2+1]);
                    }
                }
            }
        }
    }

    // ---------------- epilogue ----------------
    #pragma unroll
    for (int mf = 0; mf < 4; mf++) {
        int rbase = wm*64 + mf*16 + (lane >> 2);
        #pragma unroll
        for (int half = 0; half < 2; half++) {
            int rloc = rbase + half * 8;
            int cr = s_cout[rloc];
            if (cr < 0) continue;
            #pragma unroll
            for (int nf = 0; nf < NF; nf++) {
                int col = n0 + wn*WN + nf*8 + (lane & 3)*2;
                float v0 = acc[mf][nf][half*2 + 0] * alpha;
                float v1 = acc[mf][nf][half*2 + 1] * alpha;
                if (EPI >= 1) {
                    float2 bv = *(const float2*)&bias[col];
                    v0 += bv.x; v1 += bv.y;
                }
                if (EPI == 2) {
                    float2 rv = *(const float2*)(res + (ll)cr*ldc + col);
                    v0 += rv.x; v1 += rv.y;
                }
                if (EPI == 3 || EPI == 4) {
                    if (EPI == 3) {
                        v0 = 0.5f*v0*(1.f + erff(v0*0.70710678118654752f));
                        v1 = 0.5f*v1*(1.f + erff(v1*0.70710678118654752f));
                    }
                    __half h0 = __float2half(v0);
                    __half l0 = __float2half(v0 - __half2float(h0));
                    __half h1 = __float2half(v1);
                    __half l1 = __float2half(v1 - __half2float(h1));
                    __half* DH = (__half*)Cv + coff + (ll)cr * ldc + col;
                    __half* DL = Clo + coff + (ll)cr * ldc + col;
                    *(__half2*)DH = __halves2half2(h0, h1);
                    *(__half2*)DL = __halves2half2(l0, l1);
                } else {
                    *(float2*)((float*)Cv + coff + (ll)cr*ldc + col) = make_float2(v0, v1);
                }
            }
        }
    }
}

// ---------------- V transpose: qkv planes -> per-(b,h) V^T planes ----------------
__global__ void vtrans_k(const __half* __restrict__ qH, const __half* __restrict__ qL,
                         __half* __restrict__ vTH, __half* __restrict__ vTL) {
    int z = blockIdx.z; int b = z >> 3; int h = z & 7;
    int d0 = blockIdx.y * 32;
    int s0 = blockIdx.x * 32;
    __shared__ __half tH[32][33], tL[32][33];
    int tx = threadIdx.x, ty = threadIdx.y;   // 32 x 8
    #pragma unroll
    for (int i = 0; i < 4; i++) {
        int sl = ty*4 + i;
        ll src = (ll)(b*Sq + s0 + sl)*(3*Hq) + 2*Hq + h*DHq + d0 + tx;
        tH[sl][tx] = qH[src];
        tL[sl][tx] = qL[src];
    }
    __syncthreads();
    #pragma unroll
    for (int i = 0; i < 4; i++) {
        int dl = ty*4 + i;
        ll dst = ((ll)z*DHq + d0 + dl)*Sq + s0 + tx;
        vTH[dst] = tH[tx][dl];
        vTL[dst] = tL[tx][dl];
    }
}

// ---------------- small kernels ----------------
__global__ void embed_k(const int* __restrict__ ids, const float* __restrict__ emb) {
    int idx = blockIdx.x*256 + threadIdx.x;
    int t = idx / Hq, h = idx - t*Hq;
    g_x[idx] = emb[(ll)ids[t]*Hq + h];
}

__global__ void ln_k(const float* __restrict__ x, const float* __restrict__ g,
                     const float* __restrict__ b, float* __restrict__ o,
                     __half* __restrict__ oH, __half* __restrict__ oL) {
    int t = blockIdx.x;
    const float* xr = x + (ll)t*Hq;
    int tid = threadIdx.x;
    float v[4]; float s = 0.f;
    #pragma unroll
    for (int i = 0; i < 4; i++) { v[i] = xr[tid + 256*i]; s += v[i]; }
    __shared__ float red[256];
    red[tid] = s; __syncthreads();
    for (int o2 = 128; o2; o2 >>= 1) { if (tid < o2) red[tid] += red[tid+o2]; __syncthreads(); }
    float mu = red[0] * (1.f/Hq);
    __syncthreads();
    s = 0.f;
    #pragma unroll
    for (int i = 0; i < 4; i++) { float d = v[i]-mu; s += d*d; }
    red[tid] = s; __syncthreads();
    for (int o2 = 128; o2; o2 >>= 1) { if (tid < o2) red[tid] += red[tid+o2]; __syncthreads(); }
    float inv = rsqrtf(red[0]*(1.f/Hq) + 1e-5f);
    float* orow = o + (ll)t*Hq;
    __half* hr = oH + (ll)t*Hq;
    __half* lr = oL + (ll)t*Hq;
    #pragma unroll
    for (int i = 0; i < 4; i++) {
        int h = tid + 256*i;
        float y = (v[i]-mu)*inv*g[h] + b[h];
        orow[h] = y;
        __half hi = __float2half(y);
        hr[h] = hi;
        lr[h] = __float2half(y - __half2float(hi));
    }
}

__global__ void softmax_k(const float* __restrict__ sc,
                          __half* __restrict__ pH, __half* __restrict__ pL) {
    ll row = blockIdx.x;
    const float* r = sc + row*Sq;
    int tid = threadIdx.x;
    float a = r[tid], b = r[tid+256];
    __shared__ float red[256];
    red[tid] = fmaxf(a,b); __syncthreads();
    for (int o = 128; o; o >>= 1) { if (tid < o) red[tid] = fmaxf(red[tid], red[tid+o]); __syncthreads(); }
    float m = red[0]; __syncthreads();
    a = expf(a-m); b = expf(b-m);
    red[tid] = a+b; __syncthreads();
    for (int o = 128; o; o >>= 1) { if (tid < o) red[tid] += red[tid+o]; __syncthreads(); }
    float inv = 1.f/red[0];
    a *= inv; b *= inv;
    __half ha = __float2half(a), hb = __float2half(b);
    pH[row*Sq + tid]       = ha;
    pL[row*Sq + tid]       = __float2half(a - __half2float(ha));
    pH[row*Sq + tid + 256] = hb;
    pL[row*Sq + tid + 256] = __float2half(b - __half2float(hb));
}

__global__ void zero_cnt_k() { if (threadIdx.x < Eq) g_cnt[threadIdx.x] = 0; }
__global__ void zero_aux_k() {
    if (threadIdx.x == 0) g_aux[0] = 0.f;
    if (threadIdx.x < DHq) g_zb[threadIdx.x] = 0.f;
}

__global__ void router_k(const float* __restrict__ n2, const float* __restrict__ rw,
                         const float* __restrict__ rb) {
    int t = blockIdx.x;
    int w = threadIdx.x >> 5, lane = threadIdx.x & 31;
    const float* xr = n2 + (ll)t*Hq;
    const float* wr = rw + (ll)w*Hq;
    float s = 0.f;
    for (int h = lane; h < Hq; h += 32) s += xr[h]*wr[h];
    #pragma unroll
    for (int o = 16; o; o >>= 1) s += __shfl_xor_sync(0xffffffffu, s, o);
    __shared__ float lg[Eq];
    if (lane == 0) lg[w] = s + rb[w];
    __syncthreads();
    if (threadIdx.x == 0) {
        int b0 = 0; float v0 = lg[0];
        for (int e = 1; e < Eq; e++) if (lg[e] > v0) { v0 = lg[e]; b0 = e; }
        int b1 = -1; float v1 = -3.4e38f;
        for (int e = 0; e < Eq; e++) { if (e == b0) continue; if (lg[e] > v1) { v1 = lg[e]; b1 = e; } }
        g_sel[2*t]   = b0;
        g_sel[2*t+1] = b1;
        atomicAdd(&g_cnt[b0], 1);
        atomicAdd(&g_cnt[b1], 1);
    }
}

__global__ void offsets_k() {
    int s = 0;
    for (int e = 0; e < Eq; e++) { g_off[e] = s; g_cur[e] = s; s += g_cnt[e]; }
}

__global__ void build_k() {
    int t = blockIdx.x*256 + threadIdx.x;
    if (t >= Tq) return;
    #pragma unroll
    for (int slot = 0; slot < 2; slot++) {
        int e = g_sel[2*t + slot];
        int p = atomicAdd(&g_cur[e], 1);
        g_tokmap[p] = t;
        g_outmap[p] = slot*Tq + t;
    }
}

__global__ void aux_k() {
    float s = 0.f;
    const float target = (float)Tq / (float)Eq;
    for (int e = 0; e < Eq; e++) { float d = (float)g_cnt[e] - target; s += d*d; }
    g_aux[0] += 0.01f * s / (float)Eq;
}

__global__ void combine_k() {
    int idx = blockIdx.x*256 + threadIdx.x;
    g_x[idx] += g_moe[idx] + g_moe[(ll)Tq*Hq + idx];
}

__global__ void tail_k(float* __restrict__ out, ll out_size) {
    ll base = (ll)Tq * Vq;
    for (ll i = base + threadIdx.x; i < out_size; i += 256)
        out[i] = g_aux[0];
}

// ---------------- launch ----------------
static inline int cv8blocks(ll total) { return (int)((total/8 + 255) / 256); }

extern "C" void kernel_launch(void* const* d_in, const int* in_sizes, int n_in,
                              void* d_out, int out_size) {
    const int*   ids  = (const int*)  d_in[0];
    const float* emb  = (const float*)d_in[1];
    const float* ln1g = (const float*)d_in[2];
    const float* ln1b = (const float*)d_in[3];
    const float* aiw  = (const float*)d_in[4];
    const float* aib  = (const float*)d_in[5];
    const float* aow  = (const float*)d_in[6];
    const float* aob  = (const float*)d_in[7];
    const float* ln2g = (const float*)d_in[8];
    const float* ln2b = (const float*)d_in[9];
    const float* rw   = (const float*)d_in[10];
    const float* rb   = (const float*)d_in[11];
    const float* f1w  = (const float*)d_in[12];
    const float* f1b  = (const float*)d_in[13];
    const float* f2w  = (const float*)d_in[14];
    const float* f2b  = (const float*)d_in[15];
    const float* lmw  = (const float*)d_in[16];
    const float* lmb  = (const float*)d_in[17];
    float* out = (float*)d_out;

    cudaFuncSetAttribute(bgemm<4,0,256,3>, cudaFuncAttributeMaxDynamicSharedMemorySize, DS_TN256_T3);
    cudaFuncSetAttribute(bgemm<0,0,256,3>, cudaFuncAttributeMaxDynamicSharedMemorySize, DS_TN256_T3);
    cudaFuncSetAttribute(bgemm<4,0,128,3>, cudaFuncAttributeMaxDynamicSharedMemorySize, DS_TN128_T3);
    cudaFuncSetAttribute(bgemm<2,0,128,3>, cudaFuncAttributeMaxDynamicSharedMemorySize, DS_TN128_T3);
    cudaFuncSetAttribute(bgemm<3,1,256,2>, cudaFuncAttributeMaxDynamicSharedMemorySize, DS_TN256_T2);
    cudaFuncSetAttribute(bgemm<1,2,256,2>, cudaFuncAttributeMaxDynamicSharedMemorySize, DS_TN256_T2);
    cudaFuncSetAttribute(bgemm<1,0,256,2>, cudaFuncAttributeMaxDynamicSharedMemorySize, DS_TN256_T2);

    float *px, *pn, *psc, *pmoe;
    cudaGetSymbolAddress((void**)&px,   g_x);
    cudaGetSymbolAddress((void**)&pn,   g_n);
    cudaGetSymbolAddress((void**)&psc,  g_scores);
    cudaGetSymbolAddress((void**)&pmoe, g_moe);
    float* pzb; cudaGetSymbolAddress((void**)&pzb, g_zb);
    __half *winH,*winL,*woutH,*woutL,*f1H,*f2H,*lmH;
    __half *nH,*nL,*qkvH,*qkvL,*vTH,*vTL,*pH,*pL,*aoH,*aoL,*xH,*xL,*hH,*hL;
    cudaGetSymbolAddress((void**)&winH,  g_winH);  cudaGetSymbolAddress((void**)&winL,  g_winL);
    cudaGetSymbolAddress((void**)&woutH, g_woutH); cudaGetSymbolAddress((void**)&woutL, g_woutL);
    cudaGetSymbolAddress((void**)&f1H,   g_f1H);
    cudaGetSymbolAddress((void**)&f2H,   g_f2H);
    cudaGetSymbolAddress((void**)&lmH,   g_lmH);
    cudaGetSymbolAddress((void**)&nH,    g_nH);    cudaGetSymbolAddress((void**)&nL,    g_nL);
    cudaGetSymbolAddress((void**)&qkvH,  g_qkvH);  cudaGetSymbolAddress((void**)&qkvL,  g_qkvL);
    cudaGetSymbolAddress((void**)&vTH,   g_vTH);   cudaGetSymbolAddress((void**)&vTL,   g_vTL);
    cudaGetSymbolAddress((void**)&pH,    g_pH);    cudaGetSymbolAddress((void**)&pL,    g_pL);
    cudaGetSymbolAddress((void**)&aoH,   g_aoH);   cudaGetSymbolAddress((void**)&aoL,   g_aoL);
    cudaGetSymbolAddress((void**)&xH,    g_xH);    cudaGetSymbolAddress((void**)&xL,    g_xL);
    cudaGetSymbolAddress((void**)&hH,    g_hH);    cudaGetSymbolAddress((void**)&hL,    g_hL);

    // ---- weight conversions ----
    cvt2_k<<<cv8blocks((ll)Lq*3*Hq*Hq),  256>>>(aiw, winH,  winL,  (ll)Lq*3*Hq*Hq);
    cvt2_k<<<cv8blocks((ll)Lq*Hq*Hq),    256>>>(aow, woutH, woutL, (ll)Lq*Hq*Hq);
    cvt1_k<<<cv8blocks((ll)Lq*Eq*Iq*Hq), 256>>>(f1w, f1H, (ll)Lq*Eq*Iq*Hq);
    cvt1_k<<<cv8blocks((ll)Lq*Eq*Hq*Iq), 256>>>(f2w, f2H, (ll)Lq*Eq*Hq*Iq);
    cvt1_k<<<cv8blocks((ll)Vq*Hq),       256>>>(lmw, lmH, (ll)Vq*Hq);

    zero_aux_k<<<1,256>>>();
    embed_k<<<(Tq*Hq)/256, 256>>>(ids, emb);

    for (int l = 0; l < Lq; l++) {
        // --- attention ---
        ln_k<<<Tq,256>>>(px, ln1g + (ll)l*Hq, ln1b + (ll)l*Hq, pn, nH, nL);

        // qkv = n1 @ W_in^T + b  (3-term)
        bgemm<4,0,256,3><<<dim3(Tq/128, 3*Hq/256, 1), 256, DS_TN256_T3>>>(
            Tq, 3*Hq, Hq, nH, nL, Hq,
            winH + (ll)l*3*Hq*Hq, winL + (ll)l*3*Hq*Hq, Hq,
            qkvH, qkvL, 3*Hq, aib + (ll)l*3*Hq, nullptr,
            1.f, 1, 0,0,0,0,0,0, 0,0);

        // V^T planes per (b,h)
        vtrans_k<<<dim3(Sq/32, DHq/32, Bq*NHq), dim3(32,8)>>>(qkvH, qkvL, vTH, vTL);

        // scores = q @ k^T / sqrt(DH)  (3-term, batched over B*NH)
        bgemm<0,0,256,3><<<dim3(Sq/128, Sq/256, Bq*NHq), 256, DS_TN256_T3>>>(
            Sq, Sq, DHq, qkvH, qkvL, 3*Hq,
            qkvH + Hq, qkvL + Hq, 3*Hq,
            psc, nullptr, Sq, nullptr, nullptr,
            1.f/11.313708498984761f, NHq,
            (ll)Sq*3*Hq, DHq, (ll)Sq*3*Hq, DHq, (ll)NHq*Sq*Sq, (ll)Sq*Sq,
            0, 0);

        softmax_k<<<Bq*NHq*Sq, 256>>>(psc, pH, pL);

        // o = attn @ v  (3-term, batched, N=128)
        bgemm<4,0,128,3><<<dim3(Sq/128, DHq/128, Bq*NHq), 256, DS_TN128_T3>>>(
            Sq, DHq, Sq, pH, pL, Sq,
            vTH, vTL, Sq,
            aoH, aoL, Hq, pzb, nullptr,
            1.f, NHq,
            (ll)NHq*Sq*Sq, (ll)Sq*Sq, (ll)NHq*DHq*Sq, (ll)DHq*Sq,
            (ll)Sq*Hq, DHq,
            0, 0);

        // x = x + o @ W_out^T + b  (3-term)
        bgemm<2,0,128,3><<<dim3(Tq/128, Hq/128, 1), 256, DS_TN128_T3>>>(
            Tq, Hq, Hq, aoH, aoL, Hq,
            woutH + (ll)l*Hq*Hq, woutL + (ll)l*Hq*Hq, Hq,
            px, nullptr, Hq, aob + (ll)l*Hq, px,
            1.f, 1, 0,0,0,0,0,0, 0,0);

        // --- MoE ---
        ln_k<<<Tq,256>>>(px, ln2g + (ll)l*Hq, ln2b + (ll)l*Hq, pn, nH, nL);

        zero_cnt_k<<<1,32>>>();
        router_k<<<Tq,256>>>(pn, rw + (ll)l*Eq*Hq, rb + (ll)l*Eq);
        offsets_k<<<1,1>>>();
        build_k<<<Tq/256,256>>>();
        aux_k<<<1,1>>>();

        // fc1: gather, gelu, write hi/lo hidden planes  (2-term)
        bgemm<3,1,256,2><<<dim3(Tq/128, Iq/256, Eq), 256, DS_TN256_T2>>>(
            Tq, Iq, Hq, nH, nL, Hq,
            f1H + (ll)l*Eq*Iq*Hq, nullptr, Hq,
            hH, hL, Iq, f1b + (ll)l*Eq*Iq, nullptr,
            1.f, 1, 0,0,0,0,0,0, (ll)Iq*Hq, (ll)Iq);

        // fc2: scatter to per-slot fp32 buffers  (2-term)
        bgemm<1,2,256,2><<<dim3(Tq/128, Hq/256, Eq), 256, DS_TN256_T2>>>(
            Tq, Hq, Iq, hH, hL, Iq,
            f2H + (ll)l*Eq*Hq*Iq, nullptr, Iq,
            pmoe, nullptr, Hq, f2b + (ll)l*Eq*Hq, nullptr,
            1.f, 1, 0,0,0,0,0,0, (ll)Hq*Iq, (ll)Hq);

        combine_k<<<(Tq*Hq)/256, 256>>>();
    }

    // lm head  (2-term)
    cvt2_k<<<cv8blocks((ll)Tq*Hq), 256>>>(px, xH, xL, (ll)Tq*Hq);
    bgemm<1,0,256,2><<<dim3(Tq/128, Vq/256, 1), 256, DS_TN256_T2>>>(
        Tq, Vq, Hq, xH, xL, Hq, lmH, nullptr, Hq, out, nullptr, Vq,
        lmb, nullptr, 1.f, 1, 0,0,0,0,0,0, 0, 0);

    tail_k<<<1,256>>>(out, (ll)out_size);
}

// round 8
// speedup vs baseline: 3.6390x; 1.0523x over previous
#include <cuda_runtime.h>
#include <cuda_fp16.h>
#include <math.h>
#include <stdint.h>

// ---------------- problem constants ----------------
#define Bq 4
#define Sq 512
#define Hq 1024
#define Iq 4096
#define Eq 8
#define Vq 32000
#define Lq 2
#define NHq 8
#define DHq 128
#define Tq (Bq*Sq)          // 2048 tokens

typedef long long ll;

__device__ __forceinline__ uint32_t smem_u32(const void* p) {
    uint32_t a;
    asm("{ .reg .u64 t; cvta.to.shared.u64 t, %1; cvt.u32.u64 %0, t; }" : "=r"(a) : "l"(p));
    return a;
}

// ---------------- device scratch (static, no allocs) ----------------
__device__ float g_x[Tq*Hq];
__device__ float g_n[Tq*Hq];
__device__ float g_scores[Bq*NHq*Sq*Sq];
__device__ float g_moe[2*Tq*Hq];
__device__ int   g_sel[Tq*2];
__device__ int   g_cnt[Eq];
__device__ int   g_off[Eq];
__device__ int   g_cur[Eq];
__device__ int   g_tokmap[2*Tq];
__device__ int   g_outmap[2*Tq];
__device__ float g_aux[1];
__device__ float g_zb[DHq];      // zero bias
// fp16 planes (hi/lo for activations; hi-only for all weights now except none)
__device__ __half g_winH[Lq*3*Hq*Hq];
__device__ __half g_woutH[Lq*Hq*Hq];
__device__ __half g_f1H[(size_t)Lq*Eq*Iq*Hq];
__device__ __half g_f2H[(size_t)Lq*Eq*Hq*Iq];
__device__ __half g_lmH[(size_t)Vq*Hq];
__device__ __half g_nH[Tq*Hq],  g_nL[Tq*Hq];
__device__ __half g_qkvH[Tq*3*Hq], g_qkvL[Tq*3*Hq];
__device__ __half g_vTH[Tq*Hq], g_vTL[Tq*Hq];
__device__ __half g_pH[(size_t)Bq*NHq*Sq*Sq], g_pL[(size_t)Bq*NHq*Sq*Sq];
__device__ __half g_aoH[Tq*Hq], g_aoL[Tq*Hq];
__device__ __half g_xH[Tq*Hq],  g_xL[Tq*Hq];
__device__ __half g_hH[(size_t)2*Tq*Iq], g_hL[(size_t)2*Tq*Iq];

// ---------------- split conversions ----------------
__global__ void cvt2_k(const float* __restrict__ src, __half* __restrict__ hi,
                       __half* __restrict__ lo, ll total) {
    ll i = ((ll)blockIdx.x * 256 + threadIdx.x) * 8;
    if (i >= total) return;
    float4 a = *(const float4*)(src + i);
    float4 b = *(const float4*)(src + i + 4);
    float v[8] = {a.x, a.y, a.z, a.w, b.x, b.y, b.z, b.w};
    __align__(16) __half h[8];
    __align__(16) __half l[8];
    #pragma unroll
    for (int j = 0; j < 8; j++) {
        h[j] = __float2half(v[j]);
        l[j] = __float2half(v[j] - __half2float(h[j]));
    }
    *(uint4*)(hi + i) = *(const uint4*)h;
    *(uint4*)(lo + i) = *(const uint4*)l;
}
__global__ void cvt1_k(const float* __restrict__ src, __half* __restrict__ hi, ll total) {
    ll i = ((ll)blockIdx.x * 256 + threadIdx.x) * 8;
    if (i >= total) return;
    float4 a = *(const float4*)(src + i);
    float4 b = *(const float4*)(src + i + 4);
    float v[8] = {a.x, a.y, a.z, a.w, b.x, b.y, b.z, b.w};
    __align__(16) __half h[8];
    #pragma unroll
    for (int j = 0; j < 8; j++) h[j] = __float2half(v[j]);
    *(uint4*)(hi + i) = *(const uint4*)h;
}

// ---------------- HMMA fp16 split GEMM ----------------
// TERMS=3: C = Ah*Bh + Al*Bh + Ah*Bl    TERMS=2: C = (Ah+Al)*Bh
// CTA tile 128xTN, BK=32, cp.async pipeline, 8 warps (2x4), warp 64x(TN/4).
// EPI: 0=alpha(f32), 1=bias(f32), 2=bias+res(f32), 3=bias+gelu->planes, 4=bias->planes.
// MOE: 0 dense/batched, 1 gather-A/compact-C, 2 compact-A/scatter-C.
#define DS_TN256_T3 184320   // 3 stages x 61440
#define DS_TN128_T3 163840   // 4 stages x 40960
#define DS_TN256_T2 163840   // 4 stages x 40960
#define DS_TN128_T2 122880   // 4 stages x 30720

__device__ __forceinline__ void ldmx4(uint32_t* r, uint32_t addr) {
    asm volatile("ldmatrix.sync.aligned.m8n8.x4.shared.b16 {%0,%1,%2,%3}, [%4];"
        : "=r"(r[0]), "=r"(r[1]), "=r"(r[2]), "=r"(r[3]) : "r"(addr));
}
__device__ __forceinline__ void mma16816(float* c, const uint32_t* a, uint32_t b0, uint32_t b1) {
    asm volatile("mma.sync.aligned.m16n8k16.row.col.f32.f16.f16.f32 "
        "{%0,%1,%2,%3}, {%4,%5,%6,%7}, {%8,%9}, {%0,%1,%2,%3};"
        : "+f"(c[0]), "+f"(c[1]), "+f"(c[2]), "+f"(c[3])
        : "r"(a[0]), "r"(a[1]), "r"(a[2]), "r"(a[3]), "r"(b0), "r"(b1));
}
__device__ __forceinline__ void cpasync16(uint32_t dst, const void* src) {
    asm volatile("cp.async.cg.shared.global [%0], [%1], 16;" :: "r"(dst), "l"(src));
}
__device__ __forceinline__ void cpasync16z(uint32_t dst, const void* src, uint32_t sz) {
    asm volatile("cp.async.cg.shared.global [%0], [%1], 16, %2;" :: "r"(dst), "l"(src), "r"(sz));
}

template<int EPI, int MOE, int TN, int TERMS>
__global__ __launch_bounds__(256, 1)
void bgemm(int M, int N, int K,
           const __half* __restrict__ Ah, const __half* __restrict__ Al, int lda,
           const __half* __restrict__ Bh, const __half* __restrict__ Bl, int ldb,
           void* __restrict__ Cv, __half* __restrict__ Clo, int ldc,
           const float* __restrict__ bias,
           const float* __restrict__ res,
           float alpha, int zdiv,
           ll sA1, ll sA2, ll sB1, ll sB2, ll sC1, ll sC2,
           ll sBz, ll sBiasZ)
{
    constexpr int WN     = TN / 4;
    constexpr int NF     = WN / 8;
    constexpr int NB16   = WN / 16;
    constexpr int STAGES = (TERMS == 3 && TN == 256) ? 3 : 4;
    constexpr uint32_t STB = 20480u + (uint32_t)TN * 80u * (TERMS - 1);
    constexpr uint32_t BHOFF = 20480u;
    constexpr uint32_t BLOFF = 20480u + (uint32_t)TN * 80u;

    int Me = M, rowbase = 0;
    ll coff = 0;
    if (MOE) {
        int z = blockIdx.z;
        Me = g_cnt[z]; rowbase = g_off[z];
        Bh += (ll)z * sBz; if (TERMS == 3) Bl += (ll)z * sBz;
        bias += (ll)z * sBiasZ;
    } else {
        int z = blockIdx.z;
        int zb = z / zdiv, zh = z - zb * zdiv;
        Ah += zb*sA1 + zh*sA2; Al += zb*sA1 + zh*sA2;
        Bh += zb*sB1 + zh*sB2; if (TERMS == 3) Bl += zb*sB1 + zh*sB2;
        coff = zb*sC1 + zh*sC2;
    }
    int m0 = blockIdx.x * 128;
    if (m0 >= Me) return;
    int n0 = blockIdx.y * TN;

    __shared__ int s_row[128];
    __shared__ int s_cout[128];
    extern __shared__ __align__(16) char dsm[];
    uint32_t dbase = smem_u32(dsm);

    int tid = threadIdx.x, lane = tid & 31, wid = tid >> 5;
    int wm = wid >> 2, wn = wid & 3;

    if (tid < 128) {
        int grow = m0 + tid;
        int rid = -1, cid = -1;
        if (grow < Me) {
            if      (MOE == 1) { rid = g_tokmap[rowbase + grow]; cid = rowbase + grow; }
            else if (MOE == 2) { rid = rowbase + grow;           cid = g_outmap[rowbase + grow]; }
            else               { rid = grow;                     cid = grow; }
        }
        s_row[tid] = rid; s_cout[tid] = cid;
    }
    __syncthreads();

    float acc[4][NF][4];
    #pragma unroll
    for (int a = 0; a < 4; a++)
        #pragma unroll
        for (int b = 0; b < NF; b++)
            #pragma unroll
            for (int c = 0; c < 4; c++) acc[a][b][c] = 0.f;

    int S = K / 32;

    auto load_stage = [&](int s) {
        int c0 = s * 32;
        uint32_t base = dbase + (uint32_t)(s % STAGES) * STB;
        constexpr int CH_A = 512;
        constexpr int CH_B = TN * 4;
        constexpr int ITER = (2*CH_A + (TERMS-1)*CH_B) / 256;
        #pragma unroll
        for (int j = 0; j < ITER; j++) {
            int idx = tid + j * 256;
            if (idx < CH_A) {
                int row = idx >> 2, c = idx & 3;
                int r = s_row[row];
                ll aoff = (r >= 0) ? ((ll)r * lda + c0 + c * 8) : 0;
                cpasync16z(base + (uint32_t)(row*80 + c*16), Ah + aoff, (r>=0)?16u:0u);
            } else if (idx < 2*CH_A) {
                int k2 = idx - CH_A;
                int row = k2 >> 2, c = k2 & 3;
                int r = s_row[row];
                ll aoff = (r >= 0) ? ((ll)r * lda + c0 + c * 8) : 0;
                cpasync16z(base + 10240u + (uint32_t)(row*80 + c*16), Al + aoff, (r>=0)?16u:0u);
            } else if (idx < 2*CH_A + CH_B) {
                int k2 = idx - 2*CH_A;
                int row = k2 >> 2, c = k2 & 3;
                cpasync16(base + BHOFF + (uint32_t)(row*80 + c*16),
                          Bh + (ll)(n0 + row) * ldb + c0 + c * 8);
            } else if (TERMS == 3) {
                int k2 = idx - 2*CH_A - CH_B;
                int row = k2 >> 2, c = k2 & 3;
                cpasync16(base + BLOFF + (uint32_t)(row*80 + c*16),
                          Bl + (ll)(n0 + row) * ldb + c0 + c * 8);
            }
        }
        asm volatile("cp.async.commit_group;" ::: "memory");
    };

    #pragma unroll
    for (int i = 0; i < STAGES - 1; i++) load_stage(i);

    for (int s = 0; s < S; s++) {
        if (S - s - 1 >= STAGES - 2) {
            asm volatile("cp.async.wait_group %0;" :: "n"(STAGES - 2) : "memory");
        } else {
            asm volatile("cp.async.wait_group 0;" ::: "memory");
        }
        __syncthreads();
        if (s + STAGES - 1 < S) load_stage(s + STAGES - 1);

        uint32_t base = dbase + (uint32_t)(s % STAGES) * STB;
        uint32_t Ahb = base, Alb = base + 10240u, Bhb = base + BHOFF, Blb = base + BLOFF;

        #pragma unroll
        for (int kk = 0; kk < 2; kk++) {
            uint32_t ah[4][4], al[4][4];
            #pragma unroll
            for (int mf = 0; mf < 4; mf++) {
                uint32_t roff = (uint32_t)(((wm*64 + mf*16 + (lane & 15)) * 40
                                            + kk*16 + (lane >> 4) * 8) * 2);
                ldmx4(ah[mf], Ahb + roff);
                ldmx4(al[mf], Alb + roff);
            }
            int g = lane >> 3;
            #pragma unroll
            for (int bt = 0; bt < NB16; bt++) {
                uint32_t bhf[4], blf[4];
                uint32_t roff = (uint32_t)(((wn*WN + bt*16 + (g >> 1)*8 + (lane & 7)) * 40
                                            + kk*16 + (g & 1) * 8) * 2);
                ldmx4(bhf, Bhb + roff);
                if (TERMS == 3) ldmx4(blf, Blb + roff);
                #pragma unroll
                for (int sub = 0; sub < 2; sub++) {
                    int nf = bt*2 + sub;
                    #pragma unroll
                    for (int mf = 0; mf < 4; mf++) {
                        mma16816(acc[mf][nf], ah[mf], bhf[sub*2], bhf[sub*2+1]);
                        mma16816(acc[mf][nf], al[mf], bhf[sub*2], bhf[sub*2+1]);
                        if (TERMS == 3)
                            mma16816(acc[mf][nf], ah[mf], blf[sub*2], blf[sub*2+1]);
                    }
                }
            }
        }
    }

    // ---------------- epilogue ----------------
    #pragma unroll
    for (int mf = 0; mf < 4; mf++) {
        int rbase = wm*64 + mf*16 + (lane >> 2);
        #pragma unroll
        for (int half = 0; half < 2; half++) {
            int rloc = rbase + half * 8;
            int cr = s_cout[rloc];
            if (cr < 0) continue;
            #pragma unroll
            for (int nf = 0; nf < NF; nf++) {
                int col = n0 + wn*WN + nf*8 + (lane & 3)*2;
                float v0 = acc[mf][nf][half*2 + 0] * alpha;
                float v1 = acc[mf][nf][half*2 + 1] * alpha;
                if (EPI >= 1) {
                    float2 bv = *(const float2*)&bias[col];
                    v0 += bv.x; v1 += bv.y;
                }
                if (EPI == 2) {
                    float2 rv = *(const float2*)(res + (ll)cr*ldc + col);
                    v0 += rv.x; v1 += rv.y;
                }
                if (EPI == 3 || EPI == 4) {
                    if (EPI == 3) {
                        v0 = 0.5f*v0*(1.f + erff(v0*0.70710678118654752f));
                        v1 = 0.5f*v1*(1.f + erff(v1*0.70710678118654752f));
                    }
                    __half h0 = __float2half(v0);
                    __half l0 = __float2half(v0 - __half2float(h0));
                    __half h1 = __float2half(v1);
                    __half l1 = __float2half(v1 - __half2float(h1));
                    __half* DH = (__half*)Cv + coff + (ll)cr * ldc + col;
                    __half* DL = Clo + coff + (ll)cr * ldc + col;
                    *(__half2*)DH = __halves2half2(h0, h1);
                    *(__half2*)DL = __halves2half2(l0, l1);
                } else {
                    *(float2*)((float*)Cv + coff + (ll)cr*ldc + col) = make_float2(v0, v1);
                }
            }
        }
    }
}

// ---------------- V transpose: qkv planes -> per-(b,h) V^T planes ----------------
__global__ void vtrans_k(const __half* __restrict__ qH, const __half* __restrict__ qL,
                         __half* __restrict__ vTH, __half* __restrict__ vTL) {
    int z = blockIdx.z; int b = z >> 3; int h = z & 7;
    int d0 = blockIdx.y * 32;
    int s0 = blockIdx.x * 32;
    __shared__ __half tH[32][33], tL[32][33];
    int tx = threadIdx.x, ty = threadIdx.y;   // 32 x 8
    #pragma unroll
    for (int i = 0; i < 4; i++) {
        int sl = ty*4 + i;
        ll src = (ll)(b*Sq + s0 + sl)*(3*Hq) + 2*Hq + h*DHq + d0 + tx;
        tH[sl][tx] = qH[src];
        tL[sl][tx] = qL[src];
    }
    __syncthreads();
    #pragma unroll
    for (int i = 0; i < 4; i++) {
        int dl = ty*4 + i;
        ll dst = ((ll)z*DHq + d0 + dl)*Sq + s0 + tx;
        vTH[dst] = tH[tx][dl];
        vTL[dst] = tL[tx][dl];
    }
}

// ---------------- small kernels ----------------
__global__ void embed_k(const int* __restrict__ ids, const float* __restrict__ emb) {
    int idx = blockIdx.x*256 + threadIdx.x;
    int t = idx / Hq, h = idx - t*Hq;
    g_x[idx] = emb[(ll)ids[t]*Hq + h];
}

__global__ void ln_k(const float* __restrict__ x, const float* __restrict__ g,
                     const float* __restrict__ b, float* __restrict__ o,
                     __half* __restrict__ oH, __half* __restrict__ oL,
                     int zero_counts) {
    int t = blockIdx.x;
    if (zero_counts && t == 0 && threadIdx.x < Eq) g_cnt[threadIdx.x] = 0;
    const float* xr = x + (ll)t*Hq;
    int tid = threadIdx.x;
    float v[4]; float s = 0.f;
    #pragma unroll
    for (int i = 0; i < 4; i++) { v[i] = xr[tid + 256*i]; s += v[i]; }
    __shared__ float red[256];
    red[tid] = s; __syncthreads();
    for (int o2 = 128; o2; o2 >>= 1) { if (tid < o2) red[tid] += red[tid+o2]; __syncthreads(); }
    float mu = red[0] * (1.f/Hq);
    __syncthreads();
    s = 0.f;
    #pragma unroll
    for (int i = 0; i < 4; i++) { float d = v[i]-mu; s += d*d; }
    red[tid] = s; __syncthreads();
    for (int o2 = 128; o2; o2 >>= 1) { if (tid < o2) red[tid] += red[tid+o2]; __syncthreads(); }
    float inv = rsqrtf(red[0]*(1.f/Hq) + 1e-5f);
    float* orow = o + (ll)t*Hq;
    __half* hr = oH + (ll)t*Hq;
    __half* lr = oL + (ll)t*Hq;
    #pragma unroll
    for (int i = 0; i < 4; i++) {
        int h = tid + 256*i;
        float y = (v[i]-mu)*inv*g[h] + b[h];
        orow[h] = y;
        __half hi = __float2half(y);
        hr[h] = hi;
        lr[h] = __float2half(y - __half2float(hi));
    }
}

__global__ void softmax_k(const float* __restrict__ sc,
                          __half* __restrict__ pH, __half* __restrict__ pL) {
    ll row = blockIdx.x;
    const float* r = sc + row*Sq;
    int tid = threadIdx.x;
    float a = r[tid], b = r[tid+256];
    __shared__ float red[256];
    red[tid] = fmaxf(a,b); __syncthreads();
    for (int o = 128; o; o >>= 1) { if (tid < o) red[tid] = fmaxf(red[tid], red[tid+o]); __syncthreads(); }
    float m = red[0]; __syncthreads();
    a = expf(a-m); b = expf(b-m);
    red[tid] = a+b; __syncthreads();
    for (int o = 128; o; o >>= 1) { if (tid < o) red[tid] += red[tid+o]; __syncthreads(); }
    float inv = 1.f/red[0];
    a *= inv; b *= inv;
    __half ha = __float2half(a), hb = __float2half(b);
    pH[row*Sq + tid]       = ha;
    pL[row*Sq + tid]       = __float2half(a - __half2float(ha));
    pH[row*Sq + tid + 256] = hb;
    pL[row*Sq + tid + 256] = __float2half(b - __half2float(hb));
}

__global__ void zero_aux_k() {
    if (threadIdx.x == 0) g_aux[0] = 0.f;
    if (threadIdx.x < DHq) g_zb[threadIdx.x] = 0.f;
}

__global__ void router_k(const float* __restrict__ n2, const float* __restrict__ rw,
                         const float* __restrict__ rb) {
    int t = blockIdx.x;
    int w = threadIdx.x >> 5, lane = threadIdx.x & 31;
    const float* xr = n2 + (ll)t*Hq;
    const float* wr = rw + (ll)w*Hq;
    float s = 0.f;
    for (int h = lane; h < Hq; h += 32) s += xr[h]*wr[h];
    #pragma unroll
    for (int o = 16; o; o >>= 1) s += __shfl_xor_sync(0xffffffffu, s, o);
    __shared__ float lg[Eq];
    if (lane == 0) lg[w] = s + rb[w];
    __syncthreads();
    if (threadIdx.x == 0) {
        int b0 = 0; float v0 = lg[0];
        for (int e = 1; e < Eq; e++) if (lg[e] > v0) { v0 = lg[e]; b0 = e; }
        int b1 = -1; float v1 = -3.4e38f;
        for (int e = 0; e < Eq; e++) { if (e == b0) continue; if (lg[e] > v1) { v1 = lg[e]; b1 = e; } }
        g_sel[2*t]   = b0;
        g_sel[2*t+1] = b1;
        atomicAdd(&g_cnt[b0], 1);
        atomicAdd(&g_cnt[b1], 1);
    }
}

// offsets + aux loss fused (1 thread)
__global__ void offsets_k() {
    int s = 0;
    float acc = 0.f;
    const float target = (float)Tq / (float)Eq;
    for (int e = 0; e < Eq; e++) {
        g_off[e] = s; g_cur[e] = s; s += g_cnt[e];
        float d = (float)g_cnt[e] - target;
        acc += d*d;
    }
    g_aux[0] += 0.01f * acc / (float)Eq;
}

__global__ void build_k() {
    int t = blockIdx.x*256 + threadIdx.x;
    if (t >= Tq) return;
    #pragma unroll
    for (int slot = 0; slot < 2; slot++) {
        int e = g_sel[2*t + slot];
        int p = atomicAdd(&g_cur[e], 1);
        g_tokmap[p] = t;
        g_outmap[p] = slot*Tq + t;
    }
}

// combine + optional hi/lo plane emission (for lm-head input after last layer)
__global__ void combine_k(__half* __restrict__ xH, __half* __restrict__ xL) {
    int idx = blockIdx.x*256 + threadIdx.x;
    float v = g_x[idx] + g_moe[idx] + g_moe[(ll)Tq*Hq + idx];
    g_x[idx] = v;
    if (xH) {
        __half hi = __float2half(v);
        xH[idx] = hi;
        xL[idx] = __float2half(v - __half2float(hi));
    }
}

__global__ void tail_k(float* __restrict__ out, ll out_size) {
    ll base = (ll)Tq * Vq;
    for (ll i = base + threadIdx.x; i < out_size; i += 256)
        out[i] = g_aux[0];
}

// ---------------- launch ----------------
static inline int cv8blocks(ll total) { return (int)((total/8 + 255) / 256); }

extern "C" void kernel_launch(void* const* d_in, const int* in_sizes, int n_in,
                              void* d_out, int out_size) {
    const int*   ids  = (const int*)  d_in[0];
    const float* emb  = (const float*)d_in[1];
    const float* ln1g = (const float*)d_in[2];
    const float* ln1b = (const float*)d_in[3];
    const float* aiw  = (const float*)d_in[4];
    const float* aib  = (const float*)d_in[5];
    const float* aow  = (const float*)d_in[6];
    const float* aob  = (const float*)d_in[7];
    const float* ln2g = (const float*)d_in[8];
    const float* ln2b = (const float*)d_in[9];
    const float* rw   = (const float*)d_in[10];
    const float* rb   = (const float*)d_in[11];
    const float* f1w  = (const float*)d_in[12];
    const float* f1b  = (const float*)d_in[13];
    const float* f2w  = (const float*)d_in[14];
    const float* f2b  = (const float*)d_in[15];
    const float* lmw  = (const float*)d_in[16];
    const float* lmb  = (const float*)d_in[17];
    float* out = (float*)d_out;

    cudaFuncSetAttribute(bgemm<4,0,256,2>, cudaFuncAttributeMaxDynamicSharedMemorySize, DS_TN256_T2);
    cudaFuncSetAttribute(bgemm<0,0,256,3>, cudaFuncAttributeMaxDynamicSharedMemorySize, DS_TN256_T3);
    cudaFuncSetAttribute(bgemm<4,0,128,3>, cudaFuncAttributeMaxDynamicSharedMemorySize, DS_TN128_T3);
    cudaFuncSetAttribute(bgemm<2,0,128,2>, cudaFuncAttributeMaxDynamicSharedMemorySize, DS_TN128_T2);
    cudaFuncSetAttribute(bgemm<3,1,256,2>, cudaFuncAttributeMaxDynamicSharedMemorySize, DS_TN256_T2);
    cudaFuncSetAttribute(bgemm<1,2,256,2>, cudaFuncAttributeMaxDynamicSharedMemorySize, DS_TN256_T2);
    cudaFuncSetAttribute(bgemm<1,0,256,2>, cudaFuncAttributeMaxDynamicSharedMemorySize, DS_TN256_T2);

    float *px, *pn, *psc, *pmoe;
    cudaGetSymbolAddress((void**)&px,   g_x);
    cudaGetSymbolAddress((void**)&pn,   g_n);
    cudaGetSymbolAddress((void**)&psc,  g_scores);
    cudaGetSymbolAddress((void**)&pmoe, g_moe);
    float* pzb; cudaGetSymbolAddress((void**)&pzb, g_zb);
    __half *winH,*woutH,*f1H,*f2H,*lmH;
    __half *nH,*nL,*qkvH,*qkvL,*vTH,*vTL,*pH,*pL,*aoH,*aoL,*xH,*xL,*hH,*hL;
    cudaGetSymbolAddress((void**)&winH,  g_winH);
    cudaGetSymbolAddress((void**)&woutH, g_woutH);
    cudaGetSymbolAddress((void**)&f1H,   g_f1H);
    cudaGetSymbolAddress((void**)&f2H,   g_f2H);
    cudaGetSymbolAddress((void**)&lmH,   g_lmH);
    cudaGetSymbolAddress((void**)&nH,    g_nH);    cudaGetSymbolAddress((void**)&nL,    g_nL);
    cudaGetSymbolAddress((void**)&qkvH,  g_qkvH);  cudaGetSymbolAddress((void**)&qkvL,  g_qkvL);
    cudaGetSymbolAddress((void**)&vTH,   g_vTH);   cudaGetSymbolAddress((void**)&vTL,   g_vTL);
    cudaGetSymbolAddress((void**)&pH,    g_pH);    cudaGetSymbolAddress((void**)&pL,    g_pL);
    cudaGetSymbolAddress((void**)&aoH,   g_aoH);   cudaGetSymbolAddress((void**)&aoL,   g_aoL);
    cudaGetSymbolAddress((void**)&xH,    g_xH);    cudaGetSymbolAddress((void**)&xL,    g_xL);
    cudaGetSymbolAddress((void**)&hH,    g_hH);    cudaGetSymbolAddress((void**)&hL,    g_hL);

    // ---- weight conversions (hi-only everywhere: all weight GEMMs are 2-term) ----
    cvt1_k<<<cv8blocks((ll)Lq*3*Hq*Hq),  256>>>(aiw, winH,  (ll)Lq*3*Hq*Hq);
    cvt1_k<<<cv8blocks((ll)Lq*Hq*Hq),    256>>>(aow, woutH, (ll)Lq*Hq*Hq);
    cvt1_k<<<cv8blocks((ll)Lq*Eq*Iq*Hq), 256>>>(f1w, f1H, (ll)Lq*Eq*Iq*Hq);
    cvt1_k<<<cv8blocks((ll)Lq*Eq*Hq*Iq), 256>>>(f2w, f2H, (ll)Lq*Eq*Hq*Iq);
    cvt1_k<<<cv8blocks((ll)Vq*Hq),       256>>>(lmw, lmH, (ll)Vq*Hq);

    zero_aux_k<<<1,256>>>();
    embed_k<<<(Tq*Hq)/256, 256>>>(ids, emb);

    for (int l = 0; l < Lq; l++) {
        // --- attention ---
        ln_k<<<Tq,256>>>(px, ln1g + (ll)l*Hq, ln1b + (ll)l*Hq, pn, nH, nL, 0);

        // qkv = n1 @ W_in^T + b  (2-term: weight-lo dropped)
        bgemm<4,0,256,2><<<dim3(Tq/128, 3*Hq/256, 1), 256, DS_TN256_T2>>>(
            Tq, 3*Hq, Hq, nH, nL, Hq,
            winH + (ll)l*3*Hq*Hq, nullptr, Hq,
            qkvH, qkvL, 3*Hq, aib + (ll)l*3*Hq, nullptr,
            1.f, 1, 0,0,0,0,0,0, 0,0);

        // V^T planes per (b,h)
        vtrans_k<<<dim3(Sq/32, DHq/32, Bq*NHq), dim3(32,8)>>>(qkvH, qkvL, vTH, vTL);

        // scores = q @ k^T / sqrt(DH)  (3-term, batched over B*NH)
        bgemm<0,0,256,3><<<dim3(Sq/128, Sq/256, Bq*NHq), 256, DS_TN256_T3>>>(
            Sq, Sq, DHq, qkvH, qkvL, 3*Hq,
            qkvH + Hq, qkvL + Hq, 3*Hq,
            psc, nullptr, Sq, nullptr, nullptr,
            1.f/11.313708498984761f, NHq,
            (ll)Sq*3*Hq, DHq, (ll)Sq*3*Hq, DHq, (ll)NHq*Sq*Sq, (ll)Sq*Sq,
            0, 0);

        softmax_k<<<Bq*NHq*Sq, 256>>>(psc, pH, pL);

        // o = attn @ v  (3-term, batched, N=128)
        bgemm<4,0,128,3><<<dim3(Sq/128, DHq/128, Bq*NHq), 256, DS_TN128_T3>>>(
            Sq, DHq, Sq, pH, pL, Sq,
            vTH, vTL, Sq,
            aoH, aoL, Hq, pzb, nullptr,
            1.f, NHq,
            (ll)NHq*Sq*Sq, (ll)Sq*Sq, (ll)NHq*DHq*Sq, (ll)DHq*Sq,
            (ll)Sq*Hq, DHq,
            0, 0);

        // x = x + o @ W_out^T + b  (2-term)
        bgemm<2,0,128,2><<<dim3(Tq/128, Hq/128, 1), 256, DS_TN128_T2>>>(
            Tq, Hq, Hq, aoH, aoL, Hq,
            woutH + (ll)l*Hq*Hq, nullptr, Hq,
            px, nullptr, Hq, aob + (ll)l*Hq, px,
            1.f, 1, 0,0,0,0,0,0, 0,0);

        // --- MoE ---
        ln_k<<<Tq,256>>>(px, ln2g + (ll)l*Hq, ln2b + (ll)l*Hq, pn, nH, nL, 1);

        router_k<<<Tq,256>>>(pn, rw + (ll)l*Eq*Hq, rb + (ll)l*Eq);
        offsets_k<<<1,1>>>();
        build_k<<<Tq/256,256>>>();

        // fc1: gather, gelu, write hi/lo hidden planes  (2-term)
        bgemm<3,1,256,2><<<dim3(Tq/128, Iq/256, Eq), 256, DS_TN256_T2>>>(
            Tq, Iq, Hq, nH, nL, Hq,
            f1H + (ll)l*Eq*Iq*Hq, nullptr, Hq,
            hH, hL, Iq, f1b + (ll)l*Eq*Iq, nullptr,
            1.f, 1, 0,0,0,0,0,0, (ll)Iq*Hq, (ll)Iq);

        // fc2: scatter to per-slot fp32 buffers  (2-term)
        bgemm<1,2,256,2><<<dim3(Tq/128, Hq/256, Eq), 256, DS_TN256_T2>>>(
            Tq, Hq, Iq, hH, hL, Iq,
            f2H + (ll)l*Eq*Hq*Iq, nullptr, Iq,
            pmoe, nullptr, Hq, f2b + (ll)l*Eq*Hq, nullptr,
            1.f, 1, 0,0,0,0,0,0, (ll)Hq*Iq, (ll)Hq);

        // combine; on last layer also emit x hi/lo planes for lm head
        bool last = (l == Lq - 1);
        combine_k<<<(Tq*Hq)/256, 256>>>(last ? xH : nullptr, last ? xL : nullptr);
    }

    // lm head  (2-term)
    bgemm<1,0,256,2><<<dim3(Tq/128, Vq/256, 1), 256, DS_TN256_T2>>>(
        Tq, Vq, Hq, xH, xL, Hq, lmH, nullptr, Hq, out, nullptr, Vq,
        lmb, nullptr, 1.f, 1, 0,0,0,0,0,0, 0, 0);

    tail_k<<<1,256>>>(out, (ll)out_size);
}

// round 9
// speedup vs baseline: 4.0918x; 1.1244x over previous
#include <cuda_runtime.h>
#include <cuda_fp16.h>
#include <math.h>
#include <stdint.h>

// ---------------- problem constants ----------------
#define Bq 4
#define Sq 512
#define Hq 1024
#define Iq 4096
#define Eq 8
#define Vq 32000
#define Lq 2
#define NHq 8
#define DHq 128
#define Tq (Bq*Sq)          // 2048 tokens

typedef long long ll;

__device__ __forceinline__ uint32_t smem_u32(const void* p) {
    uint32_t a;
    asm("{ .reg .u64 t; cvta.to.shared.u64 t, %1; cvt.u32.u64 %0, t; }" : "=r"(a) : "l"(p));
    return a;
}

// ---------------- device scratch (static, no allocs) ----------------
__device__ float g_x[Tq*Hq];
__device__ float g_n[Tq*Hq];
__device__ float g_scores[Bq*NHq*Sq*Sq];
__device__ float g_moe[2*Tq*Hq];
__device__ int   g_sel[Tq*2];
__device__ int   g_cnt[Eq];
__device__ int   g_off[Eq];
__device__ int   g_cur[Eq];
__device__ int   g_tokmap[2*Tq];
__device__ int   g_outmap[2*Tq];
__device__ float g_aux[1];
__device__ float g_zb[DHq];      // zero bias
// fp16 planes
__device__ __half g_winH[Lq*3*Hq*Hq];
__device__ __half g_woutH[Lq*Hq*Hq];
__device__ __half g_f1H[(size_t)Lq*Eq*Iq*Hq];
__device__ __half g_f2H[(size_t)Lq*Eq*Hq*Iq];
__device__ __half g_lmH[(size_t)Vq*Hq];
__device__ __half g_nH[Tq*Hq],  g_nL[Tq*Hq];
__device__ __half g_qkvH[Tq*3*Hq], g_qkvL[Tq*3*Hq];
__device__ __half g_vTH[Tq*Hq], g_vTL[Tq*Hq];
__device__ __half g_pH[(size_t)Bq*NHq*Sq*Sq], g_pL[(size_t)Bq*NHq*Sq*Sq];
__device__ __half g_aoH[Tq*Hq], g_aoL[Tq*Hq];
__device__ __half g_xH[Tq*Hq];
__device__ __half g_hH[(size_t)2*Tq*Iq], g_hL[(size_t)2*Tq*Iq];

// ---------------- conversions ----------------
__global__ void cvt1_k(const float* __restrict__ src, __half* __restrict__ hi, ll total) {
    ll i = ((ll)blockIdx.x * 256 + threadIdx.x) * 8;
    if (i >= total) return;
    float4 a = *(const float4*)(src + i);
    float4 b = *(const float4*)(src + i + 4);
    float v[8] = {a.x, a.y, a.z, a.w, b.x, b.y, b.z, b.w};
    __align__(16) __half h[8];
    #pragma unroll
    for (int j = 0; j < 8; j++) h[j] = __float2half(v[j]);
    *(uint4*)(hi + i) = *(const uint4*)h;
}

// ---------------- HMMA fp16 split GEMM ----------------
// TERMS=3: C = Ah*Bh + Al*Bh + Ah*Bl
// TERMS=2: C = (Ah+Al)*Bh
// TERMS=1: C = Ah*Bh
// CTA tile 128xTN, BK=32, cp.async pipeline, 8 warps (2x4), warp 64x(TN/4).
// EPI: 0=alpha(f32), 1=bias(f32), 2=bias+res(f32), 3=bias+gelu->planes, 4=bias->planes.
// MOE: 0 dense/batched, 1 gather-A/compact-C, 2 compact-A/scatter-C.
#define DS_TN256_T3 184320   // 3 stages x 61440
#define DS_TN128_T3 163840   // 4 stages x 40960
#define DS_TN256_T2 163840   // 4 stages x 40960
#define DS_TN128_T2 122880   // 4 stages x 30720
#define DS_TN256_T1 122880   // 4 stages x 30720

__device__ __forceinline__ void ldmx4(uint32_t* r, uint32_t addr) {
    asm volatile("ldmatrix.sync.aligned.m8n8.x4.shared.b16 {%0,%1,%2,%3}, [%4];"
        : "=r"(r[0]), "=r"(r[1]), "=r"(r[2]), "=r"(r[3]) : "r"(addr));
}
__device__ __forceinline__ void mma16816(float* c, const uint32_t* a, uint32_t b0, uint32_t b1) {
    asm volatile("mma.sync.aligned.m16n8k16.row.col.f32.f16.f16.f32 "
        "{%0,%1,%2,%3}, {%4,%5,%6,%7}, {%8,%9}, {%0,%1,%2,%3};"
        : "+f"(c[0]), "+f"(c[1]), "+f"(c[2]), "+f"(c[3])
        : "r"(a[0]), "r"(a[1]), "r"(a[2]), "r"(a[3]), "r"(b0), "r"(b1));
}
__device__ __forceinline__ void cpasync16(uint32_t dst, const void* src) {
    asm volatile("cp.async.cg.shared.global [%0], [%1], 16;" :: "r"(dst), "l"(src));
}
__device__ __forceinline__ void cpasync16z(uint32_t dst, const void* src, uint32_t sz) {
    asm volatile("cp.async.cg.shared.global [%0], [%1], 16, %2;" :: "r"(dst), "l"(src), "r"(sz));
}

template<int EPI, int MOE, int TN, int TERMS>
__global__ __launch_bounds__(256, 1)
void bgemm(int M, int N, int K,
           const __half* __restrict__ Ah, const __half* __restrict__ Al, int lda,
           const __half* __restrict__ Bh, const __half* __restrict__ Bl, int ldb,
           void* __restrict__ Cv, __half* __restrict__ Clo, int ldc,
           const float* __restrict__ bias,
           const float* __restrict__ res,
           float alpha, int zdiv,
           ll sA1, ll sA2, ll sB1, ll sB2, ll sC1, ll sC2,
           ll sBz, ll sBiasZ)
{
    constexpr int WN     = TN / 4;
    constexpr int NF     = WN / 8;
    constexpr int NB16   = WN / 16;
    constexpr int APL    = (TERMS >= 2) ? 2 : 1;   // A planes in SMEM
    constexpr int BPL    = (TERMS == 3) ? 2 : 1;   // B planes in SMEM
    constexpr int STAGES = (TERMS == 3 && TN == 256) ? 3 : 4;
    constexpr uint32_t STB = 10240u * APL + (uint32_t)TN * 80u * BPL;
    constexpr uint32_t ALOFF = 10240u;
    constexpr uint32_t BHOFF = 10240u * APL;
    constexpr uint32_t BLOFF = BHOFF + (uint32_t)TN * 80u;

    int Me = M, rowbase = 0;
    ll coff = 0;
    if (MOE) {
        int z = blockIdx.z;
        Me = g_cnt[z]; rowbase = g_off[z];
        Bh += (ll)z * sBz; if (TERMS == 3) Bl += (ll)z * sBz;
        bias += (ll)z * sBiasZ;
    } else {
        int z = blockIdx.z;
        int zb = z / zdiv, zh = z - zb * zdiv;
        Ah += zb*sA1 + zh*sA2; if (TERMS >= 2) Al += zb*sA1 + zh*sA2;
        Bh += zb*sB1 + zh*sB2; if (TERMS == 3) Bl += zb*sB1 + zh*sB2;
        coff = zb*sC1 + zh*sC2;
    }
    int m0 = blockIdx.x * 128;
    if (m0 >= Me) return;
    int n0 = blockIdx.y * TN;

    __shared__ int s_row[128];
    __shared__ int s_cout[128];
    extern __shared__ __align__(16) char dsm[];
    uint32_t dbase = smem_u32(dsm);

    int tid = threadIdx.x, lane = tid & 31, wid = tid >> 5;
    int wm = wid >> 2, wn = wid & 3;

    if (tid < 128) {
        int grow = m0 + tid;
        int rid = -1, cid = -1;
        if (grow < Me) {
            if      (MOE == 1) { rid = g_tokmap[rowbase + grow]; cid = rowbase + grow; }
            else if (MOE == 2) { rid = rowbase + grow;           cid = g_outmap[rowbase + grow]; }
            else               { rid = grow;                     cid = grow; }
        }
        s_row[tid] = rid; s_cout[tid] = cid;
    }
    __syncthreads();

    float acc[4][NF][4];
    #pragma unroll
    for (int a = 0; a < 4; a++)
        #pragma unroll
        for (int b = 0; b < NF; b++)
            #pragma unroll
            for (int c = 0; c < 4; c++) acc[a][b][c] = 0.f;

    int S = K / 32;

    auto load_stage = [&](int s) {
        int c0 = s * 32;
        uint32_t base = dbase + (uint32_t)(s % STAGES) * STB;
        constexpr int CH_A = 512;
        constexpr int CH_B = TN * 4;
        constexpr int ITER = (APL*CH_A + BPL*CH_B) / 256;
        #pragma unroll
        for (int j = 0; j < ITER; j++) {
            int idx = tid + j * 256;
            if (idx < CH_A) {
                int row = idx >> 2, c = idx & 3;
                int r = s_row[row];
                ll aoff = (r >= 0) ? ((ll)r * lda + c0 + c * 8) : 0;
                cpasync16z(base + (uint32_t)(row*80 + c*16), Ah + aoff, (r>=0)?16u:0u);
            } else if (APL == 2 && idx < 2*CH_A) {
                int k2 = idx - CH_A;
                int row = k2 >> 2, c = k2 & 3;
                int r = s_row[row];
                ll aoff = (r >= 0) ? ((ll)r * lda + c0 + c * 8) : 0;
                cpasync16z(base + ALOFF + (uint32_t)(row*80 + c*16), Al + aoff, (r>=0)?16u:0u);
            } else if (idx < APL*CH_A + CH_B) {
                int k2 = idx - APL*CH_A;
                int row = k2 >> 2, c = k2 & 3;
                cpasync16(base + BHOFF + (uint32_t)(row*80 + c*16),
                          Bh + (ll)(n0 + row) * ldb + c0 + c * 8);
            } else if (BPL == 2) {
                int k2 = idx - APL*CH_A - CH_B;
                int row = k2 >> 2, c = k2 & 3;
                cpasync16(base + BLOFF + (uint32_t)(row*80 + c*16),
                          Bl + (ll)(n0 + row) * ldb + c0 + c * 8);
            }
        }
        asm volatile("cp.async.commit_group;" ::: "memory");
    };

    #pragma unroll
    for (int i = 0; i < STAGES - 1; i++) load_stage(i);

    for (int s = 0; s < S; s++) {
        if (S - s - 1 >= STAGES - 2) {
            asm volatile("cp.async.wait_group %0;" :: "n"(STAGES - 2) : "memory");
        } else {
            asm volatile("cp.async.wait_group 0;" ::: "memory");
        }
        __syncthreads();
        if (s + STAGES - 1 < S) load_stage(s + STAGES - 1);

        uint32_t base = dbase + (uint32_t)(s % STAGES) * STB;
        uint32_t Ahb = base, Alb = base + ALOFF, Bhb = base + BHOFF, Blb = base + BLOFF;

        #pragma unroll
        for (int kk = 0; kk < 2; kk++) {
            uint32_t ah[4][4], al[4][4];
            #pragma unroll
            for (int mf = 0; mf < 4; mf++) {
                uint32_t roff = (uint32_t)(((wm*64 + mf*16 + (lane & 15)) * 40
                                            + kk*16 + (lane >> 4) * 8) * 2);
                ldmx4(ah[mf], Ahb + roff);
                if (TERMS >= 2) ldmx4(al[mf], Alb + roff);
            }
            int g = lane >> 3;
            #pragma unroll
            for (int bt = 0; bt < NB16; bt++) {
                uint32_t bhf[4], blf[4];
                uint32_t roff = (uint32_t)(((wn*WN + bt*16 + (g >> 1)*8 + (lane & 7)) * 40
                                            + kk*16 + (g & 1) * 8) * 2);
                ldmx4(bhf, Bhb + roff);
                if (TERMS == 3) ldmx4(blf, Blb + roff);
                #pragma unroll
                for (int sub = 0; sub < 2; sub++) {
                    int nf = bt*2 + sub;
                    #pragma unroll
                    for (int mf = 0; mf < 4; mf++) {
                        mma16816(acc[mf][nf], ah[mf], bhf[sub*2], bhf[sub*2+1]);
                        if (TERMS >= 2)
                            mma16816(acc[mf][nf], al[mf], bhf[sub*2], bhf[sub*2+1]);
                        if (TERMS == 3)
                            mma16816(acc[mf][nf], ah[mf], blf[sub*2], blf[sub*2+1]);
                    }
                }
            }
        }
    }

    // ---------------- epilogue ----------------
    #pragma unroll
    for (int mf = 0; mf < 4; mf++) {
        int rbase = wm*64 + mf*16 + (lane >> 2);
        #pragma unroll
        for (int half = 0; half < 2; half++) {
            int rloc = rbase + half * 8;
            int cr = s_cout[rloc];
            if (cr < 0) continue;
            #pragma unroll
            for (int nf = 0; nf < NF; nf++) {
                int col = n0 + wn*WN + nf*8 + (lane & 3)*2;
                float v0 = acc[mf][nf][half*2 + 0] * alpha;
                float v1 = acc[mf][nf][half*2 + 1] * alpha;
                if (EPI >= 1) {
                    float2 bv = *(const float2*)&bias[col];
                    v0 += bv.x; v1 += bv.y;
                }
                if (EPI == 2) {
                    float2 rv = *(const float2*)(res + (ll)cr*ldc + col);
                    v0 += rv.x; v1 += rv.y;
                }
                if (EPI == 3 || EPI == 4) {
                    if (EPI == 3) {
                        v0 = 0.5f*v0*(1.f + erff(v0*0.70710678118654752f));
                        v1 = 0.5f*v1*(1.f + erff(v1*0.70710678118654752f));
                    }
                    __half h0 = __float2half(v0);
                    __half l0 = __float2half(v0 - __half2float(h0));
                    __half h1 = __float2half(v1);
                    __half l1 = __float2half(v1 - __half2float(h1));
                    __half* DH = (__half*)Cv + coff + (ll)cr * ldc + col;
                    __half* DL = Clo + coff + (ll)cr * ldc + col;
                    *(__half2*)DH = __halves2half2(h0, h1);
                    *(__half2*)DL = __halves2half2(l0, l1);
                } else {
                    *(float2*)((float*)Cv + coff + (ll)cr*ldc + col) = make_float2(v0, v1);
                }
            }
        }
    }
}

// ---------------- V transpose: qkv planes -> per-(b,h) V^T planes ----------------
__global__ void vtrans_k(const __half* __restrict__ qH, const __half* __restrict__ qL,
                         __half* __restrict__ vTH, __half* __restrict__ vTL) {
    int z = blockIdx.z; int b = z >> 3; int h = z & 7;
    int d0 = blockIdx.y * 32;
    int s0 = blockIdx.x * 32;
    __shared__ __half tH[32][33], tL[32][33];
    int tx = threadIdx.x, ty = threadIdx.y;   // 32 x 8
    #pragma unroll
    for (int i = 0; i < 4; i++) {
        int sl = ty*4 + i;
        ll src = (ll)(b*Sq + s0 + sl)*(3*Hq) + 2*Hq + h*DHq + d0 + tx;
        tH[sl][tx] = qH[src];
        tL[sl][tx] = qL[src];
    }
    __syncthreads();
    #pragma unroll
    for (int i = 0; i < 4; i++) {
        int dl = ty*4 + i;
        ll dst = ((ll)z*DHq + d0 + dl)*Sq + s0 + tx;
        vTH[dst] = tH[tx][dl];
        vTL[dst] = tL[tx][dl];
    }
}

// ---------------- small kernels ----------------
__global__ void embed_k(const int* __restrict__ ids, const float* __restrict__ emb) {
    int idx = blockIdx.x*256 + threadIdx.x;
    int t = idx / Hq, h = idx - t*Hq;
    g_x[idx] = emb[(ll)ids[t]*Hq + h];
}

__global__ void ln_k(const float* __restrict__ x, const float* __restrict__ g,
                     const float* __restrict__ b, float* __restrict__ o,
                     __half* __restrict__ oH, __half* __restrict__ oL,
                     int zero_counts) {
    int t = blockIdx.x;
    if (zero_counts && t == 0 && threadIdx.x < Eq) g_cnt[threadIdx.x] = 0;
    const float* xr = x + (ll)t*Hq;
    int tid = threadIdx.x;
    float v[4]; float s = 0.f;
    #pragma unroll
    for (int i = 0; i < 4; i++) { v[i] = xr[tid + 256*i]; s += v[i]; }
    __shared__ float red[256];
    red[tid] = s; __syncthreads();
    for (int o2 = 128; o2; o2 >>= 1) { if (tid < o2) red[tid] += red[tid+o2]; __syncthreads(); }
    float mu = red[0] * (1.f/Hq);
    __syncthreads();
    s = 0.f;
    #pragma unroll
    for (int i = 0; i < 4; i++) { float d = v[i]-mu; s += d*d; }
    red[tid] = s; __syncthreads();
    for (int o2 = 128; o2; o2 >>= 1) { if (tid < o2) red[tid] += red[tid+o2]; __syncthreads(); }
    float inv = rsqrtf(red[0]*(1.f/Hq) + 1e-5f);
    float* orow = o + (ll)t*Hq;
    __half* hr = oH + (ll)t*Hq;
    __half* lr = oL + (ll)t*Hq;
    #pragma unroll
    for (int i = 0; i < 4; i++) {
        int h = tid + 256*i;
        float y = (v[i]-mu)*inv*g[h] + b[h];
        orow[h] = y;
        __half hi = __float2half(y);
        hr[h] = hi;
        lr[h] = __float2half(y - __half2float(hi));
    }
}

__global__ void softmax_k(const float* __restrict__ sc,
                          __half* __restrict__ pH, __half* __restrict__ pL) {
    ll row = blockIdx.x;
    const float* r = sc + row*Sq;
    int tid = threadIdx.x;
    float a = r[tid], b = r[tid+256];
    __shared__ float red[256];
    red[tid] = fmaxf(a,b); __syncthreads();
    for (int o = 128; o; o >>= 1) { if (tid < o) red[tid] = fmaxf(red[tid], red[tid+o]); __syncthreads(); }
    float m = red[0]; __syncthreads();
    a = expf(a-m); b = expf(b-m);
    red[tid] = a+b; __syncthreads();
    for (int o = 128; o; o >>= 1) { if (tid < o) red[tid] += red[tid+o]; __syncthreads(); }
    float inv = 1.f/red[0];
    a *= inv; b *= inv;
    __half ha = __float2half(a), hb = __float2half(b);
    pH[row*Sq + tid]       = ha;
    pL[row*Sq + tid]       = __float2half(a - __half2float(ha));
    pH[row*Sq + tid + 256] = hb;
    pL[row*Sq + tid + 256] = __float2half(b - __half2float(hb));
}

__global__ void zero_aux_k() {
    if (threadIdx.x == 0) g_aux[0] = 0.f;
    if (threadIdx.x < DHq) g_zb[threadIdx.x] = 0.f;
}

__global__ void router_k(const float* __restrict__ n2, const float* __restrict__ rw,
                         const float* __restrict__ rb) {
    int t = blockIdx.x;
    int w = threadIdx.x >> 5, lane = threadIdx.x & 31;
    const float* xr = n2 + (ll)t*Hq;
    const float* wr = rw + (ll)w*Hq;
    float s = 0.f;
    for (int h = lane; h < Hq; h += 32) s += xr[h]*wr[h];
    #pragma unroll
    for (int o = 16; o; o >>= 1) s += __shfl_xor_sync(0xffffffffu, s, o);
    __shared__ float lg[Eq];
    if (lane == 0) lg[w] = s + rb[w];
    __syncthreads();
    if (threadIdx.x == 0) {
        int b0 = 0; float v0 = lg[0];
        for (int e = 1; e < Eq; e++) if (lg[e] > v0) { v0 = lg[e]; b0 = e; }
        int b1 = -1; float v1 = -3.4e38f;
        for (int e = 0; e < Eq; e++) { if (e == b0) continue; if (lg[e] > v1) { v1 = lg[e]; b1 = e; } }
        g_sel[2*t]   = b0;
        g_sel[2*t+1] = b1;
        atomicAdd(&g_cnt[b0], 1);
        atomicAdd(&g_cnt[b1], 1);
    }
}

// offsets + aux loss fused (1 thread)
__global__ void offsets_k() {
    int s = 0;
    float acc = 0.f;
    const float target = (float)Tq / (float)Eq;
    for (int e = 0; e < Eq; e++) {
        g_off[e] = s; g_cur[e] = s; s += g_cnt[e];
        float d = (float)g_cnt[e] - target;
        acc += d*d;
    }
    g_aux[0] += 0.01f * acc / (float)Eq;
}

__global__ void build_k() {
    int t = blockIdx.x*256 + threadIdx.x;
    if (t >= Tq) return;
    #pragma unroll
    for (int slot = 0; slot < 2; slot++) {
        int e = g_sel[2*t + slot];
        int p = atomicAdd(&g_cur[e], 1);
        g_tokmap[p] = t;
        g_outmap[p] = slot*Tq + t;
    }
}

// combine + optional hi plane emission (lm-head input after last layer)
__global__ void combine_k(__half* __restrict__ xH) {
    int idx = blockIdx.x*256 + threadIdx.x;
    float v = g_x[idx] + g_moe[idx] + g_moe[(ll)Tq*Hq + idx];
    g_x[idx] = v;
    if (xH) xH[idx] = __float2half(v);
}

__global__ void tail_k(float* __restrict__ out, ll out_size) {
    ll base = (ll)Tq * Vq;
    for (ll i = base + threadIdx.x; i < out_size; i += 256)
        out[i] = g_aux[0];
}

// ---------------- launch ----------------
static inline int cv8blocks(ll total) { return (int)((total/8 + 255) / 256); }

extern "C" void kernel_launch(void* const* d_in, const int* in_sizes, int n_in,
                              void* d_out, int out_size) {
    const int*   ids  = (const int*)  d_in[0];
    const float* emb  = (const float*)d_in[1];
    const float* ln1g = (const float*)d_in[2];
    const float* ln1b = (const float*)d_in[3];
    const float* aiw  = (const float*)d_in[4];
    const float* aib  = (const float*)d_in[5];
    const float* aow  = (const float*)d_in[6];
    const float* aob  = (const float*)d_in[7];
    const float* ln2g = (const float*)d_in[8];
    const float* ln2b = (const float*)d_in[9];
    const float* rw   = (const float*)d_in[10];
    const float* rb   = (const float*)d_in[11];
    const float* f1w  = (const float*)d_in[12];
    const float* f1b  = (const float*)d_in[13];
    const float* f2w  = (const float*)d_in[14];
    const float* f2b  = (const float*)d_in[15];
    const float* lmw  = (const float*)d_in[16];
    const float* lmb  = (const float*)d_in[17];
    float* out = (float*)d_out;

    cudaFuncSetAttribute(bgemm<4,0,256,2>, cudaFuncAttributeMaxDynamicSharedMemorySize, DS_TN256_T2);
    cudaFuncSetAttribute(bgemm<0,0,256,3>, cudaFuncAttributeMaxDynamicSharedMemorySize, DS_TN256_T3);
    cudaFuncSetAttribute(bgemm<4,0,128,3>, cudaFuncAttributeMaxDynamicSharedMemorySize, DS_TN128_T3);
    cudaFuncSetAttribute(bgemm<2,0,128,2>, cudaFuncAttributeMaxDynamicSharedMemorySize, DS_TN128_T2);
    cudaFuncSetAttribute(bgemm<3,1,256,2>, cudaFuncAttributeMaxDynamicSharedMemorySize, DS_TN256_T2);
    cudaFuncSetAttribute(bgemm<1,2,256,2>, cudaFuncAttributeMaxDynamicSharedMemorySize, DS_TN256_T2);
    cudaFuncSetAttribute(bgemm<1,0,256,1>, cudaFuncAttributeMaxDynamicSharedMemorySize, DS_TN256_T1);

    float *px, *pn, *psc, *pmoe;
    cudaGetSymbolAddress((void**)&px,   g_x);
    cudaGetSymbolAddress((void**)&pn,   g_n);
    cudaGetSymbolAddress((void**)&psc,  g_scores);
    cudaGetSymbolAddress((void**)&pmoe, g_moe);
    float* pzb; cudaGetSymbolAddress((void**)&pzb, g_zb);
    __half *winH,*woutH,*f1H,*f2H,*lmH;
    __half *nH,*nL,*qkvH,*qkvL,*vTH,*vTL,*pH,*pL,*aoH,*aoL,*xH,*hH,*hL;
    cudaGetSymbolAddress((void**)&winH,  g_winH);
    cudaGetSymbolAddress((void**)&woutH, g_woutH);
    cudaGetSymbolAddress((void**)&f1H,   g_f1H);
    cudaGetSymbolAddress((void**)&f2H,   g_f2H);
    cudaGetSymbolAddress((void**)&lmH,   g_lmH);
    cudaGetSymbolAddress((void**)&nH,    g_nH);    cudaGetSymbolAddress((void**)&nL,    g_nL);
    cudaGetSymbolAddress((void**)&qkvH,  g_qkvH);  cudaGetSymbolAddress((void**)&qkvL,  g_qkvL);
    cudaGetSymbolAddress((void**)&vTH,   g_vTH);   cudaGetSymbolAddress((void**)&vTL,   g_vTL);
    cudaGetSymbolAddress((void**)&pH,    g_pH);    cudaGetSymbolAddress((void**)&pL,    g_pL);
    cudaGetSymbolAddress((void**)&aoH,   g_aoH);   cudaGetSymbolAddress((void**)&aoL,   g_aoL);
    cudaGetSymbolAddress((void**)&xH,    g_xH);
    cudaGetSymbolAddress((void**)&hH,    g_hH);    cudaGetSymbolAddress((void**)&hL,    g_hL);

    // ---- weight conversions (hi-only: all weight GEMMs <= 2-term) ----
    cvt1_k<<<cv8blocks((ll)Lq*3*Hq*Hq),  256>>>(aiw, winH,  (ll)Lq*3*Hq*Hq);
    cvt1_k<<<cv8blocks((ll)Lq*Hq*Hq),    256>>>(aow, woutH, (ll)Lq*Hq*Hq);
    cvt1_k<<<cv8blocks((ll)Lq*Eq*Iq*Hq), 256>>>(f1w, f1H, (ll)Lq*Eq*Iq*Hq);
    cvt1_k<<<cv8blocks((ll)Lq*Eq*Hq*Iq), 256>>>(f2w, f2H, (ll)Lq*Eq*Hq*Iq);
    cvt1_k<<<cv8blocks((ll)Vq*Hq),       256>>>(lmw, lmH, (ll)Vq*Hq);

    zero_aux_k<<<1,256>>>();
    embed_k<<<(Tq*Hq)/256, 256>>>(ids, emb);

    for (int l = 0; l < Lq; l++) {
        // --- attention ---
        ln_k<<<Tq,256>>>(px, ln1g + (ll)l*Hq, ln1b + (ll)l*Hq, pn, nH, nL, 0);

        // qkv = n1 @ W_in^T + b  (2-term)
        bgemm<4,0,256,2><<<dim3(Tq/128, 3*Hq/256, 1), 256, DS_TN256_T2>>>(
            Tq, 3*Hq, Hq, nH, nL, Hq,
            winH + (ll)l*3*Hq*Hq, nullptr, Hq,
            qkvH, qkvL, 3*Hq, aib + (ll)l*3*Hq, nullptr,
            1.f, 1, 0,0,0,0,0,0, 0,0);

        // V^T planes per (b,h)
        vtrans_k<<<dim3(Sq/32, DHq/32, Bq*NHq), dim3(32,8)>>>(qkvH, qkvL, vTH, vTL);

        // scores = q @ k^T / sqrt(DH)  (3-term, batched over B*NH)
        bgemm<0,0,256,3><<<dim3(Sq/128, Sq/256, Bq*NHq), 256, DS_TN256_T3>>>(
            Sq, Sq, DHq, qkvH, qkvL, 3*Hq,
            qkvH + Hq, qkvL + Hq, 3*Hq,
            psc, nullptr, Sq, nullptr, nullptr,
            1.f/11.313708498984761f, NHq,
            (ll)Sq*3*Hq, DHq, (ll)Sq*3*Hq, DHq, (ll)NHq*Sq*Sq, (ll)Sq*Sq,
            0, 0);

        softmax_k<<<Bq*NHq*Sq, 256>>>(psc, pH, pL);

        // o = attn @ v  (3-term, batched, N=128)
        bgemm<4,0,128,3><<<dim3(Sq/128, DHq/128, Bq*NHq), 256, DS_TN128_T3>>>(
            Sq, DHq, Sq, pH, pL, Sq,
            vTH, vTL, Sq,
            aoH, aoL, Hq, pzb, nullptr,
            1.f, NHq,
            (ll)NHq*Sq*Sq, (ll)Sq*Sq, (ll)NHq*DHq*Sq, (ll)DHq*Sq,
            (ll)Sq*Hq, DHq,
            0, 0);

        // x = x + o @ W_out^T + b  (2-term)
        bgemm<2,0,128,2><<<dim3(Tq/128, Hq/128, 1), 256, DS_TN128_T2>>>(
            Tq, Hq, Hq, aoH, aoL, Hq,
            woutH + (ll)l*Hq*Hq, nullptr, Hq,
            px, nullptr, Hq, aob + (ll)l*Hq, px,
            1.f, 1, 0,0,0,0,0,0, 0,0);

        // --- MoE ---
        ln_k<<<Tq,256>>>(px, ln2g + (ll)l*Hq, ln2b + (ll)l*Hq, pn, nH, nL, 1);

        router_k<<<Tq,256>>>(pn, rw + (ll)l*Eq*Hq, rb + (ll)l*Eq);
        offsets_k<<<1,1>>>();
        build_k<<<Tq/256,256>>>();

        // fc1: gather, gelu, write hi/lo hidden planes  (2-term)
        bgemm<3,1,256,2><<<dim3(Tq/128, Iq/256, Eq), 256, DS_TN256_T2>>>(
            Tq, Iq, Hq, nH, nL, Hq,
            f1H + (ll)l*Eq*Iq*Hq, nullptr, Hq,
            hH, hL, Iq, f1b + (ll)l*Eq*Iq, nullptr,
            1.f, 1, 0,0,0,0,0,0, (ll)Iq*Hq, (ll)Iq);

        // fc2: scatter to per-slot fp32 buffers  (2-term)
        bgemm<1,2,256,2><<<dim3(Tq/128, Hq/256, Eq), 256, DS_TN256_T2>>>(
            Tq, Hq, Iq, hH, hL, Iq,
            f2H + (ll)l*Eq*Hq*Iq, nullptr, Iq,
            pmoe, nullptr, Hq, f2b + (ll)l*Eq*Hq, nullptr,
            1.f, 1, 0,0,0,0,0,0, (ll)Hq*Iq, (ll)Hq);

        // combine; on last layer also emit x hi plane for lm head
        bool last = (l == Lq - 1);
        combine_k<<<(Tq*Hq)/256, 256>>>(last ? xH : nullptr);
    }

    // lm head  (1-term: pure fp16)
    bgemm<1,0,256,1><<<dim3(Tq/128, Vq/256, 1), 256, DS_TN256_T1>>>(
        Tq, Vq, Hq, xH, nullptr, Hq, lmH, nullptr, Hq, out, nullptr, Vq,
        lmb, nullptr, 1.f, 1, 0,0,0,0,0,0, 0, 0);

    tail_k<<<1,256>>>(out, (ll)out_size);
}

// round 10
// speedup vs baseline: 4.8268x; 1.1796x over previous
#include <cuda_runtime.h>
#include <cuda_fp16.h>
#include <math.h>
#include <stdint.h>

// ---------------- problem constants ----------------
#define Bq 4
#define Sq 512
#define Hq 1024
#define Iq 4096
#define Eq 8
#define Vq 32000
#define Lq 2
#define NHq 8
#define DHq 128
#define Tq (Bq*Sq)          // 2048 tokens

typedef long long ll;

__device__ __forceinline__ uint32_t smem_u32(const void* p) {
    uint32_t a;
    asm("{ .reg .u64 t; cvta.to.shared.u64 t, %1; cvt.u32.u64 %0, t; }" : "=r"(a) : "l"(p));
    return a;
}

// ---------------- device scratch (static, no allocs) ----------------
__device__ float g_x[Tq*Hq];
__device__ float g_n[Tq*Hq];
__device__ float g_scores[Bq*NHq*Sq*Sq];
__device__ float g_moe[2*Tq*Hq];
__device__ int   g_sel[Tq*2];
__device__ int   g_cnt[Eq];
__device__ int   g_off[Eq];
__device__ int   g_cur[Eq];
__device__ int   g_tokmap[2*Tq];
__device__ int   g_outmap[2*Tq];
__device__ float g_aux[1];
__device__ float g_zb[DHq];      // zero bias
// fp16 planes
__device__ __half g_winH[Lq*3*Hq*Hq];
__device__ __half g_woutH[Lq*Hq*Hq];
__device__ __half g_f1H[(size_t)Lq*Eq*Iq*Hq];
__device__ __half g_f2H[(size_t)Lq*Eq*Hq*Iq];
__device__ __half g_lmH[(size_t)Vq*Hq];
__device__ __half g_nH[Tq*Hq],  g_nL[Tq*Hq];
__device__ __half g_qkvH[Tq*3*Hq], g_qkvL[Tq*3*Hq];
__device__ __half g_vTH[Tq*Hq], g_vTL[Tq*Hq];
__device__ __half g_pH[(size_t)Bq*NHq*Sq*Sq], g_pL[(size_t)Bq*NHq*Sq*Sq];
__device__ __half g_aoH[Tq*Hq], g_aoL[Tq*Hq];
__device__ __half g_xH[Tq*Hq];
__device__ __half g_hH[(size_t)2*Tq*Iq];

// ---------------- conversions ----------------
__global__ void cvt1_k(const float* __restrict__ src, __half* __restrict__ hi, ll total) {
    ll i = ((ll)blockIdx.x * 256 + threadIdx.x) * 8;
    if (i >= total) return;
    float4 a = *(const float4*)(src + i);
    float4 b = *(const float4*)(src + i + 4);
    float v[8] = {a.x, a.y, a.z, a.w, b.x, b.y, b.z, b.w};
    __align__(16) __half h[8];
    #pragma unroll
    for (int j = 0; j < 8; j++) h[j] = __float2half(v[j]);
    *(uint4*)(hi + i) = *(const uint4*)h;
}

// ---------------- HMMA fp16 split GEMM ----------------
// TERMS=3: C = Ah*Bh + Al*Bh + Ah*Bl
// TERMS=2: C = (Ah+Al)*Bh
// TERMS=1: C = Ah*Bh
// CTA tile 128xTN, BK=32, cp.async pipeline, 8 warps (2x4), warp 64x(TN/4).
// EPI: 0=alpha(f32), 1=bias(f32), 2=bias+res(f32), 3=bias+gelu->planes,
//      4=bias->planes, 5=bias+gelu->hi plane only.
// MOE: 0 dense/batched, 1 gather-A/compact-C, 2 compact-A/scatter-C.
#define DS_TN256_T3 184320   // 3 stages x 61440
#define DS_TN128_T3 163840   // 4 stages x 40960
#define DS_TN256_T2 163840   // 4 stages x 40960
#define DS_TN128_T2 122880   // 4 stages x 30720
#define DS_TN256_T1 122880   // 4 stages x 30720

__device__ __forceinline__ void ldmx4(uint32_t* r, uint32_t addr) {
    asm volatile("ldmatrix.sync.aligned.m8n8.x4.shared.b16 {%0,%1,%2,%3}, [%4];"
        : "=r"(r[0]), "=r"(r[1]), "=r"(r[2]), "=r"(r[3]) : "r"(addr));
}
__device__ __forceinline__ void mma16816(float* c, const uint32_t* a, uint32_t b0, uint32_t b1) {
    asm volatile("mma.sync.aligned.m16n8k16.row.col.f32.f16.f16.f32 "
        "{%0,%1,%2,%3}, {%4,%5,%6,%7}, {%8,%9}, {%0,%1,%2,%3};"
        : "+f"(c[0]), "+f"(c[1]), "+f"(c[2]), "+f"(c[3])
        : "r"(a[0]), "r"(a[1]), "r"(a[2]), "r"(a[3]), "r"(b0), "r"(b1));
}
__device__ __forceinline__ void cpasync16(uint32_t dst, const void* src) {
    asm volatile("cp.async.cg.shared.global [%0], [%1], 16;" :: "r"(dst), "l"(src));
}
__device__ __forceinline__ void cpasync16z(uint32_t dst, const void* src, uint32_t sz) {
    asm volatile("cp.async.cg.shared.global [%0], [%1], 16, %2;" :: "r"(dst), "l"(src), "r"(sz));
}

template<int EPI, int MOE, int TN, int TERMS>
__global__ __launch_bounds__(256, 1)
void bgemm(int M, int N, int K,
           const __half* __restrict__ Ah, const __half* __restrict__ Al, int lda,
           const __half* __restrict__ Bh, const __half* __restrict__ Bl, int ldb,
           void* __restrict__ Cv, __half* __restrict__ Clo, int ldc,
           const float* __restrict__ bias,
           const float* __restrict__ res,
           float alpha, int zdiv,
           ll sA1, ll sA2, ll sB1, ll sB2, ll sC1, ll sC2,
           ll sBz, ll sBiasZ)
{
    constexpr int WN     = TN / 4;
    constexpr int NF     = WN / 8;
    constexpr int NB16   = WN / 16;
    constexpr int APL    = (TERMS >= 2) ? 2 : 1;   // A planes in SMEM
    constexpr int BPL    = (TERMS == 3) ? 2 : 1;   // B planes in SMEM
    constexpr int STAGES = (TERMS == 3 && TN == 256) ? 3 : 4;
    constexpr uint32_t STB = 10240u * APL + (uint32_t)TN * 80u * BPL;
    constexpr uint32_t ALOFF = 10240u;
    constexpr uint32_t BHOFF = 10240u * APL;
    constexpr uint32_t BLOFF = BHOFF + (uint32_t)TN * 80u;

    int Me = M, rowbase = 0;
    ll coff = 0;
    if (MOE) {
        int z = blockIdx.z;
        Me = g_cnt[z]; rowbase = g_off[z];
        Bh += (ll)z * sBz; if (TERMS == 3) Bl += (ll)z * sBz;
        bias += (ll)z * sBiasZ;
    } else {
        int z = blockIdx.z;
        int zb = z / zdiv, zh = z - zb * zdiv;
        Ah += zb*sA1 + zh*sA2; if (TERMS >= 2) Al += zb*sA1 + zh*sA2;
        Bh += zb*sB1 + zh*sB2; if (TERMS == 3) Bl += zb*sB1 + zh*sB2;
        coff = zb*sC1 + zh*sC2;
    }
    int m0 = blockIdx.x * 128;
    if (m0 >= Me) return;
    int n0 = blockIdx.y * TN;

    __shared__ int s_row[128];
    __shared__ int s_cout[128];
    extern __shared__ __align__(16) char dsm[];
    uint32_t dbase = smem_u32(dsm);

    int tid = threadIdx.x, lane = tid & 31, wid = tid >> 5;
    int wm = wid >> 2, wn = wid & 3;

    if (tid < 128) {
        int grow = m0 + tid;
        int rid = -1, cid = -1;
        if (grow < Me) {
            if      (MOE == 1) { rid = g_tokmap[rowbase + grow]; cid = rowbase + grow; }
            else if (MOE == 2) { rid = rowbase + grow;           cid = g_outmap[rowbase + grow]; }
            else               { rid = grow;                     cid = grow; }
        }
        s_row[tid] = rid; s_cout[tid] = cid;
    }
    __syncthreads();

    float acc[4][NF][4];
    #pragma unroll
    for (int a = 0; a < 4; a++)
        #pragma unroll
        for (int b = 0; b < NF; b++)
            #pragma unroll
            for (int c = 0; c < 4; c++) acc[a][b][c] = 0.f;

    int S = K / 32;

    auto load_stage = [&](int s) {
        int c0 = s * 32;
        uint32_t base = dbase + (uint32_t)(s % STAGES) * STB;
        constexpr int CH_A = 512;
        constexpr int CH_B = TN * 4;
        constexpr int ITER = (APL*CH_A + BPL*CH_B) / 256;
        #pragma unroll
        for (int j = 0; j < ITER; j++) {
            int idx = tid + j * 256;
            if (idx < CH_A) {
                int row = idx >> 2, c = idx & 3;
                int r = s_row[row];
                ll aoff = (r >= 0) ? ((ll)r * lda + c0 + c * 8) : 0;
                cpasync16z(base + (uint32_t)(row*80 + c*16), Ah + aoff, (r>=0)?16u:0u);
            } else if (APL == 2 && idx < 2*CH_A) {
                int k2 = idx - CH_A;
                int row = k2 >> 2, c = k2 & 3;
                int r = s_row[row];
                ll aoff = (r >= 0) ? ((ll)r * lda + c0 + c * 8) : 0;
                cpasync16z(base + ALOFF + (uint32_t)(row*80 + c*16), Al + aoff, (r>=0)?16u:0u);
            } else if (idx < APL*CH_A + CH_B) {
                int k2 = idx - APL*CH_A;
                int row = k2 >> 2, c = k2 & 3;
                cpasync16(base + BHOFF + (uint32_t)(row*80 + c*16),
                          Bh + (ll)(n0 + row) * ldb + c0 + c * 8);
            } else if (BPL == 2) {
                int k2 = idx - APL*CH_A - CH_B;
                int row = k2 >> 2, c = k2 & 3;
                cpasync16(base + BLOFF + (uint32_t)(row*80 + c*16),
                          Bl + (ll)(n0 + row) * ldb + c0 + c * 8);
            }
        }
        asm volatile("cp.async.commit_group;" ::: "memory");
    };

    #pragma unroll
    for (int i = 0; i < STAGES - 1; i++) load_stage(i);

    for (int s = 0; s < S; s++) {
        if (S - s - 1 >= STAGES - 2) {
            asm volatile("cp.async.wait_group %0;" :: "n"(STAGES - 2) : "memory");
        } else {
            asm volatile("cp.async.wait_group 0;" ::: "memory");
        }
        __syncthreads();
        if (s + STAGES - 1 < S) load_stage(s + STAGES - 1);

        uint32_t base = dbase + (uint32_t)(s % STAGES) * STB;
        uint32_t Ahb = base, Alb = base + ALOFF, Bhb = base + BHOFF, Blb = base + BLOFF;

        #pragma unroll
        for (int kk = 0; kk < 2; kk++) {
            uint32_t ah[4][4], al[4][4];
            #pragma unroll
            for (int mf = 0; mf < 4; mf++) {
                uint32_t roff = (uint32_t)(((wm*64 + mf*16 + (lane & 15)) * 40
                                            + kk*16 + (lane >> 4) * 8) * 2);
                ldmx4(ah[mf], Ahb + roff);
                if (TERMS >= 2) ldmx4(al[mf], Alb + roff);
            }
            int g = lane >> 3;
            #pragma unroll
            for (int bt = 0; bt < NB16; bt++) {
                uint32_t bhf[4], blf[4];
                uint32_t roff = (uint32_t)(((wn*WN + bt*16 + (g >> 1)*8 + (lane & 7)) * 40
                                            + kk*16 + (g & 1) * 8) * 2);
                ldmx4(bhf, Bhb + roff);
                if (TERMS == 3) ldmx4(blf, Blb + roff);
                #pragma unroll
                for (int sub = 0; sub < 2; sub++) {
                    int nf = bt*2 + sub;
                    #pragma unroll
                    for (int mf = 0; mf < 4; mf++) {
                        mma16816(acc[mf][nf], ah[mf], bhf[sub*2], bhf[sub*2+1]);
                        if (TERMS >= 2)
                            mma16816(acc[mf][nf], al[mf], bhf[sub*2], bhf[sub*2+1]);
                        if (TERMS == 3)
                            mma16816(acc[mf][nf], ah[mf], blf[sub*2], blf[sub*2+1]);
                    }
                }
            }
        }
    }

    // ---------------- epilogue ----------------
    #pragma unroll
    for (int mf = 0; mf < 4; mf++) {
        int rbase = wm*64 + mf*16 + (lane >> 2);
        #pragma unroll
        for (int half = 0; half < 2; half++) {
            int rloc = rbase + half * 8;
            int cr = s_cout[rloc];
            if (cr < 0) continue;
            #pragma unroll
            for (int nf = 0; nf < NF; nf++) {
                int col = n0 + wn*WN + nf*8 + (lane & 3)*2;
                float v0 = acc[mf][nf][half*2 + 0] * alpha;
                float v1 = acc[mf][nf][half*2 + 1] * alpha;
                if (EPI >= 1) {
                    float2 bv = *(const float2*)&bias[col];
                    v0 += bv.x; v1 += bv.y;
                }
                if (EPI == 2) {
                    float2 rv = *(const float2*)(res + (ll)cr*ldc + col);
                    v0 += rv.x; v1 += rv.y;
                }
                if (EPI == 3 || EPI == 4 || EPI == 5) {
                    if (EPI == 3 || EPI == 5) {
                        v0 = 0.5f*v0*(1.f + erff(v0*0.70710678118654752f));
                        v1 = 0.5f*v1*(1.f + erff(v1*0.70710678118654752f));
                    }
                    __half h0 = __float2half(v0);
                    __half h1 = __float2half(v1);
                    __half* DH = (__half*)Cv + coff + (ll)cr * ldc + col;
                    *(__half2*)DH = __halves2half2(h0, h1);
                    if (EPI != 5) {
                        __half l0 = __float2half(v0 - __half2float(h0));
                        __half l1 = __float2half(v1 - __half2float(h1));
                        __half* DL = Clo + coff + (ll)cr * ldc + col;
                        *(__half2*)DL = __halves2half2(l0, l1);
                    }
                } else {
                    *(float2*)((float*)Cv + coff + (ll)cr*ldc + col) = make_float2(v0, v1);
                }
            }
        }
    }
}

// ---------------- V transpose: qkv planes -> per-(b,h) V^T planes ----------------
__global__ void vtrans_k(const __half* __restrict__ qH, const __half* __restrict__ qL,
                         __half* __restrict__ vTH, __half* __restrict__ vTL) {
    int z = blockIdx.z; int b = z >> 3; int h = z & 7;
    int d0 = blockIdx.y * 32;
    int s0 = blockIdx.x * 32;
    __shared__ __half tH[32][33], tL[32][33];
    int tx = threadIdx.x, ty = threadIdx.y;   // 32 x 8
    #pragma unroll
    for (int i = 0; i < 4; i++) {
        int sl = ty*4 + i;
        ll src = (ll)(b*Sq + s0 + sl)*(3*Hq) + 2*Hq + h*DHq + d0 + tx;
        tH[sl][tx] = qH[src];
        tL[sl][tx] = qL[src];
    }
    __syncthreads();
    #pragma unroll
    for (int i = 0; i < 4; i++) {
        int dl = ty*4 + i;
        ll dst = ((ll)z*DHq + d0 + dl)*Sq + s0 + tx;
        vTH[dst] = tH[tx][dl];
        vTL[dst] = tL[tx][dl];
    }
}

// ---------------- small kernels ----------------
__global__ void embed_k(const int* __restrict__ ids, const float* __restrict__ emb) {
    int idx = blockIdx.x*256 + threadIdx.x;
    int t = idx / Hq, h = idx - t*Hq;
    g_x[idx] = emb[(ll)ids[t]*Hq + h];
}

__global__ void ln_k(const float* __restrict__ x, const float* __restrict__ g,
                     const float* __restrict__ b, float* __restrict__ o,
                     __half* __restrict__ oH, __half* __restrict__ oL,
                     int zero_counts) {
    int t = blockIdx.x;
    if (zero_counts && t == 0 && threadIdx.x < Eq) g_cnt[threadIdx.x] = 0;
    const float* xr = x + (ll)t*Hq;
    int tid = threadIdx.x;
    float v[4]; float s = 0.f;
    #pragma unroll
    for (int i = 0; i < 4; i++) { v[i] = xr[tid + 256*i]; s += v[i]; }
    __shared__ float red[256];
    red[tid] = s; __syncthreads();
    for (int o2 = 128; o2; o2 >>= 1) { if (tid < o2) red[tid] += red[tid+o2]; __syncthreads(); }
    float mu = red[0] * (1.f/Hq);
    __syncthreads();
    s = 0.f;
    #pragma unroll
    for (int i = 0; i < 4; i++) { float d = v[i]-mu; s += d*d; }
    red[tid] = s; __syncthreads();
    for (int o2 = 128; o2; o2 >>= 1) { if (tid < o2) red[tid] += red[tid+o2]; __syncthreads(); }
    float inv = rsqrtf(red[0]*(1.f/Hq) + 1e-5f);
    float* orow = o + (ll)t*Hq;
    __half* hr = oH + (ll)t*Hq;
    __half* lr = oL + (ll)t*Hq;
    #pragma unroll
    for (int i = 0; i < 4; i++) {
        int h = tid + 256*i;
        float y = (v[i]-mu)*inv*g[h] + b[h];
        orow[h] = y;
        __half hi = __float2half(y);
        hr[h] = hi;
        lr[h] = __float2half(y - __half2float(hi));
    }
}

__global__ void softmax_k(const float* __restrict__ sc,
                          __half* __restrict__ pH, __half* __restrict__ pL) {
    ll row = blockIdx.x;
    const float* r = sc + row*Sq;
    int tid = threadIdx.x;
    float a = r[tid], b = r[tid+256];
    __shared__ float red[256];
    red[tid] = fmaxf(a,b); __syncthreads();
    for (int o = 128; o; o >>= 1) { if (tid < o) red[tid] = fmaxf(red[tid], red[tid+o]); __syncthreads(); }
    float m = red[0]; __syncthreads();
    a = expf(a-m); b = expf(b-m);
    red[tid] = a+b; __syncthreads();
    for (int o = 128; o; o >>= 1) { if (tid < o) red[tid] += red[tid+o]; __syncthreads(); }
    float inv = 1.f/red[0];
    a *= inv; b *= inv;
    __half ha = __float2half(a), hb = __float2half(b);
    pH[row*Sq + tid]       = ha;
    pL[row*Sq + tid]       = __float2half(a - __half2float(ha));
    pH[row*Sq + tid + 256] = hb;
    pL[row*Sq + tid + 256] = __float2half(b - __half2float(hb));
}

__global__ void zero_aux_k() {
    if (threadIdx.x == 0) g_aux[0] = 0.f;
    if (threadIdx.x < DHq) g_zb[threadIdx.x] = 0.f;
}

__global__ void router_k(const float* __restrict__ n2, const float* __restrict__ rw,
                         const float* __restrict__ rb) {
    int t = blockIdx.x;
    int w = threadIdx.x >> 5, lane = threadIdx.x & 31;
    const float* xr = n2 + (ll)t*Hq;
    const float* wr = rw + (ll)w*Hq;
    float s = 0.f;
    for (int h = lane; h < Hq; h += 32) s += xr[h]*wr[h];
    #pragma unroll
    for (int o = 16; o; o >>= 1) s += __shfl_xor_sync(0xffffffffu, s, o);
    __shared__ float lg[Eq];
    if (lane == 0) lg[w] = s + rb[w];
    __syncthreads();
    if (threadIdx.x == 0) {
        int b0 = 0; float v0 = lg[0];
        for (int e = 1; e < Eq; e++) if (lg[e] > v0) { v0 = lg[e]; b0 = e; }
        int b1 = -1; float v1 = -3.4e38f;
        for (int e = 0; e < Eq; e++) { if (e == b0) continue; if (lg[e] > v1) { v1 = lg[e]; b1 = e; } }
        g_sel[2*t]   = b0;
        g_sel[2*t+1] = b1;
        atomicAdd(&g_cnt[b0], 1);
        atomicAdd(&g_cnt[b1], 1);
    }
}

// offsets + aux loss fused (1 thread)
__global__ void offsets_k() {
    int s = 0;
    float acc = 0.f;
    const float target = (float)Tq / (float)Eq;
    for (int e = 0; e < Eq; e++) {
        g_off[e] = s; g_cur[e] = s; s += g_cnt[e];
        float d = (float)g_cnt[e] - target;
        acc += d*d;
    }
    g_aux[0] += 0.01f * acc / (float)Eq;
}

__global__ void build_k() {
    int t = blockIdx.x*256 + threadIdx.x;
    if (t >= Tq) return;
    #pragma unroll
    for (int slot = 0; slot < 2; slot++) {
        int e = g_sel[2*t + slot];
        int p = atomicAdd(&g_cur[e], 1);
        g_tokmap[p] = t;
        g_outmap[p] = slot*Tq + t;
    }
}

// combine + optional hi plane emission (lm-head input after last layer)
__global__ void combine_k(__half* __restrict__ xH) {
    int idx = blockIdx.x*256 + threadIdx.x;
    float v = g_x[idx] + g_moe[idx] + g_moe[(ll)Tq*Hq + idx];
    g_x[idx] = v;
    if (xH) xH[idx] = __float2half(v);
}

__global__ void tail_k(float* __restrict__ out, ll out_size) {
    ll base = (ll)Tq * Vq;
    for (ll i = base + threadIdx.x; i < out_size; i += 256)
        out[i] = g_aux[0];
}

// ---------------- launch ----------------
static inline int cv8blocks(ll total) { return (int)((total/8 + 255) / 256); }

extern "C" void kernel_launch(void* const* d_in, const int* in_sizes, int n_in,
                              void* d_out, int out_size) {
    const int*   ids  = (const int*)  d_in[0];
    const float* emb  = (const float*)d_in[1];
    const float* ln1g = (const float*)d_in[2];
    const float* ln1b = (const float*)d_in[3];
    const float* aiw  = (const float*)d_in[4];
    const float* aib  = (const float*)d_in[5];
    const float* aow  = (const float*)d_in[6];
    const float* aob  = (const float*)d_in[7];
    const float* ln2g = (const float*)d_in[8];
    const float* ln2b = (const float*)d_in[9];
    const float* rw   = (const float*)d_in[10];
    const float* rb   = (const float*)d_in[11];
    const float* f1w  = (const float*)d_in[12];
    const float* f1b  = (const float*)d_in[13];
    const float* f2w  = (const float*)d_in[14];
    const float* f2b  = (const float*)d_in[15];
    const float* lmw  = (const float*)d_in[16];
    const float* lmb  = (const float*)d_in[17];
    float* out = (float*)d_out;

    cudaFuncSetAttribute(bgemm<4,0,256,2>, cudaFuncAttributeMaxDynamicSharedMemorySize, DS_TN256_T2);
    cudaFuncSetAttribute(bgemm<0,0,256,3>, cudaFuncAttributeMaxDynamicSharedMemorySize, DS_TN256_T3);
    cudaFuncSetAttribute(bgemm<4,0,128,3>, cudaFuncAttributeMaxDynamicSharedMemorySize, DS_TN128_T3);
    cudaFuncSetAttribute(bgemm<2,0,128,2>, cudaFuncAttributeMaxDynamicSharedMemorySize, DS_TN128_T2);
    cudaFuncSetAttribute(bgemm<5,1,256,1>, cudaFuncAttributeMaxDynamicSharedMemorySize, DS_TN256_T1);
    cudaFuncSetAttribute(bgemm<1,2,256,1>, cudaFuncAttributeMaxDynamicSharedMemorySize, DS_TN256_T1);
    cudaFuncSetAttribute(bgemm<1,0,256,1>, cudaFuncAttributeMaxDynamicSharedMemorySize, DS_TN256_T1);

    float *px, *pn, *psc, *pmoe;
    cudaGetSymbolAddress((void**)&px,   g_x);
    cudaGetSymbolAddress((void**)&pn,   g_n);
    cudaGetSymbolAddress((void**)&psc,  g_scores);
    cudaGetSymbolAddress((void**)&pmoe, g_moe);
    float* pzb; cudaGetSymbolAddress((void**)&pzb, g_zb);
    __half *winH,*woutH,*f1H,*f2H,*lmH;
    __half *nH,*nL,*qkvH,*qkvL,*vTH,*vTL,*pH,*pL,*aoH,*aoL,*xH,*hH;
    cudaGetSymbolAddress((void**)&winH,  g_winH);
    cudaGetSymbolAddress((void**)&woutH, g_woutH);
    cudaGetSymbolAddress((void**)&f1H,   g_f1H);
    cudaGetSymbolAddress((void**)&f2H,   g_f2H);
    cudaGetSymbolAddress((void**)&lmH,   g_lmH);
    cudaGetSymbolAddress((void**)&nH,    g_nH);    cudaGetSymbolAddress((void**)&nL,    g_nL);
    cudaGetSymbolAddress((void**)&qkvH,  g_qkvH);  cudaGetSymbolAddress((void**)&qkvL,  g_qkvL);
    cudaGetSymbolAddress((void**)&vTH,   g_vTH);   cudaGetSymbolAddress((void**)&vTL,   g_vTL);
    cudaGetSymbolAddress((void**)&pH,    g_pH);    cudaGetSymbolAddress((void**)&pL,    g_pL);
    cudaGetSymbolAddress((void**)&aoH,   g_aoH);   cudaGetSymbolAddress((void**)&aoL,   g_aoL);
    cudaGetSymbolAddress((void**)&xH,    g_xH);
    cudaGetSymbolAddress((void**)&hH,    g_hH);

    // ---- weight conversions (hi-only) ----
    cvt1_k<<<cv8blocks((ll)Lq*3*Hq*Hq),  256>>>(aiw, winH,  (ll)Lq*3*Hq*Hq);
    cvt1_k<<<cv8blocks((ll)Lq*Hq*Hq),    256>>>(aow, woutH, (ll)Lq*Hq*Hq);
    cvt1_k<<<cv8blocks((ll)Lq*Eq*Iq*Hq), 256>>>(f1w, f1H, (ll)Lq*Eq*Iq*Hq);
    cvt1_k<<<cv8blocks((ll)Lq*Eq*Hq*Iq), 256>>>(f2w, f2H, (ll)Lq*Eq*Hq*Iq);
    cvt1_k<<<cv8blocks((ll)Vq*Hq),       256>>>(lmw, lmH, (ll)Vq*Hq);

    zero_aux_k<<<1,256>>>();
    embed_k<<<(Tq*Hq)/256, 256>>>(ids, emb);

    for (int l = 0; l < Lq; l++) {
        // --- attention ---
        ln_k<<<Tq,256>>>(px, ln1g + (ll)l*Hq, ln1b + (ll)l*Hq, pn, nH, nL, 0);

        // qkv = n1 @ W_in^T + b  (2-term)
        bgemm<4,0,256,2><<<dim3(Tq/128, 3*Hq/256, 1), 256, DS_TN256_T2>>>(
            Tq, 3*Hq, Hq, nH, nL, Hq,
            winH + (ll)l*3*Hq*Hq, nullptr, Hq,
            qkvH, qkvL, 3*Hq, aib + (ll)l*3*Hq, nullptr,
            1.f, 1, 0,0,0,0,0,0, 0,0);

        // V^T planes per (b,h)
        vtrans_k<<<dim3(Sq/32, DHq/32, Bq*NHq), dim3(32,8)>>>(qkvH, qkvL, vTH, vTL);

        // scores = q @ k^T / sqrt(DH)  (3-term, batched over B*NH)
        bgemm<0,0,256,3><<<dim3(Sq/128, Sq/256, Bq*NHq), 256, DS_TN256_T3>>>(
            Sq, Sq, DHq, qkvH, qkvL, 3*Hq,
            qkvH + Hq, qkvL + Hq, 3*Hq,
            psc, nullptr, Sq, nullptr, nullptr,
            1.f/11.313708498984761f, NHq,
            (ll)Sq*3*Hq, DHq, (ll)Sq*3*Hq, DHq, (ll)NHq*Sq*Sq, (ll)Sq*Sq,
            0, 0);

        softmax_k<<<Bq*NHq*Sq, 256>>>(psc, pH, pL);

        // o = attn @ v  (3-term, batched, N=128)
        bgemm<4,0,128,3><<<dim3(Sq/128, DHq/128, Bq*NHq), 256, DS_TN128_T3>>>(
            Sq, DHq, Sq, pH, pL, Sq,
            vTH, vTL, Sq,
            aoH, aoL, Hq, pzb, nullptr,
            1.f, NHq,
            (ll)NHq*Sq*Sq, (ll)Sq*Sq, (ll)NHq*DHq*Sq, (ll)DHq*Sq,
            (ll)Sq*Hq, DHq,
            0, 0);

        // x = x + o @ W_out^T + b  (2-term)
        bgemm<2,0,128,2><<<dim3(Tq/128, Hq/128, 1), 256, DS_TN128_T2>>>(
            Tq, Hq, Hq, aoH, aoL, Hq,
            woutH + (ll)l*Hq*Hq, nullptr, Hq,
            px, nullptr, Hq, aob + (ll)l*Hq, px,
            1.f, 1, 0,0,0,0,0,0, 0,0);

        // --- MoE ---
        ln_k<<<Tq,256>>>(px, ln2g + (ll)l*Hq, ln2b + (ll)l*Hq, pn, nH, nL, 1);

        router_k<<<Tq,256>>>(pn, rw + (ll)l*Eq*Hq, rb + (ll)l*Eq);
        offsets_k<<<1,1>>>();
        build_k<<<Tq/256,256>>>();

        // fc1: gather, gelu, write hi-plane hidden  (1-term)
        bgemm<5,1,256,1><<<dim3(Tq/128, Iq/256, Eq), 256, DS_TN256_T1>>>(
            Tq, Iq, Hq, nH, nullptr, Hq,
            f1H + (ll)l*Eq*Iq*Hq, nullptr, Hq,
            hH, nullptr, Iq, f1b + (ll)l*Eq*Iq, nullptr,
            1.f, 1, 0,0,0,0,0,0, (ll)Iq*Hq, (ll)Iq);

        // fc2: scatter to per-slot fp32 buffers  (1-term)
        bgemm<1,2,256,1><<<dim3(Tq/128, Hq/256, Eq), 256, DS_TN256_T1>>>(
            Tq, Hq, Iq, hH, nullptr, Iq,
            f2H + (ll)l*Eq*Hq*Iq, nullptr, Iq,
            pmoe, nullptr, Hq, f2b + (ll)l*Eq*Hq, nullptr,
            1.f, 1, 0,0,0,0,0,0, (ll)Hq*Iq, (ll)Hq);

        // combine; on last layer also emit x hi plane for lm head
        bool last = (l == Lq - 1);
        combine_k<<<(Tq*Hq)/256, 256>>>(last ? xH : nullptr);
    }

    // lm head  (1-term: pure fp16)
    bgemm<1,0,256,1><<<dim3(Tq/128, Vq/256, 1), 256, DS_TN256_T1>>>(
        Tq, Vq, Hq, xH, nullptr, Hq, lmH, nullptr, Hq, out, nullptr, Vq,
        lmb, nullptr, 1.f, 1, 0,0,0,0,0,0, 0, 0);

    tail_k<<<1,256>>>(out, (ll)out_size);
}

// round 11
// speedup vs baseline: 5.3169x; 1.1016x over previous
#include <cuda_runtime.h>
#include <cuda_fp16.h>
#include <math.h>
#include <stdint.h>

// ---------------- problem constants ----------------
#define Bq 4
#define Sq 512
#define Hq 1024
#define Iq 4096
#define Eq 8
#define Vq 32000
#define Lq 2
#define NHq 8
#define DHq 128
#define Tq (Bq*Sq)          // 2048 tokens

typedef long long ll;

__device__ __forceinline__ uint32_t smem_u32(const void* p) {
    uint32_t a;
    asm("{ .reg .u64 t; cvta.to.shared.u64 t, %1; cvt.u32.u64 %0, t; }" : "=r"(a) : "l"(p));
    return a;
}

// ---------------- device scratch (static, no allocs) ----------------
__device__ float g_x[Tq*Hq];
__device__ float g_n[Tq*Hq];
__device__ float g_scores[Bq*NHq*Sq*Sq];
__device__ float g_moe[2*Tq*Hq];
__device__ int   g_sel[Tq*2];
__device__ int   g_cnt[Eq];
__device__ int   g_off[Eq];
__device__ int   g_cur[Eq];
__device__ int   g_tokmap[2*Tq];
__device__ int   g_outmap[2*Tq];
__device__ float g_aux[1];
__device__ float g_zb[DHq];      // zero bias
// fp16 planes
__device__ __half g_winH[Lq*3*Hq*Hq];
__device__ __half g_woutH[Lq*Hq*Hq];
__device__ __half g_f1H[(size_t)Lq*Eq*Iq*Hq];
__device__ __half g_f2H[(size_t)Lq*Eq*Hq*Iq];
__device__ __half g_lmH[(size_t)Vq*Hq];
__device__ __half g_nH[Tq*Hq],  g_nL[Tq*Hq];
__device__ __half g_qkvH[Tq*3*Hq], g_qkvL[Tq*3*Hq];
__device__ __half g_vTH[Tq*Hq];
__device__ __half g_pH[(size_t)Bq*NHq*Sq*Sq], g_pL[(size_t)Bq*NHq*Sq*Sq];
__device__ __half g_aoH[Tq*Hq], g_aoL[Tq*Hq];
__device__ __half g_xH[Tq*Hq];
__device__ __half g_hH[(size_t)2*Tq*Iq];

// ---------------- conversions ----------------
__global__ void cvt1_k(const float* __restrict__ src, __half* __restrict__ hi, ll total) {
    ll i = ((ll)blockIdx.x * 256 + threadIdx.x) * 8;
    if (i >= total) return;
    float4 a = *(const float4*)(src + i);
    float4 b = *(const float4*)(src + i + 4);
    float v[8] = {a.x, a.y, a.z, a.w, b.x, b.y, b.z, b.w};
    __align__(16) __half h[8];
    #pragma unroll
    for (int j = 0; j < 8; j++) h[j] = __float2half(v[j]);
    *(uint4*)(hi + i) = *(const uint4*)h;
}

// ---------------- HMMA fp16 split GEMM ----------------
// TERMS=3: C = Ah*Bh + Al*Bh + Ah*Bl
// TERMS=2: C = (Ah+Al)*Bh
// TERMS=1: C = Ah*Bh
// CTA tile 128xTN, K-slice BKT (32 or 64), cp.async pipeline, 8 warps (2x4).
// EPI: 0=alpha(f32), 1=bias(f32), 2=bias+res(f32), 3=bias+gelu->planes,
//      4=bias->planes, 5=bias+gelu->hi plane only.
// MOE: 0 dense/batched, 1 gather-A/compact-C, 2 compact-A/scatter-C.
#define DS_T3_256 184320     // 3 stages x 61440                (TERMS=3, TN=256, BK=32)
#define DS_T2_256 163840     // 4 stages x 40960                (TERMS=2, TN=256, BK=32)
#define DS_T2_128 122880     // 4 stages x 30720                (TERMS=2, TN=128, BK=32)
#define DS_T1_256_64 221184  // 4 stages x 55296                (TERMS=1, TN=256, BK=64)

__device__ __forceinline__ void ldmx4(uint32_t* r, uint32_t addr) {
    asm volatile("ldmatrix.sync.aligned.m8n8.x4.shared.b16 {%0,%1,%2,%3}, [%4];"
        : "=r"(r[0]), "=r"(r[1]), "=r"(r[2]), "=r"(r[3]) : "r"(addr));
}
__device__ __forceinline__ void mma16816(float* c, const uint32_t* a, uint32_t b0, uint32_t b1) {
    asm volatile("mma.sync.aligned.m16n8k16.row.col.f32.f16.f16.f32 "
        "{%0,%1,%2,%3}, {%4,%5,%6,%7}, {%8,%9}, {%0,%1,%2,%3};"
        : "+f"(c[0]), "+f"(c[1]), "+f"(c[2]), "+f"(c[3])
        : "r"(a[0]), "r"(a[1]), "r"(a[2]), "r"(a[3]), "r"(b0), "r"(b1));
}
__device__ __forceinline__ void cpasync16(uint32_t dst, const void* src) {
    asm volatile("cp.async.cg.shared.global [%0], [%1], 16;" :: "r"(dst), "l"(src));
}
__device__ __forceinline__ void cpasync16z(uint32_t dst, const void* src, uint32_t sz) {
    asm volatile("cp.async.cg.shared.global [%0], [%1], 16, %2;" :: "r"(dst), "l"(src), "r"(sz));
}

template<int EPI, int MOE, int TN, int TERMS, int BKT>
__global__ __launch_bounds__(256, 1)
void bgemm(int M, int N, int K,
           const __half* __restrict__ Ah, const __half* __restrict__ Al, int lda,
           const __half* __restrict__ Bh, const __half* __restrict__ Bl, int ldb,
           void* __restrict__ Cv, __half* __restrict__ Clo, int ldc,
           const float* __restrict__ bias,
           const float* __restrict__ res,
           float alpha, int zdiv,
           ll sA1, ll sA2, ll sB1, ll sB2, ll sC1, ll sC2,
           ll sBz, ll sBiasZ)
{
    constexpr int WN     = TN / 4;
    constexpr int NF     = WN / 8;
    constexpr int NB16   = WN / 16;
    constexpr int APL    = (TERMS >= 2) ? 2 : 1;   // A planes in SMEM
    constexpr int BPL    = (TERMS == 3) ? 2 : 1;   // B planes in SMEM
    constexpr int STAGES = (TERMS == 3 && TN == 256) ? 3 : 4;
    constexpr int RSH    = BKT + 8;                // row stride in halves
    constexpr uint32_t APB = 128u * RSH * 2u;      // bytes per A plane
    constexpr uint32_t BPB = (uint32_t)TN * RSH * 2u;
    constexpr uint32_t STB = APB * APL + BPB * BPL;
    constexpr uint32_t ALOFF = APB;
    constexpr uint32_t BHOFF = APB * APL;
    constexpr uint32_t BLOFF = BHOFF + BPB;

    int Me = M, rowbase = 0;
    ll coff = 0;
    if (MOE) {
        int z = blockIdx.z;
        Me = g_cnt[z]; rowbase = g_off[z];
        Bh += (ll)z * sBz; if (TERMS == 3) Bl += (ll)z * sBz;
        bias += (ll)z * sBiasZ;
    } else {
        int z = blockIdx.z;
        int zb = z / zdiv, zh = z - zb * zdiv;
        Ah += zb*sA1 + zh*sA2; if (TERMS >= 2) Al += zb*sA1 + zh*sA2;
        Bh += zb*sB1 + zh*sB2; if (TERMS == 3) Bl += zb*sB1 + zh*sB2;
        coff = zb*sC1 + zh*sC2;
    }
    int m0 = blockIdx.x * 128;
    if (m0 >= Me) return;
    int n0 = blockIdx.y * TN;

    __shared__ int s_row[128];
    __shared__ int s_cout[128];
    extern __shared__ __align__(16) char dsm[];
    uint32_t dbase = smem_u32(dsm);

    int tid = threadIdx.x, lane = tid & 31, wid = tid >> 5;
    int wm = wid >> 2, wn = wid & 3;

    if (tid < 128) {
        int grow = m0 + tid;
        int rid = -1, cid = -1;
        if (grow < Me) {
            if      (MOE == 1) { rid = g_tokmap[rowbase + grow]; cid = rowbase + grow; }
            else if (MOE == 2) { rid = rowbase + grow;           cid = g_outmap[rowbase + grow]; }
            else               { rid = grow;                     cid = grow; }
        }
        s_row[tid] = rid; s_cout[tid] = cid;
    }
    __syncthreads();

    float acc[4][NF][4];
    #pragma unroll
    for (int a = 0; a < 4; a++)
        #pragma unroll
        for (int b = 0; b < NF; b++)
            #pragma unroll
            for (int c = 0; c < 4; c++) acc[a][b][c] = 0.f;

    int S = K / BKT;

    auto load_stage = [&](int s) {
        int c0 = s * BKT;
        uint32_t base = dbase + (uint32_t)(s % STAGES) * STB;
        constexpr int CPR  = BKT / 8;          // 16B chunks per row
        constexpr int CH_A = 128 * CPR;
        constexpr int CH_B = TN * CPR;
        constexpr int ITER = (APL*CH_A + BPL*CH_B) / 256;
        #pragma unroll
        for (int j = 0; j < ITER; j++) {
            int idx = tid + j * 256;
            if (idx < CH_A) {
                int row = idx / CPR, c = idx % CPR;
                int r = s_row[row];
                ll aoff = (r >= 0) ? ((ll)r * lda + c0 + c * 8) : 0;
                cpasync16z(base + (uint32_t)(row*(RSH*2) + c*16), Ah + aoff, (r>=0)?16u:0u);
            } else if (APL == 2 && idx < 2*CH_A) {
                int k2 = idx - CH_A;
                int row = k2 / CPR, c = k2 % CPR;
                int r = s_row[row];
                ll aoff = (r >= 0) ? ((ll)r * lda + c0 + c * 8) : 0;
                cpasync16z(base + ALOFF + (uint32_t)(row*(RSH*2) + c*16), Al + aoff, (r>=0)?16u:0u);
            } else if (idx < APL*CH_A + CH_B) {
                int k2 = idx - APL*CH_A;
                int row = k2 / CPR, c = k2 % CPR;
                cpasync16(base + BHOFF + (uint32_t)(row*(RSH*2) + c*16),
                          Bh + (ll)(n0 + row) * ldb + c0 + c * 8);
            } else if (BPL == 2) {
                int k2 = idx - APL*CH_A - CH_B;
                int row = k2 / CPR, c = k2 % CPR;
                cpasync16(base + BLOFF + (uint32_t)(row*(RSH*2) + c*16),
                          Bl + (ll)(n0 + row) * ldb + c0 + c * 8);
            }
        }
        asm volatile("cp.async.commit_group;" ::: "memory");
    };

    #pragma unroll
    for (int i = 0; i < STAGES - 1; i++) load_stage(i);

    for (int s = 0; s < S; s++) {
        if (S - s - 1 >= STAGES - 2) {
            asm volatile("cp.async.wait_group %0;" :: "n"(STAGES - 2) : "memory");
        } else {
            asm volatile("cp.async.wait_group 0;" ::: "memory");
        }
        __syncthreads();
        if (s + STAGES - 1 < S) load_stage(s + STAGES - 1);

        uint32_t base = dbase + (uint32_t)(s % STAGES) * STB;
        uint32_t Ahb = base, Alb = base + ALOFF, Bhb = base + BHOFF, Blb = base + BLOFF;

        #pragma unroll
        for (int kk = 0; kk < BKT/16; kk++) {
            uint32_t ah[4][4], al[4][4];
            #pragma unroll
            for (int mf = 0; mf < 4; mf++) {
                uint32_t roff = (uint32_t)(((wm*64 + mf*16 + (lane & 15)) * RSH
                                            + kk*16 + (lane >> 4) * 8) * 2);
                ldmx4(ah[mf], Ahb + roff);
                if (TERMS >= 2) ldmx4(al[mf], Alb + roff);
            }
            int g = lane >> 3;
            #pragma unroll
            for (int bt = 0; bt < NB16; bt++) {
                uint32_t bhf[4], blf[4];
                uint32_t roff = (uint32_t)(((wn*WN + bt*16 + (g >> 1)*8 + (lane & 7)) * RSH
                                            + kk*16 + (g & 1) * 8) * 2);
                ldmx4(bhf, Bhb + roff);
                if (TERMS == 3) ldmx4(blf, Blb + roff);
                #pragma unroll
                for (int sub = 0; sub < 2; sub++) {
                    int nf = bt*2 + sub;
                    #pragma unroll
                    for (int mf = 0; mf < 4; mf++) {
                        mma16816(acc[mf][nf], ah[mf], bhf[sub*2], bhf[sub*2+1]);
                        if (TERMS >= 2)
                            mma16816(acc[mf][nf], al[mf], bhf[sub*2], bhf[sub*2+1]);
                        if (TERMS == 3)
                            mma16816(acc[mf][nf], ah[mf], blf[sub*2], blf[sub*2+1]);
                    }
                }
            }
        }
    }

    // ---------------- epilogue ----------------
    #pragma unroll
    for (int mf = 0; mf < 4; mf++) {
        int rbase = wm*64 + mf*16 + (lane >> 2);
        #pragma unroll
        for (int half = 0; half < 2; half++) {
            int rloc = rbase + half * 8;
            int cr = s_cout[rloc];
            if (cr < 0) continue;
            #pragma unroll
            for (int nf = 0; nf < NF; nf++) {
                int col = n0 + wn*WN + nf*8 + (lane & 3)*2;
                float v0 = acc[mf][nf][half*2 + 0] * alpha;
                float v1 = acc[mf][nf][half*2 + 1] * alpha;
                if (EPI >= 1) {
                    float2 bv = *(const float2*)&bias[col];
                    v0 += bv.x; v1 += bv.y;
                }
                if (EPI == 2) {
                    float2 rv = *(const float2*)(res + (ll)cr*ldc + col);
                    v0 += rv.x; v1 += rv.y;
                }
                if (EPI == 3 || EPI == 4 || EPI == 5) {
                    if (EPI == 3 || EPI == 5) {
                        v0 = 0.5f*v0*(1.f + erff(v0*0.70710678118654752f));
                        v1 = 0.5f*v1*(1.f + erff(v1*0.70710678118654752f));
                    }
                    __half h0 = __float2half(v0);
                    __half h1 = __float2half(v1);
                    __half* DH = (__half*)Cv + coff + (ll)cr * ldc + col;
                    *(__half2*)DH = __halves2half2(h0, h1);
                    if (EPI != 5) {
                        __half l0 = __float2half(v0 - __half2float(h0));
                        __half l1 = __float2half(v1 - __half2float(h1));
                        __half* DL = Clo + coff + (ll)cr * ldc + col;
                        *(__half2*)DL = __halves2half2(l0, l1);
                    }
                } else {
                    *(float2*)((float*)Cv + coff + (ll)cr*ldc + col) = make_float2(v0, v1);
                }
            }
        }
    }
}

// ---------------- V transpose: qkv hi plane -> per-(b,h) V^T hi plane ----------------
__global__ void vtrans_k(const __half* __restrict__ qH, __half* __restrict__ vTH) {
    int z = blockIdx.z; int b = z >> 3; int h = z & 7;
    int d0 = blockIdx.y * 32;
    int s0 = blockIdx.x * 32;
    __shared__ __half tH[32][33];
    int tx = threadIdx.x, ty = threadIdx.y;   // 32 x 8
    #pragma unroll
    for (int i = 0; i < 4; i++) {
        int sl = ty*4 + i;
        ll src = (ll)(b*Sq + s0 + sl)*(3*Hq) + 2*Hq + h*DHq + d0 + tx;
        tH[sl][tx] = qH[src];
    }
    __syncthreads();
    #pragma unroll
    for (int i = 0; i < 4; i++) {
        int dl = ty*4 + i;
        ll dst = ((ll)z*DHq + d0 + dl)*Sq + s0 + tx;
        vTH[dst] = tH[tx][dl];
    }
}

// ---------------- small kernels ----------------
__global__ void embed_k(const int* __restrict__ ids, const float* __restrict__ emb) {
    int idx = blockIdx.x*256 + threadIdx.x;
    int t = idx / Hq, h = idx - t*Hq;
    g_x[idx] = emb[(ll)ids[t]*Hq + h];
}

__global__ void ln_k(const float* __restrict__ x, const float* __restrict__ g,
                     const float* __restrict__ b, float* __restrict__ o,
                     __half* __restrict__ oH, __half* __restrict__ oL,
                     int zero_counts) {
    int t = blockIdx.x;
    if (zero_counts && t == 0 && threadIdx.x < Eq) g_cnt[threadIdx.x] = 0;
    const float* xr = x + (ll)t*Hq;
    int tid = threadIdx.x;
    float v[4]; float s = 0.f;
    #pragma unroll
    for (int i = 0; i < 4; i++) { v[i] = xr[tid + 256*i]; s += v[i]; }
    __shared__ float red[256];
    red[tid] = s; __syncthreads();
    for (int o2 = 128; o2; o2 >>= 1) { if (tid < o2) red[tid] += red[tid+o2]; __syncthreads(); }
    float mu = red[0] * (1.f/Hq);
    __syncthreads();
    s = 0.f;
    #pragma unroll
    for (int i = 0; i < 4; i++) { float d = v[i]-mu; s += d*d; }
    red[tid] = s; __syncthreads();
    for (int o2 = 128; o2; o2 >>= 1) { if (tid < o2) red[tid] += red[tid+o2]; __syncthreads(); }
    float inv = rsqrtf(red[0]*(1.f/Hq) + 1e-5f);
    float* orow = o + (ll)t*Hq;
    __half* hr = oH + (ll)t*Hq;
    __half* lr = oL + (ll)t*Hq;
    #pragma unroll
    for (int i = 0; i < 4; i++) {
        int h = tid + 256*i;
        float y = (v[i]-mu)*inv*g[h] + b[h];
        orow[h] = y;
        __half hi = __float2half(y);
        hr[h] = hi;
        lr[h] = __float2half(y - __half2float(hi));
    }
}

__global__ void softmax_k(const float* __restrict__ sc,
                          __half* __restrict__ pH, __half* __restrict__ pL) {
    ll row = blockIdx.x;
    const float* r = sc + row*Sq;
    int tid = threadIdx.x;
    float a = r[tid], b = r[tid+256];
    __shared__ float red[256];
    red[tid] = fmaxf(a,b); __syncthreads();
    for (int o = 128; o; o >>= 1) { if (tid < o) red[tid] = fmaxf(red[tid], red[tid+o]); __syncthreads(); }
    float m = red[0]; __syncthreads();
    a = expf(a-m); b = expf(b-m);
    red[tid] = a+b; __syncthreads();
    for (int o = 128; o; o >>= 1) { if (tid < o) red[tid] += red[tid+o]; __syncthreads(); }
    float inv = 1.f/red[0];
    a *= inv; b *= inv;
    __half ha = __float2half(a), hb = __float2half(b);
    pH[row*Sq + tid]       = ha;
    pL[row*Sq + tid]       = __float2half(a - __half2float(ha));
    pH[row*Sq + tid + 256] = hb;
    pL[row*Sq + tid + 256] = __float2half(b - __half2float(hb));
}

__global__ void zero_aux_k() {
    if (threadIdx.x == 0) g_aux[0] = 0.f;
    if (threadIdx.x < DHq) g_zb[threadIdx.x] = 0.f;
}

__global__ void router_k(const float* __restrict__ n2, const float* __restrict__ rw,
                         const float* __restrict__ rb) {
    int t = blockIdx.x;
    int w = threadIdx.x >> 5, lane = threadIdx.x & 31;
    const float* xr = n2 + (ll)t*Hq;
    const float* wr = rw + (ll)w*Hq;
    float s = 0.f;
    for (int h = lane; h < Hq; h += 32) s += xr[h]*wr[h];
    #pragma unroll
    for (int o = 16; o; o >>= 1) s += __shfl_xor_sync(0xffffffffu, s, o);
    __shared__ float lg[Eq];
    if (lane == 0) lg[w] = s + rb[w];
    __syncthreads();
    if (threadIdx.x == 0) {
        int b0 = 0; float v0 = lg[0];
        for (int e = 1; e < Eq; e++) if (lg[e] > v0) { v0 = lg[e]; b0 = e; }
        int b1 = -1; float v1 = -3.4e38f;
        for (int e = 0; e < Eq; e++) { if (e == b0) continue; if (lg[e] > v1) { v1 = lg[e]; b1 = e; } }
        g_sel[2*t]   = b0;
        g_sel[2*t+1] = b1;
        atomicAdd(&g_cnt[b0], 1);
        atomicAdd(&g_cnt[b1], 1);
    }
}

// offsets + aux loss fused (1 thread)
__global__ void offsets_k() {
    int s = 0;
    float acc = 0.f;
    const float target = (float)Tq / (float)Eq;
    for (int e = 0; e < Eq; e++) {
        g_off[e] = s; g_cur[e] = s; s += g_cnt[e];
        float d = (float)g_cnt[e] - target;
        acc += d*d;
    }
    g_aux[0] += 0.01f * acc / (float)Eq;
}

__global__ void build_k() {
    int t = blockIdx.x*256 + threadIdx.x;
    if (t >= Tq) return;
    #pragma unroll
    for (int slot = 0; slot < 2; slot++) {
        int e = g_sel[2*t + slot];
        int p = atomicAdd(&g_cur[e], 1);
        g_tokmap[p] = t;
        g_outmap[p] = slot*Tq + t;
    }
}

// combine + optional hi plane emission (lm-head input after last layer)
__global__ void combine_k(__half* __restrict__ xH) {
    int idx = blockIdx.x*256 + threadIdx.x;
    float v = g_x[idx] + g_moe[idx] + g_moe[(ll)Tq*Hq + idx];
    g_x[idx] = v;
    if (xH) xH[idx] = __float2half(v);
}

__global__ void tail_k(float* __restrict__ out, ll out_size) {
    ll base = (ll)Tq * Vq;
    for (ll i = base + threadIdx.x; i < out_size; i += 256)
        out[i] = g_aux[0];
}

// ---------------- launch ----------------
static inline int cv8blocks(ll total) { return (int)((total/8 + 255) / 256); }

extern "C" void kernel_launch(void* const* d_in, const int* in_sizes, int n_in,
                              void* d_out, int out_size) {
    const int*   ids  = (const int*)  d_in[0];
    const float* emb  = (const float*)d_in[1];
    const float* ln1g = (const float*)d_in[2];
    const float* ln1b = (const float*)d_in[3];
    const float* aiw  = (const float*)d_in[4];
    const float* aib  = (const float*)d_in[5];
    const float* aow  = (const float*)d_in[6];
    const float* aob  = (const float*)d_in[7];
    const float* ln2g = (const float*)d_in[8];
    const float* ln2b = (const float*)d_in[9];
    const float* rw   = (const float*)d_in[10];
    const float* rb   = (const float*)d_in[11];
    const float* f1w  = (const float*)d_in[12];
    const float* f1b  = (const float*)d_in[13];
    const float* f2w  = (const float*)d_in[14];
    const float* f2b  = (const float*)d_in[15];
    const float* lmw  = (const float*)d_in[16];
    const float* lmb  = (const float*)d_in[17];
    float* out = (float*)d_out;

    cudaFuncSetAttribute(bgemm<4,0,256,2,32>, cudaFuncAttributeMaxDynamicSharedMemorySize, DS_T2_256);
    cudaFuncSetAttribute(bgemm<0,0,256,2,32>, cudaFuncAttributeMaxDynamicSharedMemorySize, DS_T2_256);
    cudaFuncSetAttribute(bgemm<4,0,128,2,32>, cudaFuncAttributeMaxDynamicSharedMemorySize, DS_T2_128);
    cudaFuncSetAttribute(bgemm<2,0,128,2,32>, cudaFuncAttributeMaxDynamicSharedMemorySize, DS_T2_128);
    cudaFuncSetAttribute(bgemm<5,1,256,1,64>, cudaFuncAttributeMaxDynamicSharedMemorySize, DS_T1_256_64);
    cudaFuncSetAttribute(bgemm<1,2,256,1,64>, cudaFuncAttributeMaxDynamicSharedMemorySize, DS_T1_256_64);
    cudaFuncSetAttribute(bgemm<1,0,256,1,64>, cudaFuncAttributeMaxDynamicSharedMemorySize, DS_T1_256_64);

    float *px, *pn, *psc, *pmoe;
    cudaGetSymbolAddress((void**)&px,   g_x);
    cudaGetSymbolAddress((void**)&pn,   g_n);
    cudaGetSymbolAddress((void**)&psc,  g_scores);
    cudaGetSymbolAddress((void**)&pmoe, g_moe);
    float* pzb; cudaGetSymbolAddress((void**)&pzb, g_zb);
    __half *winH,*woutH,*f1H,*f2H,*lmH;
    __half *nH,*nL,*qkvH,*qkvL,*vTH,*pH,*pL,*aoH,*aoL,*xH,*hH;
    cudaGetSymbolAddress((void**)&winH,  g_winH);
    cudaGetSymbolAddress((void**)&woutH, g_woutH);
    cudaGetSymbolAddress((void**)&f1H,   g_f1H);
    cudaGetSymbolAddress((void**)&f2H,   g_f2H);
    cudaGetSymbolAddress((void**)&lmH,   g_lmH);
    cudaGetSymbolAddress((void**)&nH,    g_nH);    cudaGetSymbolAddress((void**)&nL,    g_nL);
    cudaGetSymbolAddress((void**)&qkvH,  g_qkvH);  cudaGetSymbolAddress((void**)&qkvL,  g_qkvL);
    cudaGetSymbolAddress((void**)&vTH,   g_vTH);
    cudaGetSymbolAddress((void**)&pH,    g_pH);    cudaGetSymbolAddress((void**)&pL,    g_pL);
    cudaGetSymbolAddress((void**)&aoH,   g_aoH);   cudaGetSymbolAddress((void**)&aoL,   g_aoL);
    cudaGetSymbolAddress((void**)&xH,    g_xH);
    cudaGetSymbolAddress((void**)&hH,    g_hH);

    // ---- weight conversions (hi-only) ----
    cvt1_k<<<cv8blocks((ll)Lq*3*Hq*Hq),  256>>>(aiw, winH,  (ll)Lq*3*Hq*Hq);
    cvt1_k<<<cv8blocks((ll)Lq*Hq*Hq),    256>>>(aow, woutH, (ll)Lq*Hq*Hq);
    cvt1_k<<<cv8blocks((ll)Lq*Eq*Iq*Hq), 256>>>(f1w, f1H, (ll)Lq*Eq*Iq*Hq);
    cvt1_k<<<cv8blocks((ll)Lq*Eq*Hq*Iq), 256>>>(f2w, f2H, (ll)Lq*Eq*Hq*Iq);
    cvt1_k<<<cv8blocks((ll)Vq*Hq),       256>>>(lmw, lmH, (ll)Vq*Hq);

    zero_aux_k<<<1,256>>>();
    embed_k<<<(Tq*Hq)/256, 256>>>(ids, emb);

    for (int l = 0; l < Lq; l++) {
        // --- attention ---
        ln_k<<<Tq,256>>>(px, ln1g + (ll)l*Hq, ln1b + (ll)l*Hq, pn, nH, nL, 0);

        // qkv = n1 @ W_in^T + b  (2-term)
        bgemm<4,0,256,2,32><<<dim3(Tq/128, 3*Hq/256, 1), 256, DS_T2_256>>>(
            Tq, 3*Hq, Hq, nH, nL, Hq,
            winH + (ll)l*3*Hq*Hq, nullptr, Hq,
            qkvH, qkvL, 3*Hq, aib + (ll)l*3*Hq, nullptr,
            1.f, 1, 0,0,0,0,0,0, 0,0);

        // V^T hi plane per (b,h)
        vtrans_k<<<dim3(Sq/32, DHq/32, Bq*NHq), dim3(32,8)>>>(qkvH, vTH);

        // scores = q @ k^T / sqrt(DH)  (2-term: Q hi+lo x K hi, batched)
        bgemm<0,0,256,2,32><<<dim3(Sq/128, Sq/256, Bq*NHq), 256, DS_T2_256>>>(
            Sq, Sq, DHq, qkvH, qkvL, 3*Hq,
            qkvH + Hq, nullptr, 3*Hq,
            psc, nullptr, Sq, nullptr, nullptr,
            1.f/11.313708498984761f, NHq,
            (ll)Sq*3*Hq, DHq, (ll)Sq*3*Hq, DHq, (ll)NHq*Sq*Sq, (ll)Sq*Sq,
            0, 0);

        softmax_k<<<Bq*NHq*Sq, 256>>>(psc, pH, pL);

        // o = attn @ v  (2-term: probs hi+lo x V hi, batched, N=128)
        bgemm<4,0,128,2,32><<<dim3(Sq/128, DHq/128, Bq*NHq), 256, DS_T2_128>>>(
            Sq, DHq, Sq, pH, pL, Sq,
            vTH, nullptr, Sq,
            aoH, aoL, Hq, pzb, nullptr,
            1.f, NHq,
            (ll)NHq*Sq*Sq, (ll)Sq*Sq, (ll)NHq*DHq*Sq, (ll)DHq*Sq,
            (ll)Sq*Hq, DHq,
            0, 0);

        // x = x + o @ W_out^T + b  (2-term)
        bgemm<2,0,128,2,32><<<dim3(Tq/128, Hq/128, 1), 256, DS_T2_128>>>(
            Tq, Hq, Hq, aoH, aoL, Hq,
            woutH + (ll)l*Hq*Hq, nullptr, Hq,
            px, nullptr, Hq, aob + (ll)l*Hq, px,
            1.f, 1, 0,0,0,0,0,0, 0,0);

        // --- MoE ---
        ln_k<<<Tq,256>>>(px, ln2g + (ll)l*Hq, ln2b + (ll)l*Hq, pn, nH, nL, 1);

        router_k<<<Tq,256>>>(pn, rw + (ll)l*Eq*Hq, rb + (ll)l*Eq);
        offsets_k<<<1,1>>>();
        build_k<<<Tq/256,256>>>();

        // fc1: gather, gelu, write hi-plane hidden  (1-term, BK=64)
        bgemm<5,1,256,1,64><<<dim3(Tq/128, Iq/256, Eq), 256, DS_T1_256_64>>>(
            Tq, Iq, Hq, nH, nullptr, Hq,
            f1H + (ll)l*Eq*Iq*Hq, nullptr, Hq,
            hH, nullptr, Iq, f1b + (ll)l*Eq*Iq, nullptr,
            1.f, 1, 0,0,0,0,0,0, (ll)Iq*Hq, (ll)Iq);

        // fc2: scatter to per-slot fp32 buffers  (1-term, BK=64)
        bgemm<1,2,256,1,64><<<dim3(Tq/128, Hq/256, Eq), 256, DS_T1_256_64>>>(
            Tq, Hq, Iq, hH, nullptr, Iq,
            f2H + (ll)l*Eq*Hq*Iq, nullptr, Iq,
            pmoe, nullptr, Hq, f2b + (ll)l*Eq*Hq, nullptr,
            1.f, 1, 0,0,0,0,0,0, (ll)Hq*Iq, (ll)Hq);

        // combine; on last layer also emit x hi plane for lm head
        bool last = (l == Lq - 1);
        combine_k<<<(Tq*Hq)/256, 256>>>(last ? xH : nullptr);
    }

    // lm head  (1-term, BK=64)
    bgemm<1,0,256,1,64><<<dim3(Tq/128, Vq/256, 1), 256, DS_T1_256_64>>>(
        Tq, Vq, Hq, xH, nullptr, Hq, lmH, nullptr, Hq, out, nullptr, Vq,
        lmb, nullptr, 1.f, 1, 0,0,0,0,0,0, 0, 0);

    tail_k<<<1,256>>>(out, (ll)out_size);
}

// round 13
// speedup vs baseline: 5.6386x; 1.0605x over previous
#include <cuda_runtime.h>
#include <cuda_fp16.h>
#include <math.h>
#include <stdint.h>

// ---------------- problem constants ----------------
#define Bq 4
#define Sq 512
#define Hq 1024
#define Iq 4096
#define Eq 8
#define Vq 32000
#define Lq 2
#define NHq 8
#define DHq 128
#define Tq (Bq*Sq)          // 2048 tokens

typedef long long ll;

__device__ __forceinline__ uint32_t smem_u32(const void* p) {
    uint32_t a;
    asm("{ .reg .u64 t; cvta.to.shared.u64 t, %1; cvt.u32.u64 %0, t; }" : "=r"(a) : "l"(p));
    return a;
}

// ---------------- device scratch (static, no allocs) ----------------
__device__ float g_x[Tq*Hq];
__device__ float g_n[Tq*Hq];
__device__ float g_scores[Bq*NHq*Sq*Sq];
__device__ float g_moe[2*Tq*Hq];
__device__ int   g_sel[Tq*2];
__device__ int   g_cnt[Eq];
__device__ int   g_off[Eq];
__device__ int   g_cur[Eq];
__device__ int   g_tokmap[2*Tq];
__device__ int   g_outmap[2*Tq];
__device__ float g_aux[1];
__device__ float g_zb[DHq];      // zero bias
// fp16 planes
__device__ __half g_winH[Lq*3*Hq*Hq];
__device__ __half g_woutH[Lq*Hq*Hq];
__device__ __half g_f1H[(size_t)Lq*Eq*Iq*Hq];
__device__ __half g_f2H[(size_t)Lq*Eq*Hq*Iq];
__device__ __half g_lmH[(size_t)Vq*Hq];
__device__ __half g_nH[Tq*Hq];
__device__ __half g_qkvH[Tq*3*Hq], g_qkvL[Tq*3*Hq];
__device__ __half g_vTH[Tq*Hq];
__device__ __half g_pH[(size_t)Bq*NHq*Sq*Sq], g_pL[(size_t)Bq*NHq*Sq*Sq];
__device__ __half g_aoH[Tq*Hq], g_aoL[Tq*Hq];
__device__ __half g_xH[Tq*Hq];
__device__ __half g_hH[(size_t)2*Tq*Iq];

// ---------------- conversions ----------------
__global__ void cvt1_k(const float* __restrict__ src, __half* __restrict__ hi, ll total) {
    ll i = ((ll)blockIdx.x * 256 + threadIdx.x) * 8;
    if (i >= total) return;
    float4 a = *(const float4*)(src + i);
    float4 b = *(const float4*)(src + i + 4);
    float v[8] = {a.x, a.y, a.z, a.w, b.x, b.y, b.z, b.w};
    __align__(16) __half h[8];
    #pragma unroll
    for (int j = 0; j < 8; j++) h[j] = __float2half(v[j]);
    *(uint4*)(hi + i) = *(const uint4*)h;
}

// ---------------- HMMA fp16 split GEMM ----------------
// TERMS=3: C = Ah*Bh + Al*Bh + Ah*Bl   TERMS=2: C = (Ah+Al)*Bh   TERMS=1: C = Ah*Bh
// CTA tile 128xTN, K-slice BKT (32/64), 4-stage cp.async pipeline, 8 warps (2x4).
// EPI: 0=alpha(f32), 1=bias(f32), 2=bias+res(f32), 3=bias+gelu->hi/lo planes,
//      4=bias->hi/lo planes, 5=bias+gelu->hi only.
// MOE: 0 dense/batched, 1 gather-A/compact-C, 2 compact-A/scatter-C.
#define DS_T2_256 163840     // 4 stages x 40960  (TERMS=2, TN=256, BK=32)
#define DS_T2_128 122880     // 4 stages x 30720  (TERMS=2, TN=128, BK=32)
#define DS_T1_256_64 221184  // 4 stages x 55296  (TERMS=1, TN=256, BK=64)

__device__ __forceinline__ void ldmx4(uint32_t* r, uint32_t addr) {
    asm volatile("ldmatrix.sync.aligned.m8n8.x4.shared.b16 {%0,%1,%2,%3}, [%4];"
        : "=r"(r[0]), "=r"(r[1]), "=r"(r[2]), "=r"(r[3]) : "r"(addr));
}
__device__ __forceinline__ void mma16816(float* c, const uint32_t* a, uint32_t b0, uint32_t b1) {
    asm volatile("mma.sync.aligned.m16n8k16.row.col.f32.f16.f16.f32 "
        "{%0,%1,%2,%3}, {%4,%5,%6,%7}, {%8,%9}, {%0,%1,%2,%3};"
        : "+f"(c[0]), "+f"(c[1]), "+f"(c[2]), "+f"(c[3])
        : "r"(a[0]), "r"(a[1]), "r"(a[2]), "r"(a[3]), "r"(b0), "r"(b1));
}
__device__ __forceinline__ void cpasync16(uint32_t dst, const void* src) {
    asm volatile("cp.async.cg.shared.global [%0], [%1], 16;" :: "r"(dst), "l"(src));
}
__device__ __forceinline__ void cpasync16z(uint32_t dst, const void* src, uint32_t sz) {
    asm volatile("cp.async.cg.shared.global [%0], [%1], 16, %2;" :: "r"(dst), "l"(src), "r"(sz));
}

template<int EPI, int MOE, int TN, int TERMS, int BKT>
__global__ __launch_bounds__(256, 1)
void bgemm(int M, int N, int K,
           const __half* __restrict__ Ah, const __half* __restrict__ Al, int lda,
           const __half* __restrict__ Bh, const __half* __restrict__ Bl, int ldb,
           void* __restrict__ Cv, __half* __restrict__ Clo, int ldc,
           const float* __restrict__ bias,
           const float* __restrict__ res,
           float alpha, int zdiv,
           ll sA1, ll sA2, ll sB1, ll sB2, ll sC1, ll sC2,
           ll sBz, ll sBiasZ)
{
    constexpr int WN     = TN / 4;
    constexpr int NF     = WN / 8;
    constexpr int NB16   = WN / 16;
    constexpr int APL    = (TERMS >= 2) ? 2 : 1;
    constexpr int BPL    = (TERMS == 3) ? 2 : 1;
    constexpr int STAGES = 4;
    constexpr int RSH    = BKT + 8;                // row stride in halves
    constexpr uint32_t APB = 128u * RSH * 2u;
    constexpr uint32_t BPB = (uint32_t)TN * RSH * 2u;
    constexpr uint32_t STB = APB * APL + BPB * BPL;
    constexpr uint32_t ALOFF = APB;
    constexpr uint32_t BHOFF = APB * APL;
    constexpr uint32_t BLOFF = BHOFF + BPB;

    int Me = M, rowbase = 0;
    ll coff = 0;
    if (MOE) {
        int z = blockIdx.z;
        Me = g_cnt[z]; rowbase = g_off[z];
        Bh += (ll)z * sBz; if (TERMS == 3) Bl += (ll)z * sBz;
        bias += (ll)z * sBiasZ;
    } else {
        int z = blockIdx.z;
        int zb = z / zdiv, zh = z - zb * zdiv;
        Ah += zb*sA1 + zh*sA2; if (TERMS >= 2) Al += zb*sA1 + zh*sA2;
        Bh += zb*sB1 + zh*sB2; if (TERMS == 3) Bl += zb*sB1 + zh*sB2;
        coff = zb*sC1 + zh*sC2;
    }
    int m0 = blockIdx.x * 128;
    if (m0 >= Me) return;
    int n0 = blockIdx.y * TN;

    __shared__ int s_row[128];
    __shared__ int s_cout[128];
    extern __shared__ __align__(16) char dsm[];
    uint32_t dbase = smem_u32(dsm);

    int tid = threadIdx.x, lane = tid & 31, wid = tid >> 5;
    int wm = wid >> 2, wn = wid & 3;

    if (tid < 128) {
        int grow = m0 + tid;
        int rid = -1, cid = -1;
        if (grow < Me) {
            if      (MOE == 1) { rid = g_tokmap[rowbase + grow]; cid = rowbase + grow; }
            else if (MOE == 2) { rid = rowbase + grow;           cid = g_outmap[rowbase + grow]; }
            else               { rid = grow;                     cid = grow; }
        }
        s_row[tid] = rid; s_cout[tid] = cid;
    }
    __syncthreads();

    float acc[4][NF][4];
    #pragma unroll
    for (int a = 0; a < 4; a++)
        #pragma unroll
        for (int b = 0; b < NF; b++)
            #pragma unroll
            for (int c = 0; c < 4; c++) acc[a][b][c] = 0.f;

    int S = K / BKT;

    auto load_stage = [&](int s) {
        int c0 = s * BKT;
        uint32_t base = dbase + (uint32_t)(s % STAGES) * STB;
        constexpr int CPR  = BKT / 8;
        constexpr int CH_A = 128 * CPR;
        constexpr int CH_B = TN * CPR;
        constexpr int ITER = (APL*CH_A + BPL*CH_B) / 256;
        #pragma unroll
        for (int j = 0; j < ITER; j++) {
            int idx = tid + j * 256;
            if (idx < CH_A) {
                int row = idx / CPR, c = idx % CPR;
                int r = s_row[row];
                ll aoff = (r >= 0) ? ((ll)r * lda + c0 + c * 8) : 0;
                cpasync16z(base + (uint32_t)(row*(RSH*2) + c*16), Ah + aoff, (r>=0)?16u:0u);
            } else if (APL == 2 && idx < 2*CH_A) {
                int k2 = idx - CH_A;
                int row = k2 / CPR, c = k2 % CPR;
                int r = s_row[row];
                ll aoff = (r >= 0) ? ((ll)r * lda + c0 + c * 8) : 0;
                cpasync16z(base + ALOFF + (uint32_t)(row*(RSH*2) + c*16), Al + aoff, (r>=0)?16u:0u);
            } else if (idx < APL*CH_A + CH_B) {
                int k2 = idx - APL*CH_A;
                int row = k2 / CPR, c = k2 % CPR;
                cpasync16(base + BHOFF + (uint32_t)(row*(RSH*2) + c*16),
                          Bh + (ll)(n0 + row) * ldb + c0 + c * 8);
            } else if (BPL == 2) {
                int k2 = idx - APL*CH_A - CH_B;
                int row = k2 / CPR, c = k2 % CPR;
                cpasync16(base + BLOFF + (uint32_t)(row*(RSH*2) + c*16),
                          Bl + (ll)(n0 + row) * ldb + c0 + c * 8);
            }
        }
        asm volatile("cp.async.commit_group;" ::: "memory");
    };

    #pragma unroll
    for (int i = 0; i < STAGES - 1; i++) load_stage(i);

    for (int s = 0; s < S; s++) {
        if (S - s - 1 >= STAGES - 2) {
            asm volatile("cp.async.wait_group %0;" :: "n"(STAGES - 2) : "memory");
        } else {
            asm volatile("cp.async.wait_group 0;" ::: "memory");
        }
        __syncthreads();
        if (s + STAGES - 1 < S) load_stage(s + STAGES - 1);

        uint32_t base = dbase + (uint32_t)(s % STAGES) * STB;
        uint32_t Ahb = base, Alb = base + ALOFF, Bhb = base + BHOFF, Blb = base + BLOFF;

        #pragma unroll
        for (int kk = 0; kk < BKT/16; kk++) {
            uint32_t ah[4][4], al[4][4];
            #pragma unroll
            for (int mf = 0; mf < 4; mf++) {
                uint32_t roff = (uint32_t)(((wm*64 + mf*16 + (lane & 15)) * RSH
                                            + kk*16 + (lane >> 4) * 8) * 2);
                ldmx4(ah[mf], Ahb + roff);
                if (TERMS >= 2) ldmx4(al[mf], Alb + roff);
            }
            int g = lane >> 3;
            #pragma unroll
            for (int bt = 0; bt < NB16; bt++) {
                uint32_t bhf[4], blf[4];
                uint32_t roff = (uint32_t)(((wn*WN + bt*16 + (g >> 1)*8 + (lane & 7)) * RSH
                                            + kk*16 + (g & 1) * 8) * 2);
                ldmx4(bhf, Bhb + roff);
                if (TERMS == 3) ldmx4(blf, Blb + roff);
                #pragma unroll
                for (int sub = 0; sub < 2; sub++) {
                    int nf = bt*2 + sub;
                    #pragma unroll
                    for (int mf = 0; mf < 4; mf++) {
                        mma16816(acc[mf][nf], ah[mf], bhf[sub*2], bhf[sub*2+1]);
                        if (TERMS >= 2)
                            mma16816(acc[mf][nf], al[mf], bhf[sub*2], bhf[sub*2+1]);
                        if (TERMS == 3)
                            mma16816(acc[mf][nf], ah[mf], blf[sub*2], blf[sub*2+1]);
                    }
                }
            }
        }
    }

    // ---------------- epilogue ----------------
    #pragma unroll
    for (int mf = 0; mf < 4; mf++) {
        int rbase = wm*64 + mf*16 + (lane >> 2);
        #pragma unroll
        for (int half = 0; half < 2; half++) {
            int rloc = rbase + half * 8;
            int cr = s_cout[rloc];
            if (cr < 0) continue;
            #pragma unroll
            for (int nf = 0; nf < NF; nf++) {
                int col = n0 + wn*WN + nf*8 + (lane & 3)*2;
                float v0 = acc[mf][nf][half*2 + 0] * alpha;
                float v1 = acc[mf][nf][half*2 + 1] * alpha;
                if (EPI >= 1) {
                    float2 bv = *(const float2*)&bias[col];
                    v0 += bv.x; v1 += bv.y;
                }
                if (EPI == 2) {
                    float2 rv = *(const float2*)(res + (ll)cr*ldc + col);
                    v0 += rv.x; v1 += rv.y;
                }
                if (EPI >= 3) {
                    if (EPI == 3 || EPI == 5) {
                        v0 = 0.5f*v0*(1.f + erff(v0*0.70710678118654752f));
                        v1 = 0.5f*v1*(1.f + erff(v1*0.70710678118654752f));
                    }
                    __half h0 = __float2half(v0);
                    __half h1 = __float2half(v1);
                    __half* DH = (__half*)Cv + coff + (ll)cr * ldc + col;
                    *(__half2*)DH = __halves2half2(h0, h1);
                    if (EPI == 3 || EPI == 4) {
                        __half l0 = __float2half(v0 - __half2float(h0));
                        __half l1 = __float2half(v1 - __half2float(h1));
                        __half* DL = Clo + coff + (ll)cr * ldc + col;
                        *(__half2*)DL = __halves2half2(l0, l1);
                    }
                } else {
                    *(float2*)((float*)Cv + coff + (ll)cr*ldc + col) = make_float2(v0, v1);
                }
            }
        }
    }
}

// ---------------- V transpose: qkv hi plane -> per-(b,h) V^T hi plane ----------------
__global__ void vtrans_k(const __half* __restrict__ qH, __half* __restrict__ vTH) {
    int z = blockIdx.z; int b = z >> 3; int h = z & 7;
    int d0 = blockIdx.y * 32;
    int s0 = blockIdx.x * 32;
    __shared__ __half tH[32][33];
    int tx = threadIdx.x, ty = threadIdx.y;   // 32 x 8
    #pragma unroll
    for (int i = 0; i < 4; i++) {
        int sl = ty*4 + i;
        ll src = (ll)(b*Sq + s0 + sl)*(3*Hq) + 2*Hq + h*DHq + d0 + tx;
        tH[sl][tx] = qH[src];
    }
    __syncthreads();
    #pragma unroll
    for (int i = 0; i < 4; i++) {
        int dl = ty*4 + i;
        ll dst = ((ll)z*DHq + d0 + dl)*Sq + s0 + tx;
        vTH[dst] = tH[tx][dl];
    }
}

// ---------------- small kernels ----------------
__global__ void embed_k(const int* __restrict__ ids, const float* __restrict__ emb) {
    int idx = blockIdx.x*256 + threadIdx.x;
    int t = idx / Hq, h = idx - t*Hq;
    g_x[idx] = emb[(ll)ids[t]*Hq + h];
}

// LayerNorm: emits fp16 hi plane always; fp32 output + cnt-zeroing optional
__global__ void ln_k(const float* __restrict__ x, const float* __restrict__ g,
                     const float* __restrict__ b, float* __restrict__ o,
                     __half* __restrict__ oH, int flags) {
    int t = blockIdx.x;
    if ((flags & 2) && t == 0 && threadIdx.x < Eq) g_cnt[threadIdx.x] = 0;
    const float* xr = x + (ll)t*Hq;
    int tid = threadIdx.x;
    float v[4]; float s = 0.f;
    #pragma unroll
    for (int i = 0; i < 4; i++) { v[i] = xr[tid + 256*i]; s += v[i]; }
    __shared__ float red[256];
    red[tid] = s; __syncthreads();
    for (int o2 = 128; o2; o2 >>= 1) { if (tid < o2) red[tid] += red[tid+o2]; __syncthreads(); }
    float mu = red[0] * (1.f/Hq);
    __syncthreads();
    s = 0.f;
    #pragma unroll
    for (int i = 0; i < 4; i++) { float d = v[i]-mu; s += d*d; }
    red[tid] = s; __syncthreads();
    for (int o2 = 128; o2; o2 >>= 1) { if (tid < o2) red[tid] += red[tid+o2]; __syncthreads(); }
    float inv = rsqrtf(red[0]*(1.f/Hq) + 1e-5f);
    float* orow = o + (ll)t*Hq;
    __half* hr = oH + (ll)t*Hq;
    #pragma unroll
    for (int i = 0; i < 4; i++) {
        int h = tid + 256*i;
        float y = (v[i]-mu)*inv*g[h] + b[h];
        if (flags & 1) orow[h] = y;
        hr[h] = __float2half(y);
    }
}

__global__ void softmax_k(const float* __restrict__ sc,
                          __half* __restrict__ pH, __half* __restrict__ pL) {
    ll row = blockIdx.x;
    const float* r = sc + row*Sq;
    int tid = threadIdx.x;
    float a = r[tid], b = r[tid+256];
    __shared__ float red[256];
    red[tid] = fmaxf(a,b); __syncthreads();
    for (int o = 128; o; o >>= 1) { if (tid < o) red[tid] = fmaxf(red[tid], red[tid+o]); __syncthreads(); }
    float m = red[0]; __syncthreads();
    a = expf(a-m); b = expf(b-m);
    red[tid] = a+b; __syncthreads();
    for (int o = 128; o; o >>= 1) { if (tid < o) red[tid] += red[tid+o]; __syncthreads(); }
    float inv = 1.f/red[0];
    a *= inv; b *= inv;
    __half ha = __float2half(a), hb = __float2half(b);
    pH[row*Sq + tid]       = ha;
    pL[row*Sq + tid]       = __float2half(a - __half2float(ha));
    pH[row*Sq + tid + 256] = hb;
    pL[row*Sq + tid + 256] = __float2half(b - __half2float(hb));
}

__global__ void zero_aux_k() {
    if (threadIdx.x == 0) g_aux[0] = 0.f;
    if (threadIdx.x < DHq) g_zb[threadIdx.x] = 0.f;
}

__global__ void router_k(const float* __restrict__ n2, const float* __restrict__ rw,
                         const float* __restrict__ rb) {
    int t = blockIdx.x;
    int w = threadIdx.x >> 5, lane = threadIdx.x & 31;
    const float* xr = n2 + (ll)t*Hq;
    const float* wr = rw + (ll)w*Hq;
    float s = 0.f;
    for (int h = lane; h < Hq; h += 32) s += xr[h]*wr[h];
    #pragma unroll
    for (int o = 16; o; o >>= 1) s += __shfl_xor_sync(0xffffffffu, s, o);
    __shared__ float lg[Eq];
    if (lane == 0) lg[w] = s + rb[w];
    __syncthreads();
    if (threadIdx.x == 0) {
        int b0 = 0; float v0 = lg[0];
        for (int e = 1; e < Eq; e++) if (lg[e] > v0) { v0 = lg[e]; b0 = e; }
        int b1 = -1; float v1 = -3.4e38f;
        for (int e = 0; e < Eq; e++) { if (e == b0) continue; if (lg[e] > v1) { v1 = lg[e]; b1 = e; } }
        g_sel[2*t]   = b0;
        g_sel[2*t+1] = b1;
        atomicAdd(&g_cnt[b0], 1);
        atomicAdd(&g_cnt[b1], 1);
    }
}

// offsets + aux loss fused (1 thread)
__global__ void offsets_k() {
    int s = 0;
    float acc = 0.f;
    const float target = (float)Tq / (float)Eq;
    for (int e = 0; e < Eq; e++) {
        g_off[e] = s; g_cur[e] = s; s += g_cnt[e];
        float d = (float)g_cnt[e] - target;
        acc += d*d;
    }
    g_aux[0] += 0.01f * acc / (float)Eq;
}

__global__ void build_k() {
    int t = blockIdx.x*256 + threadIdx.x;
    if (t >= Tq) return;
    #pragma unroll
    for (int slot = 0; slot < 2; slot++) {
        int e = g_sel[2*t + slot];
        int p = atomicAdd(&g_cur[e], 1);
        g_tokmap[p] = t;
        g_outmap[p] = slot*Tq + t;
    }
}

// combine + optional hi plane emission (lm-head input after last layer)
__global__ void combine_k(__half* __restrict__ xH) {
    int idx = blockIdx.x*256 + threadIdx.x;
    float v = g_x[idx] + g_moe[idx] + g_moe[(ll)Tq*Hq + idx];
    g_x[idx] = v;
    if (xH) xH[idx] = __float2half(v);
}

__global__ void tail_k(float* __restrict__ out, ll out_size) {
    ll base = (ll)Tq * Vq;
    for (ll i = base + threadIdx.x; i < out_size; i += 256)
        out[i] = g_aux[0];
}

// ---------------- launch ----------------
static inline int cv8blocks(ll total) { return (int)((total/8 + 255) / 256); }

extern "C" void kernel_launch(void* const* d_in, const int* in_sizes, int n_in,
                              void* d_out, int out_size) {
    const int*   ids  = (const int*)  d_in[0];
    const float* emb  = (const float*)d_in[1];
    const float* ln1g = (const float*)d_in[2];
    const float* ln1b = (const float*)d_in[3];
    const float* aiw  = (const float*)d_in[4];
    const float* aib  = (const float*)d_in[5];
    const float* aow  = (const float*)d_in[6];
    const float* aob  = (const float*)d_in[7];
    const float* ln2g = (const float*)d_in[8];
    const float* ln2b = (const float*)d_in[9];
    const float* rw   = (const float*)d_in[10];
    const float* rb   = (const float*)d_in[11];
    const float* f1w  = (const float*)d_in[12];
    const float* f1b  = (const float*)d_in[13];
    const float* f2w  = (const float*)d_in[14];
    const float* f2b  = (const float*)d_in[15];
    const float* lmw  = (const float*)d_in[16];
    const float* lmb  = (const float*)d_in[17];
    float* out = (float*)d_out;

    cudaFuncSetAttribute(bgemm<4,0,256,1,64>, cudaFuncAttributeMaxDynamicSharedMemorySize, DS_T1_256_64);
    cudaFuncSetAttribute(bgemm<0,0,256,2,32>, cudaFuncAttributeMaxDynamicSharedMemorySize, DS_T2_256);
    cudaFuncSetAttribute(bgemm<4,0,128,2,32>, cudaFuncAttributeMaxDynamicSharedMemorySize, DS_T2_128);
    cudaFuncSetAttribute(bgemm<2,0,128,2,32>, cudaFuncAttributeMaxDynamicSharedMemorySize, DS_T2_128);
    cudaFuncSetAttribute(bgemm<5,1,256,1,64>, cudaFuncAttributeMaxDynamicSharedMemorySize, DS_T1_256_64);
    cudaFuncSetAttribute(bgemm<1,2,256,1,64>, cudaFuncAttributeMaxDynamicSharedMemorySize, DS_T1_256_64);
    cudaFuncSetAttribute(bgemm<1,0,256,1,64>, cudaFuncAttributeMaxDynamicSharedMemorySize, DS_T1_256_64);

    float *px, *pn, *psc, *pmoe;
    cudaGetSymbolAddress((void**)&px,   g_x);
    cudaGetSymbolAddress((void**)&pn,   g_n);
    cudaGetSymbolAddress((void**)&psc,  g_scores);
    cudaGetSymbolAddress((void**)&pmoe, g_moe);
    float* pzb; cudaGetSymbolAddress((void**)&pzb, g_zb);
    __half *winH,*woutH,*f1H,*f2H,*lmH;
    __half *nH,*qkvH,*qkvL,*vTH,*pH,*pL,*aoH,*aoL,*xH,*hH;
    cudaGetSymbolAddress((void**)&winH,  g_winH);
    cudaGetSymbolAddress((void**)&woutH, g_woutH);
    cudaGetSymbolAddress((void**)&f1H,   g_f1H);
    cudaGetSymbolAddress((void**)&f2H,   g_f2H);
    cudaGetSymbolAddress((void**)&lmH,   g_lmH);
    cudaGetSymbolAddress((void**)&nH,    g_nH);
    cudaGetSymbolAddress((void**)&qkvH,  g_qkvH);  cudaGetSymbolAddress((void**)&qkvL,  g_qkvL);
    cudaGetSymbolAddress((void**)&vTH,   g_vTH);
    cudaGetSymbolAddress((void**)&pH,    g_pH);    cudaGetSymbolAddress((void**)&pL,    g_pL);
    cudaGetSymbolAddress((void**)&aoH,   g_aoH);   cudaGetSymbolAddress((void**)&aoL,   g_aoL);
    cudaGetSymbolAddress((void**)&xH,    g_xH);
    cudaGetSymbolAddress((void**)&hH,    g_hH);

    // ---- weight conversions (hi-only) ----
    cvt1_k<<<cv8blocks((ll)Lq*3*Hq*Hq),  256>>>(aiw, winH,  (ll)Lq*3*Hq*Hq);
    cvt1_k<<<cv8blocks((ll)Lq*Hq*Hq),    256>>>(aow, woutH, (ll)Lq*Hq*Hq);
    cvt1_k<<<cv8blocks((ll)Lq*Eq*Iq*Hq), 256>>>(f1w, f1H, (ll)Lq*Eq*Iq*Hq);
    cvt1_k<<<cv8blocks((ll)Lq*Eq*Hq*Iq), 256>>>(f2w, f2H, (ll)Lq*Eq*Hq*Iq);
    cvt1_k<<<cv8blocks((ll)Vq*Hq),       256>>>(lmw, lmH, (ll)Vq*Hq);

    zero_aux_k<<<1,256>>>();
    embed_k<<<(Tq*Hq)/256, 256>>>(ids, emb);

    for (int l = 0; l < Lq; l++) {
        // --- attention ---
        ln_k<<<Tq,256>>>(px, ln1g + (ll)l*Hq, ln1b + (ll)l*Hq, pn, nH, 0);

        // qkv = n1 @ W_in^T + b  (1-term, BK=64) -> qkv hi/lo planes
        bgemm<4,0,256,1,64><<<dim3(Tq/128, 3*Hq/256, 1), 256, DS_T1_256_64>>>(
            Tq, 3*Hq, Hq, nH, nullptr, Hq,
            winH + (ll)l*3*Hq*Hq, nullptr, Hq,
            qkvH, qkvL, 3*Hq, aib + (ll)l*3*Hq, nullptr,
            1.f, 1, 0,0,0,0,0,0, 0,0);

        // V^T hi plane per (b,h)
        vtrans_k<<<dim3(Sq/32, DHq/32, Bq*NHq), dim3(32,8)>>>(qkvH, vTH);

        // scores = q @ k^T / sqrt(DH)  (2-term: Q hi+lo x K hi, batched)
        bgemm<0,0,256,2,32><<<dim3(Sq/128, Sq/256, Bq*NHq), 256, DS_T2_256>>>(
            Sq, Sq, DHq, qkvH, qkvL, 3*Hq,
            qkvH + Hq, nullptr, 3*Hq,
            psc, nullptr, Sq, nullptr, nullptr,
            1.f/11.313708498984761f, NHq,
            (ll)Sq*3*Hq, DHq, (ll)Sq*3*Hq, DHq, (ll)NHq*Sq*Sq, (ll)Sq*Sq,
            0, 0);

        softmax_k<<<Bq*NHq*Sq, 256>>>(psc, pH, pL);

        // o = attn @ v  (2-term: probs hi+lo x V hi, batched) -> ao hi/lo planes
        bgemm<4,0,128,2,32><<<dim3(Sq/128, DHq/128, Bq*NHq), 256, DS_T2_128>>>(
            Sq, DHq, Sq, pH, pL, Sq,
            vTH, nullptr, Sq,
            aoH, aoL, Hq, pzb, nullptr,
            1.f, NHq,
            (ll)NHq*Sq*Sq, (ll)Sq*Sq, (ll)NHq*DHq*Sq, (ll)DHq*Sq,
            (ll)Sq*Hq, DHq,
            0, 0);

        // x = x + o @ W_out^T + b  (2-term: ao hi+lo x Wout hi)
        bgemm<2,0,128,2,32><<<dim3(Tq/128, Hq/128, 1), 256, DS_T2_128>>>(
            Tq, Hq, Hq, aoH, aoL, Hq,
            woutH + (ll)l*Hq*Hq, nullptr, Hq,
            px, nullptr, Hq, aob + (ll)l*Hq, px,
            1.f, 1, 0,0,0,0,0,0, 0,0);

        // --- MoE ---
        ln_k<<<Tq,256>>>(px, ln2g + (ll)l*Hq, ln2b + (ll)l*Hq, pn, nH, 3);

        router_k<<<Tq,256>>>(pn, rw + (ll)l*Eq*Hq, rb + (ll)l*Eq);
        offsets_k<<<1,1>>>();
        build_k<<<Tq/256,256>>>();

        // fc1: gather, gelu, write hi-plane hidden  (1-term, BK=64)
        bgemm<5,1,256,1,64><<<dim3(Tq/128, Iq/256, Eq), 256, DS_T1_256_64>>>(
            Tq, Iq, Hq, nH, nullptr, Hq,
            f1H + (ll)l*Eq*Iq*Hq, nullptr, Hq,
            hH, nullptr, Iq, f1b + (ll)l*Eq*Iq, nullptr,
            1.f, 1, 0,0,0,0,0,0, (ll)Iq*Hq, (ll)Iq);

        // fc2: scatter to per-slot fp32 buffers  (1-term, BK=64)
        bgemm<1,2,256,1,64><<<dim3(Tq/128, Hq/256, Eq), 256, DS_T1_256_64>>>(
            Tq, Hq, Iq, hH, nullptr, Iq,
            f2H + (ll)l*Eq*Hq*Iq, nullptr, Iq,
            pmoe, nullptr, Hq, f2b + (ll)l*Eq*Hq, nullptr,
            1.f, 1, 0,0,0,0,0,0, (ll)Hq*Iq, (ll)Hq);

        // combine; on last layer also emit x hi plane for lm head
        bool last = (l == Lq - 1);
        combine_k<<<(Tq*Hq)/256, 256>>>(last ? xH : nullptr);
    }

    // lm head  (1-term, BK=64)
    bgemm<1,0,256,1,64><<<dim3(Tq/128, Vq/256, 1), 256, DS_T1_256_64>>>(
        Tq, Vq, Hq, xH, nullptr, Hq, lmH, nullptr, Hq, out, nullptr, Vq,
        lmb, nullptr, 1.f, 1, 0,0,0,0,0,0, 0, 0);

    tail_k<<<1,256>>>(out, (ll)out_size);
}

// round 14
// speedup vs baseline: 5.7355x; 1.0172x over previous
#include <cuda_runtime.h>
#include <cuda_fp16.h>
#include <math.h>
#include <stdint.h>

// ---------------- problem constants ----------------
#define Bq 4
#define Sq 512
#define Hq 1024
#define Iq 4096
#define Eq 8
#define Vq 32000
#define Lq 2
#define NHq 8
#define DHq 128
#define Tq (Bq*Sq)          // 2048 tokens

typedef long long ll;

__device__ __forceinline__ uint32_t smem_u32(const void* p) {
    uint32_t a;
    asm("{ .reg .u64 t; cvta.to.shared.u64 t, %1; cvt.u32.u64 %0, t; }" : "=r"(a) : "l"(p));
    return a;
}

// ---------------- device scratch (static, no allocs) ----------------
__device__ float g_x[Tq*Hq];
__device__ float g_n[Tq*Hq];
__device__ float g_scores[Bq*NHq*Sq*Sq];
__device__ float g_moe[2*Tq*Hq];
__device__ int   g_sel[Tq*2];
__device__ int   g_cnt[Eq];
__device__ int   g_off[Eq];
__device__ int   g_cur[Eq];
__device__ int   g_tokmap[2*Tq];
__device__ int   g_outmap[2*Tq];
__device__ float g_aux[1];
__device__ float g_zb[DHq];      // zero bias
// fp16 planes
__device__ __half g_winH[Lq*3*Hq*Hq];
__device__ __half g_woutH[Lq*Hq*Hq];
__device__ __half g_f1H[(size_t)Lq*Eq*Iq*Hq];
__device__ __half g_f2H[(size_t)Lq*Eq*Hq*Iq];
__device__ __half g_lmH[(size_t)Vq*Hq];
__device__ __half g_nH[Tq*Hq];
__device__ __half g_qkvH[Tq*3*Hq], g_qkvL[Tq*3*Hq];
__device__ __half g_vTH[Tq*Hq];
__device__ __half g_pH[(size_t)Bq*NHq*Sq*Sq];
__device__ __half g_aoH[Tq*Hq], g_aoL[Tq*Hq];
__device__ __half g_xH[Tq*Hq];
__device__ __half g_hH[(size_t)2*Tq*Iq];

// ---------------- conversions ----------------
__global__ void cvt1_k(const float* __restrict__ src, __half* __restrict__ hi, ll total) {
    ll i = ((ll)blockIdx.x * 256 + threadIdx.x) * 8;
    if (i >= total) return;
    float4 a = *(const float4*)(src + i);
    float4 b = *(const float4*)(src + i + 4);
    float v[8] = {a.x, a.y, a.z, a.w, b.x, b.y, b.z, b.w};
    __align__(16) __half h[8];
    #pragma unroll
    for (int j = 0; j < 8; j++) h[j] = __float2half(v[j]);
    *(uint4*)(hi + i) = *(const uint4*)h;
}

// ---------------- HMMA fp16 split GEMM ----------------
// TERMS=3: C = Ah*Bh + Al*Bh + Ah*Bl   TERMS=2: C = (Ah+Al)*Bh   TERMS=1: C = Ah*Bh
// CTA tile 128xTN, K-slice BKT (32/64), 4-stage cp.async pipeline, 8 warps (2x4).
// EPI: 0=alpha(f32), 1=bias(f32), 2=bias+res(f32), 3=bias+gelu->hi/lo planes,
//      4=bias->hi/lo planes, 5=bias+gelu->hi only.
// MOE: 0 dense/batched, 1 gather-A/compact-C, 2 compact-A/scatter-C.
#define DS_T2_256 163840     // 4 stages x 40960  (TERMS=2, TN=256, BK=32)
#define DS_T2_128 122880     // 4 stages x 30720  (TERMS=2, TN=128, BK=32)
#define DS_T1_256_32 122880  // 4 stages x 30720  (TERMS=1, TN=256, BK=32)
#define DS_T1_128_32 81920   // 4 stages x 20480  (TERMS=1, TN=128, BK=32)
#define DS_T1_256_64 221184  // 4 stages x 55296  (TERMS=1, TN=256, BK=64)

__device__ __forceinline__ void ldmx4(uint32_t* r, uint32_t addr) {
    asm volatile("ldmatrix.sync.aligned.m8n8.x4.shared.b16 {%0,%1,%2,%3}, [%4];"
        : "=r"(r[0]), "=r"(r[1]), "=r"(r[2]), "=r"(r[3]) : "r"(addr));
}
__device__ __forceinline__ void mma16816(float* c, const uint32_t* a, uint32_t b0, uint32_t b1) {
    asm volatile("mma.sync.aligned.m16n8k16.row.col.f32.f16.f16.f32 "
        "{%0,%1,%2,%3}, {%4,%5,%6,%7}, {%8,%9}, {%0,%1,%2,%3};"
        : "+f"(c[0]), "+f"(c[1]), "+f"(c[2]), "+f"(c[3])
        : "r"(a[0]), "r"(a[1]), "r"(a[2]), "r"(a[3]), "r"(b0), "r"(b1));
}
__device__ __forceinline__ void cpasync16(uint32_t dst, const void* src) {
    asm volatile("cp.async.cg.shared.global [%0], [%1], 16;" :: "r"(dst), "l"(src));
}
__device__ __forceinline__ void cpasync16z(uint32_t dst, const void* src, uint32_t sz) {
    asm volatile("cp.async.cg.shared.global [%0], [%1], 16, %2;" :: "r"(dst), "l"(src), "r"(sz));
}

template<int EPI, int MOE, int TN, int TERMS, int BKT>
__global__ __launch_bounds__(256, 1)
void bgemm(int M, int N, int K,
           const __half* __restrict__ Ah, const __half* __restrict__ Al, int lda,
           const __half* __restrict__ Bh, const __half* __restrict__ Bl, int ldb,
           void* __restrict__ Cv, __half* __restrict__ Clo, int ldc,
           const float* __restrict__ bias,
           const float* __restrict__ res,
           float alpha, int zdiv,
           ll sA1, ll sA2, ll sB1, ll sB2, ll sC1, ll sC2,
           ll sBz, ll sBiasZ)
{
    constexpr int WN     = TN / 4;
    constexpr int NF     = WN / 8;
    constexpr int NB16   = WN / 16;
    constexpr int APL    = (TERMS >= 2) ? 2 : 1;
    constexpr int BPL    = (TERMS == 3) ? 2 : 1;
    constexpr int STAGES = 4;
    constexpr int RSH    = BKT + 8;                // row stride in halves
    constexpr uint32_t APB = 128u * RSH * 2u;
    constexpr uint32_t BPB = (uint32_t)TN * RSH * 2u;
    constexpr uint32_t STB = APB * APL + BPB * BPL;
    constexpr uint32_t ALOFF = APB;
    constexpr uint32_t BHOFF = APB * APL;
    constexpr uint32_t BLOFF = BHOFF + BPB;

    int Me = M, rowbase = 0;
    ll coff = 0;
    if (MOE) {
        int z = blockIdx.z;
        Me = g_cnt[z]; rowbase = g_off[z];
        Bh += (ll)z * sBz; if (TERMS == 3) Bl += (ll)z * sBz;
        bias += (ll)z * sBiasZ;
    } else {
        int z = blockIdx.z;
        int zb = z / zdiv, zh = z - zb * zdiv;
        Ah += zb*sA1 + zh*sA2; if (TERMS >= 2) Al += zb*sA1 + zh*sA2;
        Bh += zb*sB1 + zh*sB2; if (TERMS == 3) Bl += zb*sB1 + zh*sB2;
        coff = zb*sC1 + zh*sC2;
    }
    int m0 = blockIdx.x * 128;
    if (m0 >= Me) return;
    int n0 = blockIdx.y * TN;

    __shared__ int s_row[128];
    __shared__ int s_cout[128];
    extern __shared__ __align__(16) char dsm[];
    uint32_t dbase = smem_u32(dsm);

    int tid = threadIdx.x, lane = tid & 31, wid = tid >> 5;
    int wm = wid >> 2, wn = wid & 3;

    if (tid < 128) {
        int grow = m0 + tid;
        int rid = -1, cid = -1;
        if (grow < Me) {
            if      (MOE == 1) { rid = g_tokmap[rowbase + grow]; cid = rowbase + grow; }
            else if (MOE == 2) { rid = rowbase + grow;           cid = g_outmap[rowbase + grow]; }
            else               { rid = grow;                     cid = grow; }
        }
        s_row[tid] = rid; s_cout[tid] = cid;
    }
    __syncthreads();

    float acc[4][NF][4];
    #pragma unroll
    for (int a = 0; a < 4; a++)
        #pragma unroll
        for (int b = 0; b < NF; b++)
            #pragma unroll
            for (int c = 0; c < 4; c++) acc[a][b][c] = 0.f;

    int S = K / BKT;

    auto load_stage = [&](int s) {
        int c0 = s * BKT;
        uint32_t base = dbase + (uint32_t)(s % STAGES) * STB;
        constexpr int CPR  = BKT / 8;
        constexpr int CH_A = 128 * CPR;
        constexpr int CH_B = TN * CPR;
        constexpr int ITER = (APL*CH_A + BPL*CH_B) / 256;
        #pragma unroll
        for (int j = 0; j < ITER; j++) {
            int idx = tid + j * 256;
            if (idx < CH_A) {
                int row = idx / CPR, c = idx % CPR;
                int r = s_row[row];
                ll aoff = (r >= 0) ? ((ll)r * lda + c0 + c * 8) : 0;
                cpasync16z(base + (uint32_t)(row*(RSH*2) + c*16), Ah + aoff, (r>=0)?16u:0u);
            } else if (APL == 2 && idx < 2*CH_A) {
                int k2 = idx - CH_A;
                int row = k2 / CPR, c = k2 % CPR;
                int r = s_row[row];
                ll aoff = (r >= 0) ? ((ll)r * lda + c0 + c * 8) : 0;
                cpasync16z(base + ALOFF + (uint32_t)(row*(RSH*2) + c*16), Al + aoff, (r>=0)?16u:0u);
            } else if (idx < APL*CH_A + CH_B) {
                int k2 = idx - APL*CH_A;
                int row = k2 / CPR, c = k2 % CPR;
                cpasync16(base + BHOFF + (uint32_t)(row*(RSH*2) + c*16),
                          Bh + (ll)(n0 + row) * ldb + c0 + c * 8);
            } else if (BPL == 2) {
                int k2 = idx - APL*CH_A - CH_B;
                int row = k2 / CPR, c = k2 % CPR;
                cpasync16(base + BLOFF + (uint32_t)(row*(RSH*2) + c*16),
                          Bl + (ll)(n0 + row) * ldb + c0 + c * 8);
            }
        }
        asm volatile("cp.async.commit_group;" ::: "memory");
    };

    #pragma unroll
    for (int i = 0; i < STAGES - 1; i++) load_stage(i);

    for (int s = 0; s < S; s++) {
        if (S - s - 1 >= STAGES - 2) {
            asm volatile("cp.async.wait_group %0;" :: "n"(STAGES - 2) : "memory");
        } else {
            asm volatile("cp.async.wait_group 0;" ::: "memory");
        }
        __syncthreads();
        if (s + STAGES - 1 < S) load_stage(s + STAGES - 1);

        uint32_t base = dbase + (uint32_t)(s % STAGES) * STB;
        uint32_t Ahb = base, Alb = base + ALOFF, Bhb = base + BHOFF, Blb = base + BLOFF;

        #pragma unroll
        for (int kk = 0; kk < BKT/16; kk++) {
            uint32_t ah[4][4], al[4][4];
            #pragma unroll
            for (int mf = 0; mf < 4; mf++) {
                uint32_t roff = (uint32_t)(((wm*64 + mf*16 + (lane & 15)) * RSH
                                            + kk*16 + (lane >> 4) * 8) * 2);
                ldmx4(ah[mf], Ahb + roff);
                if (TERMS >= 2) ldmx4(al[mf], Alb + roff);
            }
            int g = lane >> 3;
            #pragma unroll
            for (int bt = 0; bt < NB16; bt++) {
                uint32_t bhf[4], blf[4];
                uint32_t roff = (uint32_t)(((wn*WN + bt*16 + (g >> 1)*8 + (lane & 7)) * RSH
                                            + kk*16 + (g & 1) * 8) * 2);
                ldmx4(bhf, Bhb + roff);
                if (TERMS == 3) ldmx4(blf, Blb + roff);
                #pragma unroll
                for (int sub = 0; sub < 2; sub++) {
                    int nf = bt*2 + sub;
                    #pragma unroll
                    for (int mf = 0; mf < 4; mf++) {
                        mma16816(acc[mf][nf], ah[mf], bhf[sub*2], bhf[sub*2+1]);
                        if (TERMS >= 2)
                            mma16816(acc[mf][nf], al[mf], bhf[sub*2], bhf[sub*2+1]);
                        if (TERMS == 3)
                            mma16816(acc[mf][nf], ah[mf], blf[sub*2], blf[sub*2+1]);
                    }
                }
            }
        }
    }

    // ---------------- epilogue ----------------
    #pragma unroll
    for (int mf = 0; mf < 4; mf++) {
        int rbase = wm*64 + mf*16 + (lane >> 2);
        #pragma unroll
        for (int half = 0; half < 2; half++) {
            int rloc = rbase + half * 8;
            int cr = s_cout[rloc];
            if (cr < 0) continue;
            #pragma unroll
            for (int nf = 0; nf < NF; nf++) {
                int col = n0 + wn*WN + nf*8 + (lane & 3)*2;
                float v0 = acc[mf][nf][half*2 + 0] * alpha;
                float v1 = acc[mf][nf][half*2 + 1] * alpha;
                if (EPI >= 1) {
                    float2 bv = *(const float2*)&bias[col];
                    v0 += bv.x; v1 += bv.y;
                }
                if (EPI == 2) {
                    float2 rv = *(const float2*)(res + (ll)cr*ldc + col);
                    v0 += rv.x; v1 += rv.y;
                }
                if (EPI >= 3) {
                    if (EPI == 3 || EPI == 5) {
                        v0 = 0.5f*v0*(1.f + erff(v0*0.70710678118654752f));
                        v1 = 0.5f*v1*(1.f + erff(v1*0.70710678118654752f));
                    }
                    __half h0 = __float2half(v0);
                    __half h1 = __float2half(v1);
                    __half* DH = (__half*)Cv + coff + (ll)cr * ldc + col;
                    *(__half2*)DH = __halves2half2(h0, h1);
                    if (EPI == 3 || EPI == 4) {
                        __half l0 = __float2half(v0 - __half2float(h0));
                        __half l1 = __float2half(v1 - __half2float(h1));
                        __half* DL = Clo + coff + (ll)cr * ldc + col;
                        *(__half2*)DL = __halves2half2(l0, l1);
                    }
                } else {
                    *(float2*)((float*)Cv + coff + (ll)cr*ldc + col) = make_float2(v0, v1);
                }
            }
        }
    }
}

// ---------------- V transpose: qkv hi plane -> per-(b,h) V^T hi plane ----------------
__global__ void vtrans_k(const __half* __restrict__ qH, __half* __restrict__ vTH) {
    int z = blockIdx.z; int b = z >> 3; int h = z & 7;
    int d0 = blockIdx.y * 32;
    int s0 = blockIdx.x * 32;
    __shared__ __half tH[32][33];
    int tx = threadIdx.x, ty = threadIdx.y;   // 32 x 8
    #pragma unroll
    for (int i = 0; i < 4; i++) {
        int sl = ty*4 + i;
        ll src = (ll)(b*Sq + s0 + sl)*(3*Hq) + 2*Hq + h*DHq + d0 + tx;
        tH[sl][tx] = qH[src];
    }
    __syncthreads();
    #pragma unroll
    for (int i = 0; i < 4; i++) {
        int dl = ty*4 + i;
        ll dst = ((ll)z*DHq + d0 + dl)*Sq + s0 + tx;
        vTH[dst] = tH[tx][dl];
    }
}

// ---------------- small kernels ----------------
__global__ void embed_k(const int* __restrict__ ids, const float* __restrict__ emb) {
    int idx = blockIdx.x*256 + threadIdx.x;
    int t = idx / Hq, h = idx - t*Hq;
    g_x[idx] = emb[(ll)ids[t]*Hq + h];
}

// LayerNorm: emits fp16 hi plane always; fp32 output + cnt-zeroing optional
__global__ void ln_k(const float* __restrict__ x, const float* __restrict__ g,
                     const float* __restrict__ b, float* __restrict__ o,
                     __half* __restrict__ oH, int flags) {
    int t = blockIdx.x;
    if ((flags & 2) && t == 0 && threadIdx.x < Eq) g_cnt[threadIdx.x] = 0;
    const float* xr = x + (ll)t*Hq;
    int tid = threadIdx.x;
    float v[4]; float s = 0.f;
    #pragma unroll
    for (int i = 0; i < 4; i++) { v[i] = xr[tid + 256*i]; s += v[i]; }
    __shared__ float red[256];
    red[tid] = s; __syncthreads();
    for (int o2 = 128; o2; o2 >>= 1) { if (tid < o2) red[tid] += red[tid+o2]; __syncthreads(); }
    float mu = red[0] * (1.f/Hq);
    __syncthreads();
    s = 0.f;
    #pragma unroll
    for (int i = 0; i < 4; i++) { float d = v[i]-mu; s += d*d; }
    red[tid] = s; __syncthreads();
    for (int o2 = 128; o2; o2 >>= 1) { if (tid < o2) red[tid] += red[tid+o2]; __syncthreads(); }
    float inv = rsqrtf(red[0]*(1.f/Hq) + 1e-5f);
    float* orow = o + (ll)t*Hq;
    __half* hr = oH + (ll)t*Hq;
    #pragma unroll
    for (int i = 0; i < 4; i++) {
        int h = tid + 256*i;
        float y = (v[i]-mu)*inv*g[h] + b[h];
        if (flags & 1) orow[h] = y;
        hr[h] = __float2half(y);
    }
}

__global__ void softmax_k(const float* __restrict__ sc, __half* __restrict__ pH) {
    ll row = blockIdx.x;
    const float* r = sc + row*Sq;
    int tid = threadIdx.x;
    float a = r[tid], b = r[tid+256];
    __shared__ float red[256];
    red[tid] = fmaxf(a,b); __syncthreads();
    for (int o = 128; o; o >>= 1) { if (tid < o) red[tid] = fmaxf(red[tid], red[tid+o]); __syncthreads(); }
    float m = red[0]; __syncthreads();
    a = expf(a-m); b = expf(b-m);
    red[tid] = a+b; __syncthreads();
    for (int o = 128; o; o >>= 1) { if (tid < o) red[tid] += red[tid+o]; __syncthreads(); }
    float inv = 1.f/red[0];
    pH[row*Sq + tid]       = __float2half(a*inv);
    pH[row*Sq + tid + 256] = __float2half(b*inv);
}

__global__ void zero_aux_k() {
    if (threadIdx.x == 0) g_aux[0] = 0.f;
    if (threadIdx.x < DHq) g_zb[threadIdx.x] = 0.f;
}

__global__ void router_k(const float* __restrict__ n2, const float* __restrict__ rw,
                         const float* __restrict__ rb) {
    int t = blockIdx.x;
    int w = threadIdx.x >> 5, lane = threadIdx.x & 31;
    const float* xr = n2 + (ll)t*Hq;
    const float* wr = rw + (ll)w*Hq;
    float s = 0.f;
    for (int h = lane; h < Hq; h += 32) s += xr[h]*wr[h];
    #pragma unroll
    for (int o = 16; o; o >>= 1) s += __shfl_xor_sync(0xffffffffu, s, o);
    __shared__ float lg[Eq];
    if (lane == 0) lg[w] = s + rb[w];
    __syncthreads();
    if (threadIdx.x == 0) {
        int b0 = 0; float v0 = lg[0];
        for (int e = 1; e < Eq; e++) if (lg[e] > v0) { v0 = lg[e]; b0 = e; }
        int b1 = -1; float v1 = -3.4e38f;
        for (int e = 0; e < Eq; e++) { if (e == b0) continue; if (lg[e] > v1) { v1 = lg[e]; b1 = e; } }
        g_sel[2*t]   = b0;
        g_sel[2*t+1] = b1;
        atomicAdd(&g_cnt[b0], 1);
        atomicAdd(&g_cnt[b1], 1);
    }
}

// offsets + aux loss fused (1 thread)
__global__ void offsets_k() {
    int s = 0;
    float acc = 0.f;
    const float target = (float)Tq / (float)Eq;
    for (int e = 0; e < Eq; e++) {
        g_off[e] = s; g_cur[e] = s; s += g_cnt[e];
        float d = (float)g_cnt[e] - target;
        acc += d*d;
    }
    g_aux[0] += 0.01f * acc / (float)Eq;
}

__global__ void build_k() {
    int t = blockIdx.x*256 + threadIdx.x;
    if (t >= Tq) return;
    #pragma unroll
    for (int slot = 0; slot < 2; slot++) {
        int e = g_sel[2*t + slot];
        int p = atomicAdd(&g_cur[e], 1);
        g_tokmap[p] = t;
        g_outmap[p] = slot*Tq + t;
    }
}

// combine + optional hi plane emission (lm-head input after last layer)
__global__ void combine_k(__half* __restrict__ xH) {
    int idx = blockIdx.x*256 + threadIdx.x;
    float v = g_x[idx] + g_moe[idx] + g_moe[(ll)Tq*Hq + idx];
    g_x[idx] = v;
    if (xH) xH[idx] = __float2half(v);
}

__global__ void tail_k(float* __restrict__ out, ll out_size) {
    ll base = (ll)Tq * Vq;
    for (ll i = base + threadIdx.x; i < out_size; i += 256)
        out[i] = g_aux[0];
}

// ---------------- launch ----------------
static inline int cv8blocks(ll total) { return (int)((total/8 + 255) / 256); }

extern "C" void kernel_launch(void* const* d_in, const int* in_sizes, int n_in,
                              void* d_out, int out_size) {
    const int*   ids  = (const int*)  d_in[0];
    const float* emb  = (const float*)d_in[1];
    const float* ln1g = (const float*)d_in[2];
    const float* ln1b = (const float*)d_in[3];
    const float* aiw  = (const float*)d_in[4];
    const float* aib  = (const float*)d_in[5];
    const float* aow  = (const float*)d_in[6];
    const float* aob  = (const float*)d_in[7];
    const float* ln2g = (const float*)d_in[8];
    const float* ln2b = (const float*)d_in[9];
    const float* rw   = (const float*)d_in[10];
    const float* rb   = (const float*)d_in[11];
    const float* f1w  = (const float*)d_in[12];
    const float* f1b  = (const float*)d_in[13];
    const float* f2w  = (const float*)d_in[14];
    const float* f2b  = (const float*)d_in[15];
    const float* lmw  = (const float*)d_in[16];
    const float* lmb  = (const float*)d_in[17];
    float* out = (float*)d_out;

    cudaFuncSetAttribute(bgemm<4,0,256,1,64>, cudaFuncAttributeMaxDynamicSharedMemorySize, DS_T1_256_64);
    cudaFuncSetAttribute(bgemm<0,0,256,1,32>, cudaFuncAttributeMaxDynamicSharedMemorySize, DS_T1_256_32);
    cudaFuncSetAttribute(bgemm<4,0,128,1,32>, cudaFuncAttributeMaxDynamicSharedMemorySize, DS_T1_128_32);
    cudaFuncSetAttribute(bgemm<2,0,128,2,32>, cudaFuncAttributeMaxDynamicSharedMemorySize, DS_T2_128);
    cudaFuncSetAttribute(bgemm<5,1,256,1,64>, cudaFuncAttributeMaxDynamicSharedMemorySize, DS_T1_256_64);
    cudaFuncSetAttribute(bgemm<1,2,256,1,64>, cudaFuncAttributeMaxDynamicSharedMemorySize, DS_T1_256_64);
    cudaFuncSetAttribute(bgemm<1,0,256,1,64>, cudaFuncAttributeMaxDynamicSharedMemorySize, DS_T1_256_64);

    float *px, *pn, *psc, *pmoe;
    cudaGetSymbolAddress((void**)&px,   g_x);
    cudaGetSymbolAddress((void**)&pn,   g_n);
    cudaGetSymbolAddress((void**)&psc,  g_scores);
    cudaGetSymbolAddress((void**)&pmoe, g_moe);
    float* pzb; cudaGetSymbolAddress((void**)&pzb, g_zb);
    __half *winH,*woutH,*f1H,*f2H,*lmH;
    __half *nH,*qkvH,*qkvL,*vTH,*pH,*aoH,*aoL,*xH,*hH;
    cudaGetSymbolAddress((void**)&winH,  g_winH);
    cudaGetSymbolAddress((void**)&woutH, g_woutH);
    cudaGetSymbolAddress((void**)&f1H,   g_f1H);
    cudaGetSymbolAddress((void**)&f2H,   g_f2H);
    cudaGetSymbolAddress((void**)&lmH,   g_lmH);
    cudaGetSymbolAddress((void**)&nH,    g_nH);
    cudaGetSymbolAddress((void**)&qkvH,  g_qkvH);  cudaGetSymbolAddress((void**)&qkvL,  g_qkvL);
    cudaGetSymbolAddress((void**)&vTH,   g_vTH);
    cudaGetSymbolAddress((void**)&pH,    g_pH);
    cudaGetSymbolAddress((void**)&aoH,   g_aoH);   cudaGetSymbolAddress((void**)&aoL,   g_aoL);
    cudaGetSymbolAddress((void**)&xH,    g_xH);
    cudaGetSymbolAddress((void**)&hH,    g_hH);

    // ---- weight conversions (hi-only) ----
    cvt1_k<<<cv8blocks((ll)Lq*3*Hq*Hq),  256>>>(aiw, winH,  (ll)Lq*3*Hq*Hq);
    cvt1_k<<<cv8blocks((ll)Lq*Hq*Hq),    256>>>(aow, woutH, (ll)Lq*Hq*Hq);
    cvt1_k<<<cv8blocks((ll)Lq*Eq*Iq*Hq), 256>>>(f1w, f1H, (ll)Lq*Eq*Iq*Hq);
    cvt1_k<<<cv8blocks((ll)Lq*Eq*Hq*Iq), 256>>>(f2w, f2H, (ll)Lq*Eq*Hq*Iq);
    cvt1_k<<<cv8blocks((ll)Vq*Hq),       256>>>(lmw, lmH, (ll)Vq*Hq);

    zero_aux_k<<<1,256>>>();
    embed_k<<<(Tq*Hq)/256, 256>>>(ids, emb);

    for (int l = 0; l < Lq; l++) {
        // --- attention ---
        ln_k<<<Tq,256>>>(px, ln1g + (ll)l*Hq, ln1b + (ll)l*Hq, pn, nH, 0);

        // qkv = n1 @ W_in^T + b  (1-term, BK=64) -> qkv hi/lo planes
        bgemm<4,0,256,1,64><<<dim3(Tq/128, 3*Hq/256, 1), 256, DS_T1_256_64>>>(
            Tq, 3*Hq, Hq, nH, nullptr, Hq,
            winH + (ll)l*3*Hq*Hq, nullptr, Hq,
            qkvH, qkvL, 3*Hq, aib + (ll)l*3*Hq, nullptr,
            1.f, 1, 0,0,0,0,0,0, 0,0);

        // V^T hi plane per (b,h)
        vtrans_k<<<dim3(Sq/32, DHq/32, Bq*NHq), dim3(32,8)>>>(qkvH, vTH);

        // scores = q @ k^T / sqrt(DH)  (1-term: Q hi x K hi, batched)
        bgemm<0,0,256,1,32><<<dim3(Sq/128, Sq/256, Bq*NHq), 256, DS_T1_256_32>>>(
            Sq, Sq, DHq, qkvH, nullptr, 3*Hq,
            qkvH + Hq, nullptr, 3*Hq,
            psc, nullptr, Sq, nullptr, nullptr,
            1.f/11.313708498984761f, NHq,
            (ll)Sq*3*Hq, DHq, (ll)Sq*3*Hq, DHq, (ll)NHq*Sq*Sq, (ll)Sq*Sq,
            0, 0);

        softmax_k<<<Bq*NHq*Sq, 256>>>(psc, pH);

        // o = attn @ v  (1-term: probs hi x V hi, batched) -> ao hi/lo planes
        bgemm<4,0,128,1,32><<<dim3(Sq/128, DHq/128, Bq*NHq), 256, DS_T1_128_32>>>(
            Sq, DHq, Sq, pH, nullptr, Sq,
            vTH, nullptr, Sq,
            aoH, aoL, Hq, pzb, nullptr,
            1.f, NHq,
            (ll)NHq*Sq*Sq, (ll)Sq*Sq, (ll)NHq*DHq*Sq, (ll)DHq*Sq,
            (ll)Sq*Hq, DHq,
            0, 0);

        // x = x + o @ W_out^T + b  (2-term: ao hi+lo x Wout hi)
        bgemm<2,0,128,2,32><<<dim3(Tq/128, Hq/128, 1), 256, DS_T2_128>>>(
            Tq, Hq, Hq, aoH, aoL, Hq,
            woutH + (ll)l*Hq*Hq, nullptr, Hq,
            px, nullptr, Hq, aob + (ll)l*Hq, px,
            1.f, 1, 0,0,0,0,0,0, 0,0);

        // --- MoE ---
        ln_k<<<Tq,256>>>(px, ln2g + (ll)l*Hq, ln2b + (ll)l*Hq, pn, nH, 3);

        router_k<<<Tq,256>>>(pn, rw + (ll)l*Eq*Hq, rb + (ll)l*Eq);
        offsets_k<<<1,1>>>();
        build_k<<<Tq/256,256>>>();

        // fc1: gather, gelu, write hi-plane hidden  (1-term, BK=64)
        bgemm<5,1,256,1,64><<<dim3(Tq/128, Iq/256, Eq), 256, DS_T1_256_64>>>(
            Tq, Iq, Hq, nH, nullptr, Hq,
            f1H + (ll)l*Eq*Iq*Hq, nullptr, Hq,
            hH, nullptr, Iq, f1b + (ll)l*Eq*Iq, nullptr,
            1.f, 1, 0,0,0,0,0,0, (ll)Iq*Hq, (ll)Iq);

        // fc2: scatter to per-slot fp32 buffers  (1-term, BK=64)
        bgemm<1,2,256,1,64><<<dim3(Tq/128, Hq/256, Eq), 256, DS_T1_256_64>>>(
            Tq, Hq, Iq, hH, nullptr, Iq,
            f2H + (ll)l*Eq*Hq*Iq, nullptr, Iq,
            pmoe, nullptr, Hq, f2b + (ll)l*Eq*Hq, nullptr,
            1.f, 1, 0,0,0,0,0,0, (ll)Hq*Iq, (ll)Hq);

        // combine; on last layer also emit x hi plane for lm head
        bool last = (l == Lq - 1);
        combine_k<<<(Tq*Hq)/256, 256>>>(last ? xH : nullptr);
    }

    // lm head  (1-term, BK=64)
    bgemm<1,0,256,1,64><<<dim3(Tq/128, Vq/256, 1), 256, DS_T1_256_64>>>(
        Tq, Vq, Hq, xH, nullptr, Hq, lmH, nullptr, Hq, out, nullptr, Vq,
        lmb, nullptr, 1.f, 1, 0,0,0,0,0,0, 0, 0);

    tail_k<<<1,256>>>(out, (ll)out_size);
}

// round 15
// speedup vs baseline: 5.9101x; 1.0304x over previous
#include <cuda_runtime.h>
#include <cuda_fp16.h>
#include <math.h>
#include <stdint.h>

// ---------------- problem constants ----------------
#define Bq 4
#define Sq 512
#define Hq 1024
#define Iq 4096
#define Eq 8
#define Vq 32000
#define Lq 2
#define NHq 8
#define DHq 128
#define Tq (Bq*Sq)          // 2048 tokens

typedef long long ll;

__device__ __forceinline__ uint32_t smem_u32(const void* p) {
    uint32_t a;
    asm("{ .reg .u64 t; cvta.to.shared.u64 t, %1; cvt.u32.u64 %0, t; }" : "=r"(a) : "l"(p));
    return a;
}

// ---------------- device scratch (static, no allocs) ----------------
__device__ float g_x[Tq*Hq];
__device__ float g_n[Tq*Hq];
__device__ float g_scores[Bq*NHq*Sq*Sq];
__device__ float g_moe[2*Tq*Hq];
__device__ int   g_sel[Tq*2];
__device__ int   g_cnt[Eq];
__device__ int   g_off[Eq];
__device__ int   g_cur[Eq];
__device__ int   g_tokmap[2*Tq];
__device__ int   g_outmap[2*Tq];
__device__ float g_aux[1];
__device__ float g_zb[DHq];      // zero bias
// fp16 planes
__device__ __half g_winH[Lq*3*Hq*Hq];
__device__ __half g_woutH[Lq*Hq*Hq];
__device__ __half g_f1H[(size_t)Lq*Eq*Iq*Hq];
__device__ __half g_f2H[(size_t)Lq*Eq*Hq*Iq];
__device__ __half g_lmH[(size_t)Vq*Hq];
__device__ __half g_nH[Tq*Hq];
__device__ __half g_qkvH[Tq*3*Hq];
__device__ __half g_vTH[Tq*Hq];
__device__ __half g_pH[(size_t)Bq*NHq*Sq*Sq];
__device__ __half g_aoH[Tq*Hq];
__device__ __half g_xH[Tq*Hq];
__device__ __half g_hH[(size_t)2*Tq*Iq];

// ---------------- conversions ----------------
__global__ void cvt1_k(const float* __restrict__ src, __half* __restrict__ hi, ll total) {
    ll i = ((ll)blockIdx.x * 256 + threadIdx.x) * 8;
    if (i >= total) return;
    float4 a = *(const float4*)(src + i);
    float4 b = *(const float4*)(src + i + 4);
    float v[8] = {a.x, a.y, a.z, a.w, b.x, b.y, b.z, b.w};
    __align__(16) __half h[8];
    #pragma unroll
    for (int j = 0; j < 8; j++) h[j] = __float2half(v[j]);
    *(uint4*)(hi + i) = *(const uint4*)h;
}

// ---------------- HMMA fp16 split GEMM ----------------
// TERMS=3: C = Ah*Bh + Al*Bh + Ah*Bl   TERMS=2: C = (Ah+Al)*Bh   TERMS=1: C = Ah*Bh
// CTA tile 128xTN, K-slice BKT (32/64), 4-stage cp.async pipeline, 8 warps (2x4).
// EPI: 0=alpha(f32), 1=bias(f32), 2=bias+res(f32), 3=bias+gelu->hi/lo planes,
//      4=bias->hi/lo planes, 5=bias+gelu->hi only, 6=bias->hi only.
// MOE: 0 dense/batched, 1 gather-A/compact-C, 2 compact-A/scatter-C.
#define DS_T2_128 122880     // 4 stages x 30720  (TERMS=2, TN=128, BK=32)
#define DS_T1_256_32 122880  // 4 stages x 30720  (TERMS=1, TN=256, BK=32)
#define DS_T1_128_32 81920   // 4 stages x 20480  (TERMS=1, TN=128, BK=32)
#define DS_T1_256_64 221184  // 4 stages x 55296  (TERMS=1, TN=256, BK=64)
#define DS_T1_128_64 147456  // 4 stages x 36864  (TERMS=1, TN=128, BK=64)

__device__ __forceinline__ void ldmx4(uint32_t* r, uint32_t addr) {
    asm volatile("ldmatrix.sync.aligned.m8n8.x4.shared.b16 {%0,%1,%2,%3}, [%4];"
        : "=r"(r[0]), "=r"(r[1]), "=r"(r[2]), "=r"(r[3]) : "r"(addr));
}
__device__ __forceinline__ void mma16816(float* c, const uint32_t* a, uint32_t b0, uint32_t b1) {
    asm volatile("mma.sync.aligned.m16n8k16.row.col.f32.f16.f16.f32 "
        "{%0,%1,%2,%3}, {%4,%5,%6,%7}, {%8,%9}, {%0,%1,%2,%3};"
        : "+f"(c[0]), "+f"(c[1]), "+f"(c[2]), "+f"(c[3])
        : "r"(a[0]), "r"(a[1]), "r"(a[2]), "r"(a[3]), "r"(b0), "r"(b1));
}
__device__ __forceinline__ void cpasync16(uint32_t dst, const void* src) {
    asm volatile("cp.async.cg.shared.global [%0], [%1], 16;" :: "r"(dst), "l"(src));
}
__device__ __forceinline__ void cpasync16z(uint32_t dst, const void* src, uint32_t sz) {
    asm volatile("cp.async.cg.shared.global [%0], [%1], 16, %2;" :: "r"(dst), "l"(src), "r"(sz));
}

template<int EPI, int MOE, int TN, int TERMS, int BKT>
__global__ __launch_bounds__(256, 1)
void bgemm(int M, int N, int K,
           const __half* __restrict__ Ah, const __half* __restrict__ Al, int lda,
           const __half* __restrict__ Bh, const __half* __restrict__ Bl, int ldb,
           void* __restrict__ Cv, __half* __restrict__ Clo, int ldc,
           const float* __restrict__ bias,
           const float* __restrict__ res,
           float alpha, int zdiv,
           ll sA1, ll sA2, ll sB1, ll sB2, ll sC1, ll sC2,
           ll sBz, ll sBiasZ)
{
    constexpr int WN     = TN / 4;
    constexpr int NF     = WN / 8;
    constexpr int NB16   = WN / 16;
    constexpr int APL    = (TERMS >= 2) ? 2 : 1;
    constexpr int BPL    = (TERMS == 3) ? 2 : 1;
    constexpr int STAGES = 4;
    constexpr int RSH    = BKT + 8;                // row stride in halves
    constexpr uint32_t APB = 128u * RSH * 2u;
    constexpr uint32_t BPB = (uint32_t)TN * RSH * 2u;
    constexpr uint32_t STB = APB * APL + BPB * BPL;
    constexpr uint32_t ALOFF = APB;
    constexpr uint32_t BHOFF = APB * APL;
    constexpr uint32_t BLOFF = BHOFF + BPB;

    int Me = M, rowbase = 0;
    ll coff = 0;
    if (MOE) {
        int z = blockIdx.z;
        Me = g_cnt[z]; rowbase = g_off[z];
        Bh += (ll)z * sBz; if (TERMS == 3) Bl += (ll)z * sBz;
        bias += (ll)z * sBiasZ;
    } else {
        int z = blockIdx.z;
        int zb = z / zdiv, zh = z - zb * zdiv;
        Ah += zb*sA1 + zh*sA2; if (TERMS >= 2) Al += zb*sA1 + zh*sA2;
        Bh += zb*sB1 + zh*sB2; if (TERMS == 3) Bl += zb*sB1 + zh*sB2;
        coff = zb*sC1 + zh*sC2;
    }
    int m0 = blockIdx.x * 128;
    if (m0 >= Me) return;
    int n0 = blockIdx.y * TN;

    __shared__ int s_row[128];
    __shared__ int s_cout[128];
    extern __shared__ __align__(16) char dsm[];
    uint32_t dbase = smem_u32(dsm);

    int tid = threadIdx.x, lane = tid & 31, wid = tid >> 5;
    int wm = wid >> 2, wn = wid & 3;

    if (tid < 128) {
        int grow = m0 + tid;
        int rid = -1, cid = -1;
        if (grow < Me) {
            if      (MOE == 1) { rid = g_tokmap[rowbase + grow]; cid = rowbase + grow; }
            else if (MOE == 2) { rid = rowbase + grow;           cid = g_outmap[rowbase + grow]; }
            else               { rid = grow;                     cid = grow; }
        }
        s_row[tid] = rid; s_cout[tid] = cid;
    }
    __syncthreads();

    float acc[4][NF][4];
    #pragma unroll
    for (int a = 0; a < 4; a++)
        #pragma unroll
        for (int b = 0; b < NF; b++)
            #pragma unroll
            for (int c = 0; c < 4; c++) acc[a][b][c] = 0.f;

    int S = K / BKT;

    auto load_stage = [&](int s) {
        int c0 = s * BKT;
        uint32_t base = dbase + (uint32_t)(s % STAGES) * STB;
        constexpr int CPR  = BKT / 8;
        constexpr int CH_A = 128 * CPR;
        constexpr int CH_B = TN * CPR;
        constexpr int ITER = (APL*CH_A + BPL*CH_B) / 256;
        #pragma unroll
        for (int j = 0; j < ITER; j++) {
            int idx = tid + j * 256;
            if (idx < CH_A) {
                int row = idx / CPR, c = idx % CPR;
                int r = s_row[row];
                ll aoff = (r >= 0) ? ((ll)r * lda + c0 + c * 8) : 0;
                cpasync16z(base + (uint32_t)(row*(RSH*2) + c*16), Ah + aoff, (r>=0)?16u:0u);
            } else if (APL == 2 && idx < 2*CH_A) {
                int k2 = idx - CH_A;
                int row = k2 / CPR, c = k2 % CPR;
                int r = s_row[row];
                ll aoff = (r >= 0) ? ((ll)r * lda + c0 + c * 8) : 0;
                cpasync16z(base + ALOFF + (uint32_t)(row*(RSH*2) + c*16), Al + aoff, (r>=0)?16u:0u);
            } else if (idx < APL*CH_A + CH_B) {
                int k2 = idx - APL*CH_A;
                int row = k2 / CPR, c = k2 % CPR;
                cpasync16(base + BHOFF + (uint32_t)(row*(RSH*2) + c*16),
                          Bh + (ll)(n0 + row) * ldb + c0 + c * 8);
            } else if (BPL == 2) {
                int k2 = idx - APL*CH_A - CH_B;
                int row = k2 / CPR, c = k2 % CPR;
                cpasync16(base + BLOFF + (uint32_t)(row*(RSH*2) + c*16),
                          Bl + (ll)(n0 + row) * ldb + c0 + c * 8);
            }
        }
        asm volatile("cp.async.commit_group;" ::: "memory");
    };

    #pragma unroll
    for (int i = 0; i < STAGES - 1; i++) load_stage(i);

    for (int s = 0; s < S; s++) {
        if (S - s - 1 >= STAGES - 2) {
            asm volatile("cp.async.wait_group %0;" :: "n"(STAGES - 2) : "memory");
        } else {
            asm volatile("cp.async.wait_group 0;" ::: "memory");
        }
        __syncthreads();
        if (s + STAGES - 1 < S) load_stage(s + STAGES - 1);

        uint32_t base = dbase + (uint32_t)(s % STAGES) * STB;
        uint32_t Ahb = base, Alb = base + ALOFF, Bhb = base + BHOFF, Blb = base + BLOFF;

        #pragma unroll
        for (int kk = 0; kk < BKT/16; kk++) {
            uint32_t ah[4][4], al[4][4];
            #pragma unroll
            for (int mf = 0; mf < 4; mf++) {
                uint32_t roff = (uint32_t)(((wm*64 + mf*16 + (lane & 15)) * RSH
                                            + kk*16 + (lane >> 4) * 8) * 2);
                ldmx4(ah[mf], Ahb + roff);
                if (TERMS >= 2) ldmx4(al[mf], Alb + roff);
            }
            int g = lane >> 3;
            #pragma unroll
            for (int bt = 0; bt < NB16; bt++) {
                uint32_t bhf[4], blf[4];
                uint32_t roff = (uint32_t)(((wn*WN + bt*16 + (g >> 1)*8 + (lane & 7)) * RSH
                                            + kk*16 + (g & 1) * 8) * 2);
                ldmx4(bhf, Bhb + roff);
                if (TERMS == 3) ldmx4(blf, Blb + roff);
                #pragma unroll
                for (int sub = 0; sub < 2; sub++) {
                    int nf = bt*2 + sub;
                    #pragma unroll
                    for (int mf = 0; mf < 4; mf++) {
                        mma16816(acc[mf][nf], ah[mf], bhf[sub*2], bhf[sub*2+1]);
                        if (TERMS >= 2)
                            mma16816(acc[mf][nf], al[mf], bhf[sub*2], bhf[sub*2+1]);
                        if (TERMS == 3)
                            mma16816(acc[mf][nf], ah[mf], blf[sub*2], blf[sub*2+1]);
                    }
                }
            }
        }
    }

    // ---------------- epilogue ----------------
    #pragma unroll
    for (int mf = 0; mf < 4; mf++) {
        int rbase = wm*64 + mf*16 + (lane >> 2);
        #pragma unroll
        for (int half = 0; half < 2; half++) {
            int rloc = rbase + half * 8;
            int cr = s_cout[rloc];
            if (cr < 0) continue;
            #pragma unroll
            for (int nf = 0; nf < NF; nf++) {
                int col = n0 + wn*WN + nf*8 + (lane & 3)*2;
                float v0 = acc[mf][nf][half*2 + 0] * alpha;
                float v1 = acc[mf][nf][half*2 + 1] * alpha;
                if (EPI >= 1) {
                    float2 bv = *(const float2*)&bias[col];
                    v0 += bv.x; v1 += bv.y;
                }
                if (EPI == 2) {
                    float2 rv = *(const float2*)(res + (ll)cr*ldc + col);
                    v0 += rv.x; v1 += rv.y;
                }
                if (EPI >= 3) {
                    if (EPI == 3 || EPI == 5) {
                        v0 = 0.5f*v0*(1.f + erff(v0*0.70710678118654752f));
                        v1 = 0.5f*v1*(1.f + erff(v1*0.70710678118654752f));
                    }
                    __half h0 = __float2half(v0);
                    __half h1 = __float2half(v1);
                    __half* DH = (__half*)Cv + coff + (ll)cr * ldc + col;
                    *(__half2*)DH = __halves2half2(h0, h1);
                    if (EPI == 3 || EPI == 4) {
                        __half l0 = __float2half(v0 - __half2float(h0));
                        __half l1 = __float2half(v1 - __half2float(h1));
                        __half* DL = Clo + coff + (ll)cr * ldc + col;
                        *(__half2*)DL = __halves2half2(l0, l1);
                    }
                } else {
                    *(float2*)((float*)Cv + coff + (ll)cr*ldc + col) = make_float2(v0, v1);
                }
            }
        }
    }
}

// ---------------- V transpose: qkv hi plane -> per-(b,h) V^T hi plane ----------------
__global__ void vtrans_k(const __half* __restrict__ qH, __half* __restrict__ vTH) {
    int z = blockIdx.z; int b = z >> 3; int h = z & 7;
    int d0 = blockIdx.y * 32;
    int s0 = blockIdx.x * 32;
    __shared__ __half tH[32][33];
    int tx = threadIdx.x, ty = threadIdx.y;   // 32 x 8
    #pragma unroll
    for (int i = 0; i < 4; i++) {
        int sl = ty*4 + i;
        ll src = (ll)(b*Sq + s0 + sl)*(3*Hq) + 2*Hq + h*DHq + d0 + tx;
        tH[sl][tx] = qH[src];
    }
    __syncthreads();
    #pragma unroll
    for (int i = 0; i < 4; i++) {
        int dl = ty*4 + i;
        ll dst = ((ll)z*DHq + d0 + dl)*Sq + s0 + tx;
        vTH[dst] = tH[tx][dl];
    }
}

// ---------------- small kernels ----------------
__global__ void embed_k(const int* __restrict__ ids, const float* __restrict__ emb) {
    int idx = blockIdx.x*256 + threadIdx.x;
    int t = idx / Hq, h = idx - t*Hq;
    g_x[idx] = emb[(ll)ids[t]*Hq + h];
}

// LayerNorm: emits fp16 hi plane always; fp32 output + cnt-zeroing optional
__global__ void ln_k(const float* __restrict__ x, const float* __restrict__ g,
                     const float* __restrict__ b, float* __restrict__ o,
                     __half* __restrict__ oH, int flags) {
    int t = blockIdx.x;
    if ((flags & 2) && t == 0 && threadIdx.x < Eq) g_cnt[threadIdx.x] = 0;
    const float* xr = x + (ll)t*Hq;
    int tid = threadIdx.x;
    float v[4]; float s = 0.f;
    #pragma unroll
    for (int i = 0; i < 4; i++) { v[i] = xr[tid + 256*i]; s += v[i]; }
    __shared__ float red[256];
    red[tid] = s; __syncthreads();
    for (int o2 = 128; o2; o2 >>= 1) { if (tid < o2) red[tid] += red[tid+o2]; __syncthreads(); }
    float mu = red[0] * (1.f/Hq);
    __syncthreads();
    s = 0.f;
    #pragma unroll
    for (int i = 0; i < 4; i++) { float d = v[i]-mu; s += d*d; }
    red[tid] = s; __syncthreads();
    for (int o2 = 128; o2; o2 >>= 1) { if (tid < o2) red[tid] += red[tid+o2]; __syncthreads(); }
    float inv = rsqrtf(red[0]*(1.f/Hq) + 1e-5f);
    float* orow = o + (ll)t*Hq;
    __half* hr = oH + (ll)t*Hq;
    #pragma unroll
    for (int i = 0; i < 4; i++) {
        int h = tid + 256*i;
        float y = (v[i]-mu)*inv*g[h] + b[h];
        if (flags & 1) orow[h] = y;
        hr[h] = __float2half(y);
    }
}

__global__ void softmax_k(const float* __restrict__ sc, __half* __restrict__ pH) {
    ll row = blockIdx.x;
    const float* r = sc + row*Sq;
    int tid = threadIdx.x;
    float a = r[tid], b = r[tid+256];
    __shared__ float red[256];
    red[tid] = fmaxf(a,b); __syncthreads();
    for (int o = 128; o; o >>= 1) { if (tid < o) red[tid] = fmaxf(red[tid], red[tid+o]); __syncthreads(); }
    float m = red[0]; __syncthreads();
    a = expf(a-m); b = expf(b-m);
    red[tid] = a+b; __syncthreads();
    for (int o = 128; o; o >>= 1) { if (tid < o) red[tid] += red[tid+o]; __syncthreads(); }
    float inv = 1.f/red[0];
    pH[row*Sq + tid]       = __float2half(a*inv);
    pH[row*Sq + tid + 256] = __float2half(b*inv);
}

__global__ void zero_aux_k() {
    if (threadIdx.x == 0) g_aux[0] = 0.f;
    if (threadIdx.x < DHq) g_zb[threadIdx.x] = 0.f;
}

__global__ void router_k(const float* __restrict__ n2, const float* __restrict__ rw,
                         const float* __restrict__ rb) {
    int t = blockIdx.x;
    int w = threadIdx.x >> 5, lane = threadIdx.x & 31;
    const float* xr = n2 + (ll)t*Hq;
    const float* wr = rw + (ll)w*Hq;
    float s = 0.f;
    for (int h = lane; h < Hq; h += 32) s += xr[h]*wr[h];
    #pragma unroll
    for (int o = 16; o; o >>= 1) s += __shfl_xor_sync(0xffffffffu, s, o);
    __shared__ float lg[Eq];
    if (lane == 0) lg[w] = s + rb[w];
    __syncthreads();
    if (threadIdx.x == 0) {
        int b0 = 0; float v0 = lg[0];
        for (int e = 1; e < Eq; e++) if (lg[e] > v0) { v0 = lg[e]; b0 = e; }
        int b1 = -1; float v1 = -3.4e38f;
        for (int e = 0; e < Eq; e++) { if (e == b0) continue; if (lg[e] > v1) { v1 = lg[e]; b1 = e; } }
        g_sel[2*t]   = b0;
        g_sel[2*t+1] = b1;
        atomicAdd(&g_cnt[b0], 1);
        atomicAdd(&g_cnt[b1], 1);
    }
}

// offsets + aux loss fused (1 thread)
__global__ void offsets_k() {
    int s = 0;
    float acc = 0.f;
    const float target = (float)Tq / (float)Eq;
    for (int e = 0; e < Eq; e++) {
        g_off[e] = s; g_cur[e] = s; s += g_cnt[e];
        float d = (float)g_cnt[e] - target;
        acc += d*d;
    }
    g_aux[0] += 0.01f * acc / (float)Eq;
}

__global__ void build_k() {
    int t = blockIdx.x*256 + threadIdx.x;
    if (t >= Tq) return;
    #pragma unroll
    for (int slot = 0; slot < 2; slot++) {
        int e = g_sel[2*t + slot];
        int p = atomicAdd(&g_cur[e], 1);
        g_tokmap[p] = t;
        g_outmap[p] = slot*Tq + t;
    }
}

// combine + optional hi plane emission (lm-head input after last layer)
__global__ void combine_k(__half* __restrict__ xH) {
    int idx = blockIdx.x*256 + threadIdx.x;
    float v = g_x[idx] + g_moe[idx] + g_moe[(ll)Tq*Hq + idx];
    g_x[idx] = v;
    if (xH) xH[idx] = __float2half(v);
}

__global__ void tail_k(float* __restrict__ out, ll out_size) {
    ll base = (ll)Tq * Vq;
    for (ll i = base + threadIdx.x; i < out_size; i += 256)
        out[i] = g_aux[0];
}

// ---------------- launch ----------------
static inline int cv8blocks(ll total) { return (int)((total/8 + 255) / 256); }

extern "C" void kernel_launch(void* const* d_in, const int* in_sizes, int n_in,
                              void* d_out, int out_size) {
    const int*   ids  = (const int*)  d_in[0];
    const float* emb  = (const float*)d_in[1];
    const float* ln1g = (const float*)d_in[2];
    const float* ln1b = (const float*)d_in[3];
    const float* aiw  = (const float*)d_in[4];
    const float* aib  = (const float*)d_in[5];
    const float* aow  = (const float*)d_in[6];
    const float* aob  = (const float*)d_in[7];
    const float* ln2g = (const float*)d_in[8];
    const float* ln2b = (const float*)d_in[9];
    const float* rw   = (const float*)d_in[10];
    const float* rb   = (const float*)d_in[11];
    const float* f1w  = (const float*)d_in[12];
    const float* f1b  = (const float*)d_in[13];
    const float* f2w  = (const float*)d_in[14];
    const float* f2b  = (const float*)d_in[15];
    const float* lmw  = (const float*)d_in[16];
    const float* lmb  = (const float*)d_in[17];
    float* out = (float*)d_out;

    cudaFuncSetAttribute(bgemm<6,0,256,1,64>, cudaFuncAttributeMaxDynamicSharedMemorySize, DS_T1_256_64);
    cudaFuncSetAttribute(bgemm<0,0,256,1,32>, cudaFuncAttributeMaxDynamicSharedMemorySize, DS_T1_256_32);
    cudaFuncSetAttribute(bgemm<6,0,128,1,32>, cudaFuncAttributeMaxDynamicSharedMemorySize, DS_T1_128_32);
    cudaFuncSetAttribute(bgemm<2,0,128,1,64>, cudaFuncAttributeMaxDynamicSharedMemorySize, DS_T1_128_64);
    cudaFuncSetAttribute(bgemm<5,1,256,1,64>, cudaFuncAttributeMaxDynamicSharedMemorySize, DS_T1_256_64);
    cudaFuncSetAttribute(bgemm<1,2,256,1,64>, cudaFuncAttributeMaxDynamicSharedMemorySize, DS_T1_256_64);
    cudaFuncSetAttribute(bgemm<1,0,256,1,64>, cudaFuncAttributeMaxDynamicSharedMemorySize, DS_T1_256_64);

    float *px, *pn, *psc, *pmoe;
    cudaGetSymbolAddress((void**)&px,   g_x);
    cudaGetSymbolAddress((void**)&pn,   g_n);
    cudaGetSymbolAddress((void**)&psc,  g_scores);
    cudaGetSymbolAddress((void**)&pmoe, g_moe);
    float* pzb; cudaGetSymbolAddress((void**)&pzb, g_zb);
    __half *winH,*woutH,*f1H,*f2H,*lmH;
    __half *nH,*qkvH,*vTH,*pH,*aoH,*xH,*hH;
    cudaGetSymbolAddress((void**)&winH,  g_winH);
    cudaGetSymbolAddress((void**)&woutH, g_woutH);
    cudaGetSymbolAddress((void**)&f1H,   g_f1H);
    cudaGetSymbolAddress((void**)&f2H,   g_f2H);
    cudaGetSymbolAddress((void**)&lmH,   g_lmH);
    cudaGetSymbolAddress((void**)&nH,    g_nH);
    cudaGetSymbolAddress((void**)&qkvH,  g_qkvH);
    cudaGetSymbolAddress((void**)&vTH,   g_vTH);
    cudaGetSymbolAddress((void**)&pH,    g_pH);
    cudaGetSymbolAddress((void**)&aoH,   g_aoH);
    cudaGetSymbolAddress((void**)&xH,    g_xH);
    cudaGetSymbolAddress((void**)&hH,    g_hH);

    // ---- weight conversions (hi-only) ----
    cvt1_k<<<cv8blocks((ll)Lq*3*Hq*Hq),  256>>>(aiw, winH,  (ll)Lq*3*Hq*Hq);
    cvt1_k<<<cv8blocks((ll)Lq*Hq*Hq),    256>>>(aow, woutH, (ll)Lq*Hq*Hq);
    cvt1_k<<<cv8blocks((ll)Lq*Eq*Iq*Hq), 256>>>(f1w, f1H, (ll)Lq*Eq*Iq*Hq);
    cvt1_k<<<cv8blocks((ll)Lq*Eq*Hq*Iq), 256>>>(f2w, f2H, (ll)Lq*Eq*Hq*Iq);
    cvt1_k<<<cv8blocks((ll)Vq*Hq),       256>>>(lmw, lmH, (ll)Vq*Hq);

    zero_aux_k<<<1,256>>>();
    embed_k<<<(Tq*Hq)/256, 256>>>(ids, emb);

    for (int l = 0; l < Lq; l++) {
        // --- attention ---
        ln_k<<<Tq,256>>>(px, ln1g + (ll)l*Hq, ln1b + (ll)l*Hq, pn, nH, 0);

        // qkv = n1 @ W_in^T + b  (1-term, BK=64) -> hi plane only
        bgemm<6,0,256,1,64><<<dim3(Tq/128, 3*Hq/256, 1), 256, DS_T1_256_64>>>(
            Tq, 3*Hq, Hq, nH, nullptr, Hq,
            winH + (ll)l*3*Hq*Hq, nullptr, Hq,
            qkvH, nullptr, 3*Hq, aib + (ll)l*3*Hq, nullptr,
            1.f, 1, 0,0,0,0,0,0, 0,0);

        // V^T hi plane per (b,h)
        vtrans_k<<<dim3(Sq/32, DHq/32, Bq*NHq), dim3(32,8)>>>(qkvH, vTH);

        // scores = q @ k^T / sqrt(DH)  (1-term, batched)
        bgemm<0,0,256,1,32><<<dim3(Sq/128, Sq/256, Bq*NHq), 256, DS_T1_256_32>>>(
            Sq, Sq, DHq, qkvH, nullptr, 3*Hq,
            qkvH + Hq, nullptr, 3*Hq,
            psc, nullptr, Sq, nullptr, nullptr,
            1.f/11.313708498984761f, NHq,
            (ll)Sq*3*Hq, DHq, (ll)Sq*3*Hq, DHq, (ll)NHq*Sq*Sq, (ll)Sq*Sq,
            0, 0);

        softmax_k<<<Bq*NHq*Sq, 256>>>(psc, pH);

        // o = attn @ v  (1-term, batched) -> ao hi plane only
        bgemm<6,0,128,1,32><<<dim3(Sq/128, DHq/128, Bq*NHq), 256, DS_T1_128_32>>>(
            Sq, DHq, Sq, pH, nullptr, Sq,
            vTH, nullptr, Sq,
            aoH, nullptr, Hq, pzb, nullptr,
            1.f, NHq,
            (ll)NHq*Sq*Sq, (ll)Sq*Sq, (ll)NHq*DHq*Sq, (ll)DHq*Sq,
            (ll)Sq*Hq, DHq,
            0, 0);

        // x = x + o @ W_out^T + b  (1-term, BK=64)
        bgemm<2,0,128,1,64><<<dim3(Tq/128, Hq/128, 1), 256, DS_T1_128_64>>>(
            Tq, Hq, Hq, aoH, nullptr, Hq,
            woutH + (ll)l*Hq*Hq, nullptr, Hq,
            px, nullptr, Hq, aob + (ll)l*Hq, px,
            1.f, 1, 0,0,0,0,0,0, 0,0);

        // --- MoE ---
        ln_k<<<Tq,256>>>(px, ln2g + (ll)l*Hq, ln2b + (ll)l*Hq, pn, nH, 3);

        router_k<<<Tq,256>>>(pn, rw + (ll)l*Eq*Hq, rb + (ll)l*Eq);
        offsets_k<<<1,1>>>();
        build_k<<<Tq/256,256>>>();

        // fc1: gather, gelu, write hi-plane hidden  (1-term, BK=64)
        bgemm<5,1,256,1,64><<<dim3(Tq/128, Iq/256, Eq), 256, DS_T1_256_64>>>(
            Tq, Iq, Hq, nH, nullptr, Hq,
            f1H + (ll)l*Eq*Iq*Hq, nullptr, Hq,
            hH, nullptr, Iq, f1b + (ll)l*Eq*Iq, nullptr,
            1.f, 1, 0,0,0,0,0,0, (ll)Iq*Hq, (ll)Iq);

        // fc2: scatter to per-slot fp32 buffers  (1-term, BK=64)
        bgemm<1,2,256,1,64><<<dim3(Tq/128, Hq/256, Eq), 256, DS_T1_256_64>>>(
            Tq, Hq, Iq, hH, nullptr, Iq,
            f2H + (ll)l*Eq*Hq*Iq, nullptr, Iq,
            pmoe, nullptr, Hq, f2b + (ll)l*Eq*Hq, nullptr,
            1.f, 1, 0,0,0,0,0,0, (ll)Hq*Iq, (ll)Hq);

        // combine; on last layer also emit x hi plane for lm head
        bool last = (l == Lq - 1);
        combine_k<<<(Tq*Hq)/256, 256>>>(last ? xH : nullptr);
    }

    // lm head  (1-term, BK=64)
    bgemm<1,0,256,1,64><<<dim3(Tq/128, Vq/256, 1), 256, DS_T1_256_64>>>(
        Tq, Vq, Hq, xH, nullptr, Hq, lmH, nullptr, Hq, out, nullptr, Vq,
        lmb, nullptr, 1.f, 1, 0,0,0,0,0,0, 0, 0);

    tail_k<<<1,256>>>(out, (ll)out_size);
}